// round 5
// baseline (speedup 1.0000x reference)
#include <cuda_runtime.h>
#include <cuda_bf16.h>
#include <math.h>
#include <stdint.h>

#define NN 50000
#define EE 800000
#define DIN 384
#define DH 128

// ---------------- scratch (device globals) ------------------------------------
__device__ int   g_is64;
__device__ int   g_cnt[NN];
__device__ int   g_off[NN + 1];
__device__ int   g_cur[NN];
__device__ int   g_csr[EE];
__device__ float g_dinv[NN];
__device__ float g_hws[NN * DH];
__device__ float g_res[NN * DH];
__device__ float g_h1 [NN * DH];
// split-precision transposed weights: [N=128, K] row-major
__device__ unsigned short g_b1hi[DH * DIN];  // W1^T
__device__ unsigned short g_b1lo[DH * DIN];
__device__ unsigned short g_brhi[DH * DIN];  // rW^T
__device__ unsigned short g_brlo[DH * DIN];
__device__ unsigned short g_w2hi[DH * DH];   // W2^T
__device__ unsigned short g_w2lo[DH * DH];

// ---------------- helpers ------------------------------------------------------
__device__ __forceinline__ float elu1(float x) { return x > 0.f ? x : expm1f(x); }

__device__ __forceinline__ uint32_t smem_u32(const void* p) {
    uint32_t a;
    asm("{ .reg .u64 t; cvta.to.shared.u64 t, %1; cvt.u32.u64 %0, t; }" : "=r"(a) : "l"(p));
    return a;
}

__device__ __forceinline__ void ldm4(uint32_t* r, uint32_t addr) {
    asm volatile("ldmatrix.sync.aligned.m8n8.x4.shared.b16 {%0,%1,%2,%3}, [%4];"
                 : "=r"(r[0]), "=r"(r[1]), "=r"(r[2]), "=r"(r[3]) : "r"(addr));
}
__device__ __forceinline__ void mma16816(float* d, const uint32_t* a, const uint32_t* b) {
    asm volatile("mma.sync.aligned.m16n8k16.row.col.f32.bf16.bf16.f32 "
                 "{%0,%1,%2,%3}, {%4,%5,%6,%7}, {%8,%9}, {%0,%1,%2,%3};"
                 : "+f"(d[0]), "+f"(d[1]), "+f"(d[2]), "+f"(d[3])
                 : "r"(a[0]), "r"(a[1]), "r"(a[2]), "r"(a[3]), "r"(b[0]), "r"(b[1]));
}

__device__ __forceinline__ void load_edge(const void* ei, int e, int& s, int& d) {
    if (g_is64) {
        const long long* p = (const long long*)ei;
        s = (int)p[e]; d = (int)p[EE + e];
    } else {
        const int* p = (const int*)ei;
        s = p[e]; d = p[EE + e];
    }
}

// Pull-mode aggregation: self + sum of neighbor rows (rows are pre-scaled).
__device__ __forceinline__ float4 agg_row(int n, int lane) {
    float4 a = *(const float4*)&g_hws[(size_t)n * DH + lane * 4];
    int e  = g_off[n];
    int e1 = g_off[n + 1];
    for (; e + 4 <= e1; e += 4) {
        int s0 = g_csr[e], s1 = g_csr[e + 1], s2 = g_csr[e + 2], s3 = g_csr[e + 3];
        float4 v0 = *(const float4*)&g_hws[(size_t)s0 * DH + lane * 4];
        float4 v1 = *(const float4*)&g_hws[(size_t)s1 * DH + lane * 4];
        float4 v2 = *(const float4*)&g_hws[(size_t)s2 * DH + lane * 4];
        float4 v3 = *(const float4*)&g_hws[(size_t)s3 * DH + lane * 4];
        a.x += (v0.x + v1.x) + (v2.x + v3.x);
        a.y += (v0.y + v1.y) + (v2.y + v3.y);
        a.z += (v0.z + v1.z) + (v2.z + v3.z);
        a.w += (v0.w + v1.w) + (v2.w + v3.w);
    }
    for (; e < e1; e++) {
        int s0 = g_csr[e];
        float4 v0 = *(const float4*)&g_hws[(size_t)s0 * DH + lane * 4];
        a.x += v0.x; a.y += v0.y; a.z += v0.z; a.w += v0.w;
    }
    return a;
}

// ---------------- setup / CSR --------------------------------------------------
__global__ void k_init(const void* edges) {
    int i = blockIdx.x * blockDim.x + threadIdx.x;
    if (i < NN) g_cnt[i] = 0;
    if (i == 0) {
        const unsigned long long* p = (const unsigned long long*)edges;
        int is64 = 1;
        for (int j = 0; j < 8; j++) if (p[j] >= (unsigned long long)NN) is64 = 0;
        g_is64 = is64;
    }
}
__global__ void k_hist(const void* edges) {
    int e = blockIdx.x * blockDim.x + threadIdx.x;
    if (e >= EE) return;
    int s, d;
    load_edge(edges, e, s, d);
    atomicAdd(&g_cnt[d], 1);
}
__global__ void k_scan() {
    __shared__ int warp_sums[32];
    const int t = threadIdx.x;
    const int CH = 49;
    int start = t * CH;
    int end   = min(start + CH, NN);
    int s = 0;
    for (int i = start; i < end; i++) s += g_cnt[i];
    int lane = t & 31, wid = t >> 5;
    int v = s;
#pragma unroll
    for (int o = 1; o < 32; o <<= 1) {
        int u = __shfl_up_sync(0xffffffffu, v, o);
        if (lane >= o) v += u;
    }
    if (lane == 31) warp_sums[wid] = v;
    __syncthreads();
    if (wid == 0) {
        int w = warp_sums[lane];
#pragma unroll
        for (int o = 1; o < 32; o <<= 1) {
            int u = __shfl_up_sync(0xffffffffu, w, o);
            if (lane >= o) w += u;
        }
        warp_sums[lane] = w;
    }
    __syncthreads();
    int excl = v - s + (wid ? warp_sums[wid - 1] : 0);
    int run = excl;
    for (int i = start; i < end; i++) {
        g_off[i] = run;
        g_cur[i] = run;
        int c = g_cnt[i];
        g_dinv[i] = rsqrtf((float)(c + 1));
        run += c;
    }
    if (t == 1023) g_off[NN] = run;
}
__global__ void k_fill(const void* edges) {
    int e = blockIdx.x * blockDim.x + threadIdx.x;
    if (e >= EE) return;
    int s, d;
    load_edge(edges, e, s, d);
    int pos = atomicAdd(&g_cur[d], 1);
    g_csr[pos] = s;
}

// ---------------- weight prep: transpose + bf16 split --------------------------
__global__ void k_prep(const float* __restrict__ W1, const float* __restrict__ rW,
                       const float* __restrict__ W2) {
    int i = blockIdx.x * blockDim.x + threadIdx.x;
    float val;
    unsigned short *ph, *pl;
    int idx;
    if (i < DH * DIN) {
        int n = i / DIN, k = i % DIN;
        val = W1[k * DH + n]; ph = g_b1hi; pl = g_b1lo; idx = i;
    } else if (i < 2 * DH * DIN) {
        int j = i - DH * DIN;
        int n = j / DIN, k = j % DIN;
        val = rW[k * DH + n]; ph = g_brhi; pl = g_brlo; idx = j;
    } else if (i < 2 * DH * DIN + DH * DH) {
        int j = i - 2 * DH * DIN;
        int n = j / DH, k = j % DH;
        val = W2[k * DH + n]; ph = g_w2hi; pl = g_w2lo; idx = j;
    } else return;
    __nv_bfloat16 h = __float2bfloat16(val);
    float r = val - __bfloat162float(h);
    __nv_bfloat16 l = __float2bfloat16(r);
    ph[idx] = __bfloat16_as_ushort(h);
    pl[idx] = __bfloat16_as_ushort(l);
}

// ---------------- tensor-core GEMM via mma.sync (bf16x3 split) -----------------
// which==0: A=x (kd=384). blockIdx.y: 0 -> W1, dinv-scale -> g_hws
//                                     1 -> rW, LayerNorm  -> g_res
// which==1: A=g_h1 (kd=128), single mode: W2, dinv-scale -> g_hws
#define SROW 80   // padded smem row stride in bytes (conflict-free for ldmatrix)

__global__ __launch_bounds__(256, 2) void k_gemm_mma(
    const float* __restrict__ Ain, int kd, int which,
    const float* __restrict__ lb, const float* __restrict__ lg, const float* __restrict__ lbe)
{
    __shared__ __align__(16) unsigned char sA_hi[128 * SROW];
    __shared__ __align__(16) unsigned char sA_lo[128 * SROW];
    __shared__ __align__(16) unsigned char sB_hi[128 * SROW];
    __shared__ __align__(16) unsigned char sB_lo[128 * SROW];
    __shared__ float s_lb[DH], s_lg[DH], s_lbe[DH];

    const int tid  = threadIdx.x;
    const int wid  = tid >> 5;
    const int lane = tid & 31;
    const int mode = blockIdx.y;
    const int row0 = blockIdx.x * 128;
    const float* A = which ? (const float*)g_h1 : Ain;
    const unsigned short* Bh;
    const unsigned short* Bl;
    if (which == 0) { Bh = mode ? g_brhi : g_b1hi; Bl = mode ? g_brlo : g_b1lo; }
    else            { Bh = g_w2hi; Bl = g_w2lo; }

    if (which == 0 && mode == 1 && tid < DH) {
        s_lb[tid] = lb[tid]; s_lg[tid] = lg[tid]; s_lbe[tid] = lbe[tid];
    }

    float acc[16][4];
#pragma unroll
    for (int i = 0; i < 16; i++)
#pragma unroll
        for (int j = 0; j < 4; j++) acc[i][j] = 0.f;

    // per-lane ldmatrix addresses
    const uint32_t bAhi = smem_u32(sA_hi) + (wid * 16 + (lane & 15)) * SROW + ((lane >> 4) & 1) * 16;
    const uint32_t bAlo = smem_u32(sA_lo) + (wid * 16 + (lane & 15)) * SROW + ((lane >> 4) & 1) * 16;
    const uint32_t nrow = (uint32_t)((lane & 7) | ((lane >> 4) << 3));
    const uint32_t bBhi = smem_u32(sB_hi) + nrow * SROW + ((lane >> 3) & 1) * 16;
    const uint32_t bBlo = smem_u32(sB_lo) + nrow * SROW + ((lane >> 3) & 1) * 16;
    const uint32_t stAhi = smem_u32(sA_hi), stAlo = smem_u32(sA_lo);
    const uint32_t stBhi = smem_u32(sB_hi), stBlo = smem_u32(sB_lo);

    const int T = kd >> 5;   // k-chunks of 32
    for (int t = 0; t < T; t++) {
        const int kt = t << 5;
        if (t) __syncthreads();
        // ---- A chunk: 128 rows x 32 fp32 -> hi/lo bf16 ----
#pragma unroll
        for (int u = 0; u < 4; u++) {
            int idx = u * 256 + tid;
            int r = idx >> 3, q = idx & 7;
            int gr = row0 + r;
            float4 v = make_float4(0.f, 0.f, 0.f, 0.f);
            if (gr < NN) v = *(const float4*)&A[(size_t)gr * kd + kt + q * 4];
            uint32_t h01, h23;
            asm("cvt.rn.bf16x2.f32 %0, %1, %2;" : "=r"(h01) : "f"(v.y), "f"(v.x));
            asm("cvt.rn.bf16x2.f32 %0, %1, %2;" : "=r"(h23) : "f"(v.w), "f"(v.z));
            float rx = v.x - __uint_as_float(h01 << 16);
            float ry = v.y - __uint_as_float(h01 & 0xffff0000u);
            float rz = v.z - __uint_as_float(h23 << 16);
            float rw = v.w - __uint_as_float(h23 & 0xffff0000u);
            uint32_t l01, l23;
            asm("cvt.rn.bf16x2.f32 %0, %1, %2;" : "=r"(l01) : "f"(ry), "f"(rx));
            asm("cvt.rn.bf16x2.f32 %0, %1, %2;" : "=r"(l23) : "f"(rw), "f"(rz));
            uint32_t off = (uint32_t)(r * SROW + q * 8);
            asm volatile("st.shared.v2.b32 [%0], {%1, %2};" :: "r"(stAhi + off), "r"(h01), "r"(h23) : "memory");
            asm volatile("st.shared.v2.b32 [%0], {%1, %2};" :: "r"(stAlo + off), "r"(l01), "r"(l23) : "memory");
        }
        // ---- B chunk: 128 n-rows x 32 k bf16 (hi & lo) ----
#pragma unroll
        for (int u = 0; u < 2; u++) {
            int idx = u * 256 + tid;
            int r = idx >> 2, q = idx & 3;
            uint4 vh = *(const uint4*)&Bh[(size_t)r * kd + kt + q * 8];
            uint4 vl = *(const uint4*)&Bl[(size_t)r * kd + kt + q * 8];
            uint32_t off = (uint32_t)(r * SROW + q * 16);
            asm volatile("st.shared.v4.b32 [%0], {%1, %2, %3, %4};"
                         :: "r"(stBhi + off), "r"(vh.x), "r"(vh.y), "r"(vh.z), "r"(vh.w) : "memory");
            asm volatile("st.shared.v4.b32 [%0], {%1, %2, %3, %4};"
                         :: "r"(stBlo + off), "r"(vl.x), "r"(vl.y), "r"(vl.z), "r"(vl.w) : "memory");
        }
        __syncthreads();
        // ---- compute ----
#pragma unroll
        for (int kb = 0; kb < 2; kb++) {
            uint32_t ah[4], al[4];
            ldm4(ah, bAhi + kb * 32);
            ldm4(al, bAlo + kb * 32);
#pragma unroll
            for (int nt = 0; nt < 8; nt++) {
                uint32_t bh[4], blr[4];
                ldm4(bh,  bBhi + nt * 16 * SROW + kb * 32);
                ldm4(blr, bBlo + nt * 16 * SROW + kb * 32);
                mma16816(acc[2 * nt],     ah, &bh[0]);
                mma16816(acc[2 * nt],     ah, &blr[0]);
                mma16816(acc[2 * nt],     al, &bh[0]);
                mma16816(acc[2 * nt + 1], ah, &bh[2]);
                mma16816(acc[2 * nt + 1], ah, &blr[2]);
                mma16816(acc[2 * nt + 1], al, &bh[2]);
            }
        }
    }

    // ---- epilogue ----
    const int r_in = lane >> 2;
    const int cq = (lane & 3) * 2;
    if (which == 1 || mode == 0) {
#pragma unroll
        for (int p = 0; p < 2; p++) {
            int row = row0 + wid * 16 + r_in + p * 8;
            if (row < NN) {
                float dv = g_dinv[row];
#pragma unroll
                for (int nt = 0; nt < 16; nt++) {
                    *(float2*)&g_hws[(size_t)row * DH + nt * 8 + cq] =
                        make_float2(acc[nt][2 * p] * dv, acc[nt][2 * p + 1] * dv);
                }
            }
        }
    } else {
#pragma unroll
        for (int p = 0; p < 2; p++) {
            float s = 0.f, q = 0.f;
#pragma unroll
            for (int nt = 0; nt < 16; nt++) {
                float v0 = acc[nt][2 * p]     + s_lb[nt * 8 + cq];
                float v1 = acc[nt][2 * p + 1] + s_lb[nt * 8 + cq + 1];
                s += v0 + v1; q += v0 * v0 + v1 * v1;
            }
            s += __shfl_xor_sync(0xffffffffu, s, 1);
            s += __shfl_xor_sync(0xffffffffu, s, 2);
            q += __shfl_xor_sync(0xffffffffu, q, 1);
            q += __shfl_xor_sync(0xffffffffu, q, 2);
            float m = s * (1.f / DH);
            float var = q * (1.f / DH) - m * m;
            float rstd = rsqrtf(var + 1e-5f);
            int row = row0 + wid * 16 + r_in + p * 8;
            if (row < NN) {
#pragma unroll
                for (int nt = 0; nt < 16; nt++) {
                    int c = nt * 8 + cq;
                    float v0 = acc[nt][2 * p]     + s_lb[c];
                    float v1 = acc[nt][2 * p + 1] + s_lb[c + 1];
                    *(float2*)&g_res[(size_t)row * DH + c] =
                        make_float2((v0 - m) * rstd * s_lg[c]     + s_lbe[c],
                                    (v1 - m) * rstd * s_lg[c + 1] + s_lbe[c + 1]);
                }
            }
        }
    }
}

// ---------------- agg1: h1 = elu(LN(agg*dinv + b1)) + res ----------------------
__global__ __launch_bounds__(256) void k_agg1(const float* __restrict__ b1,
                                              const float* __restrict__ g1,
                                              const float* __restrict__ be1) {
    int n = (blockIdx.x * blockDim.x + threadIdx.x) >> 5;
    if (n >= NN) return;
    int lane = threadIdx.x & 31;
    float4 a = agg_row(n, lane);
    float dv = g_dinv[n];
    float4 bb = *(const float4*)&b1[lane * 4];
    float v0 = fmaf(a.x, dv, bb.x), v1 = fmaf(a.y, dv, bb.y);
    float v2 = fmaf(a.z, dv, bb.z), v3 = fmaf(a.w, dv, bb.w);
    float s = v0 + v1 + v2 + v3;
    float q = v0 * v0 + v1 * v1 + v2 * v2 + v3 * v3;
#pragma unroll
    for (int o = 16; o; o >>= 1) {
        s += __shfl_xor_sync(0xffffffffu, s, o);
        q += __shfl_xor_sync(0xffffffffu, q, o);
    }
    float m = s * (1.f / DH);
    float var = q * (1.f / DH) - m * m;
    float rstd = rsqrtf(var + 1e-5f);
    float4 gg = *(const float4*)&g1[lane * 4];
    float4 be = *(const float4*)&be1[lane * 4];
    float y0 = elu1((v0 - m) * rstd * gg.x + be.x);
    float y1 = elu1((v1 - m) * rstd * gg.y + be.y);
    float y2 = elu1((v2 - m) * rstd * gg.z + be.z);
    float y3 = elu1((v3 - m) * rstd * gg.w + be.w);
    float4 r = *(const float4*)&g_res[(size_t)n * DH + lane * 4];
    *(float4*)&g_h1[(size_t)n * DH + lane * 4] =
        make_float4(y0 + r.x, y1 + r.y, y2 + r.z, y3 + r.w);
}

// ---------------- epilogue 2 (fused agg) + MLP head + softmax ------------------
#define EPI2_SMEM ((128 * 128 + 8 * 4 * 132) * 4)
__global__ __launch_bounds__(256, 2) void k_epi2(
    const float* __restrict__ b2, const float* __restrict__ g2, const float* __restrict__ be2,
    const float* __restrict__ mW1, const float* __restrict__ mb1,
    const float* __restrict__ mg_, const float* __restrict__ mbe_,
    const float* __restrict__ mW2, const float* __restrict__ mb2,
    float* __restrict__ out)
{
    extern __shared__ float sm[];
    float* W1s = sm;
    float* h2s = sm + 128 * 128;
    const int tid = threadIdx.x;
    for (int i = tid; i < 128 * 128 / 4; i += 256)
        ((float4*)W1s)[i] = ((const float4*)mW1)[i];
    __syncthreads();

    const int wid = tid >> 5, lane = tid & 31;
    float* myh2 = h2s + wid * (4 * 132);
    float4 b2v  = *(const float4*)&b2 [lane * 4];
    float4 g2v  = *(const float4*)&g2 [lane * 4];
    float4 be2v = *(const float4*)&be2[lane * 4];
    float4 mb1v = *(const float4*)&mb1[lane * 4];
    float4 mgv  = *(const float4*)&mg_[lane * 4];
    float4 mbev = *(const float4*)&mbe_[lane * 4];
    float mb2v[16];
#pragma unroll
    for (int c = 0; c < 16; c++) mb2v[c] = mb2[c];

    const int gw = blockIdx.x * 8 + wid;
    const int step = gridDim.x * 8 * 4;
    for (int nb = gw * 4; nb < NN; nb += step) {
#pragma unroll
        for (int s2 = 0; s2 < 4; s2++) {
            int n = nb + s2;
            float4 a = make_float4(0.f, 0.f, 0.f, 0.f), r = a;
            float dv = 0.f;
            if (n < NN) {
                dv = g_dinv[n];
                a = agg_row(n, lane);
                r = *(const float4*)&g_h1[(size_t)n * DH + lane * 4];
            }
            float v0 = fmaf(a.x, dv, b2v.x), v1 = fmaf(a.y, dv, b2v.y);
            float v2 = fmaf(a.z, dv, b2v.z), v3 = fmaf(a.w, dv, b2v.w);
            float s = v0 + v1 + v2 + v3;
            float q = v0 * v0 + v1 * v1 + v2 * v2 + v3 * v3;
#pragma unroll
            for (int o = 16; o; o >>= 1) {
                s += __shfl_xor_sync(0xffffffffu, s, o);
                q += __shfl_xor_sync(0xffffffffu, q, o);
            }
            float m = s * (1.f / DH);
            float var = q * (1.f / DH) - m * m;
            float rstd = rsqrtf(var + 1e-5f);
            float y0 = elu1((v0 - m) * rstd * g2v.x + be2v.x) + r.x;
            float y1 = elu1((v1 - m) * rstd * g2v.y + be2v.y) + r.y;
            float y2 = elu1((v2 - m) * rstd * g2v.z + be2v.z) + r.z;
            float y3 = elu1((v3 - m) * rstd * g2v.w + be2v.w) + r.w;
            *(float4*)&myh2[s2 * 132 + lane * 4] = make_float4(y0, y1, y2, y3);
        }
        __syncwarp();

        float4 zz[4];
#pragma unroll
        for (int s2 = 0; s2 < 4; s2++) zz[s2] = mb1v;
        for (int kk = 0; kk < 32; kk++) {
            float4 hq0 = *(const float4*)&myh2[0 * 132 + 4 * kk];
            float4 hq1 = *(const float4*)&myh2[1 * 132 + 4 * kk];
            float4 hq2 = *(const float4*)&myh2[2 * 132 + 4 * kk];
            float4 hq3 = *(const float4*)&myh2[3 * 132 + 4 * kk];
            float ha0[4] = {hq0.x, hq0.y, hq0.z, hq0.w};
            float ha1[4] = {hq1.x, hq1.y, hq1.z, hq1.w};
            float ha2[4] = {hq2.x, hq2.y, hq2.z, hq2.w};
            float ha3[4] = {hq3.x, hq3.y, hq3.z, hq3.w};
#pragma unroll
            for (int j = 0; j < 4; j++) {
                float4 w = *(const float4*)&W1s[(4 * kk + j) * 128 + lane * 4];
                zz[0].x = fmaf(ha0[j], w.x, zz[0].x); zz[0].y = fmaf(ha0[j], w.y, zz[0].y);
                zz[0].z = fmaf(ha0[j], w.z, zz[0].z); zz[0].w = fmaf(ha0[j], w.w, zz[0].w);
                zz[1].x = fmaf(ha1[j], w.x, zz[1].x); zz[1].y = fmaf(ha1[j], w.y, zz[1].y);
                zz[1].z = fmaf(ha1[j], w.z, zz[1].z); zz[1].w = fmaf(ha1[j], w.w, zz[1].w);
                zz[2].x = fmaf(ha2[j], w.x, zz[2].x); zz[2].y = fmaf(ha2[j], w.y, zz[2].y);
                zz[2].z = fmaf(ha2[j], w.z, zz[2].z); zz[2].w = fmaf(ha2[j], w.w, zz[2].w);
                zz[3].x = fmaf(ha3[j], w.x, zz[3].x); zz[3].y = fmaf(ha3[j], w.y, zz[3].y);
                zz[3].z = fmaf(ha3[j], w.z, zz[3].z); zz[3].w = fmaf(ha3[j], w.w, zz[3].w);
            }
        }
        __syncwarp();

#pragma unroll
        for (int s2 = 0; s2 < 4; s2++) {
            float4 z = zz[s2];
            float s = z.x + z.y + z.z + z.w;
            float q = z.x * z.x + z.y * z.y + z.z * z.z + z.w * z.w;
#pragma unroll
            for (int o = 16; o; o >>= 1) {
                s += __shfl_xor_sync(0xffffffffu, s, o);
                q += __shfl_xor_sync(0xffffffffu, q, o);
            }
            float m = s * (1.f / DH);
            float var = q * (1.f / DH) - m * m;
            float rstd = rsqrtf(var + 1e-5f);
            z.x = elu1((z.x - m) * rstd * mgv.x + mbev.x);
            z.y = elu1((z.y - m) * rstd * mgv.y + mbev.y);
            z.z = elu1((z.z - m) * rstd * mgv.z + mbev.z);
            z.w = elu1((z.w - m) * rstd * mgv.w + mbev.w);
            zz[s2] = z;
        }

#pragma unroll
        for (int s2 = 0; s2 < 4; s2++) {
            float Hp[16];
#pragma unroll
            for (int c = 0; c < 16; c++) Hp[c] = 0.f;
            float za[4] = {zz[s2].x, zz[s2].y, zz[s2].z, zz[s2].w};
#pragma unroll
            for (int j = 0; j < 4; j++) {
                int k = 4 * lane + j;
                const float4* wr = (const float4*)&mW2[k * 16];
                float4 w0 = wr[0], w1 = wr[1], w2 = wr[2], w3 = wr[3];
                float zv = za[j];
                Hp[0]  = fmaf(zv, w0.x, Hp[0]);  Hp[1]  = fmaf(zv, w0.y, Hp[1]);
                Hp[2]  = fmaf(zv, w0.z, Hp[2]);  Hp[3]  = fmaf(zv, w0.w, Hp[3]);
                Hp[4]  = fmaf(zv, w1.x, Hp[4]);  Hp[5]  = fmaf(zv, w1.y, Hp[5]);
                Hp[6]  = fmaf(zv, w1.z, Hp[6]);  Hp[7]  = fmaf(zv, w1.w, Hp[7]);
                Hp[8]  = fmaf(zv, w2.x, Hp[8]);  Hp[9]  = fmaf(zv, w2.y, Hp[9]);
                Hp[10] = fmaf(zv, w2.z, Hp[10]); Hp[11] = fmaf(zv, w2.w, Hp[11]);
                Hp[12] = fmaf(zv, w3.x, Hp[12]); Hp[13] = fmaf(zv, w3.y, Hp[13]);
                Hp[14] = fmaf(zv, w3.z, Hp[14]); Hp[15] = fmaf(zv, w3.w, Hp[15]);
            }
#pragma unroll
            for (int o = 16; o; o >>= 1)
#pragma unroll
                for (int c = 0; c < 16; c++)
                    Hp[c] += __shfl_xor_sync(0xffffffffu, Hp[c], o);
            int n = nb + s2;
            if (lane == 0 && n < NN) {
                float mx = -1e30f;
#pragma unroll
                for (int c = 0; c < 16; c++) { Hp[c] += mb2v[c]; mx = fmaxf(mx, Hp[c]); }
                float ss = 0.f;
#pragma unroll
                for (int c = 0; c < 16; c++) { Hp[c] = __expf(Hp[c] - mx); ss += Hp[c]; }
                float inv = 1.f / ss;
                *(float4*)&out[(size_t)n * 16 + 0]  = make_float4(Hp[0] * inv, Hp[1] * inv, Hp[2] * inv, Hp[3] * inv);
                *(float4*)&out[(size_t)n * 16 + 4]  = make_float4(Hp[4] * inv, Hp[5] * inv, Hp[6] * inv, Hp[7] * inv);
                *(float4*)&out[(size_t)n * 16 + 8]  = make_float4(Hp[8] * inv, Hp[9] * inv, Hp[10] * inv, Hp[11] * inv);
                *(float4*)&out[(size_t)n * 16 + 12] = make_float4(Hp[12] * inv, Hp[13] * inv, Hp[14] * inv, Hp[15] * inv);
            }
        }
    }
}

// ---------------- launcher -----------------------------------------------------
extern "C" void kernel_launch(void* const* d_in, const int* in_sizes, int n_in,
                              void* d_out, int out_size) {
    const float* x   = (const float*)d_in[0];
    const void*  ei  = d_in[1];
    const float* W1  = (const float*)d_in[2];
    const float* b1  = (const float*)d_in[3];
    const float* g1  = (const float*)d_in[4];
    const float* be1 = (const float*)d_in[5];
    const float* W2  = (const float*)d_in[6];
    const float* rW  = (const float*)d_in[10];
    const float* rb  = (const float*)d_in[11];
    const float* rg  = (const float*)d_in[12];
    const float* rbe = (const float*)d_in[13];
    const float* b2  = (const float*)d_in[7];
    const float* g2  = (const float*)d_in[8];
    const float* be2 = (const float*)d_in[9];
    const float* mW1 = (const float*)d_in[14];
    const float* mb1 = (const float*)d_in[15];
    const float* mg  = (const float*)d_in[16];
    const float* mbe = (const float*)d_in[17];
    const float* mW2 = (const float*)d_in[18];
    const float* mb2 = (const float*)d_in[19];
    float* out = (float*)d_out;

    cudaFuncSetAttribute(k_epi2, cudaFuncAttributeMaxDynamicSharedMemorySize, EPI2_SMEM);

    // CSR build + weight prep
    k_init<<<(NN + 255) / 256, 256>>>(ei);
    k_hist<<<(EE + 255) / 256, 256>>>(ei);
    k_prep<<<(2 * DH * DIN + DH * DH + 255) / 256, 256>>>(W1, rW, W2);
    k_scan<<<1, 1024>>>();
    k_fill<<<(EE + 255) / 256, 256>>>(ei);

    const int nblk = (NN + 127) / 128;  // 391
    // layer 1: x@[W1|rW] via mma.sync, fused scale + LN epilogues
    dim3 grid1(nblk, 2);
    k_gemm_mma<<<grid1, 256>>>(x, DIN, 0, rb, rg, rbe);
    k_agg1<<<(NN * 32 + 255) / 256, 256>>>(b1, g1, be1);

    // layer 2: h1@W2 via mma.sync, fused scale epilogue
    dim3 grid2(nblk, 1);
    k_gemm_mma<<<grid2, 256>>>(x, DH, 1, rb, rg, rbe);

    // fused layer-2 aggregation + epilogue + MLP head + softmax
    k_epi2<<<296, 256, EPI2_SMEM>>>(b2, g2, be2, mW1, mb1, mg, mbe, mW2, mb2, out);
}

// round 6
// speedup vs baseline: 1.8998x; 1.8998x over previous
#include <cuda_runtime.h>
#include <cuda_bf16.h>
#include <math.h>
#include <stdint.h>

#define NN 50000
#define EE 800000
#define DIN 384
#define DH 128
#define NB_SCAN 196   // ceil(50000/256)

// ---------------- scratch (device globals) ------------------------------------
__device__ int   g_is64;
__device__ int   g_cnt[NN];
__device__ int   g_bsum[256];
__device__ int   g_off[NN + 1];
__device__ int   g_cur[NN];
__device__ int   g_csr[EE];
__device__ float g_dinv[NN];
__device__ float g_hws[NN * DH];
__device__ float g_res[NN * DH];
__device__ float g_h1 [NN * DH];
// split-precision transposed weights: [N=128, K] row-major
__device__ unsigned short g_b1hi[DH * DIN];  // W1^T
__device__ unsigned short g_b1lo[DH * DIN];
__device__ unsigned short g_brhi[DH * DIN];  // rW^T
__device__ unsigned short g_brlo[DH * DIN];
__device__ unsigned short g_w2hi[DH * DH];   // W2^T
__device__ unsigned short g_w2lo[DH * DH];

// ---------------- helpers ------------------------------------------------------
__device__ __forceinline__ float elu1(float x) { return x > 0.f ? x : expm1f(x); }

__device__ __forceinline__ uint32_t smem_u32(const void* p) {
    uint32_t a;
    asm("{ .reg .u64 t; cvta.to.shared.u64 t, %1; cvt.u32.u64 %0, t; }" : "=r"(a) : "l"(p));
    return a;
}

__device__ __forceinline__ void ldm4(uint32_t* r, uint32_t addr) {
    asm volatile("ldmatrix.sync.aligned.m8n8.x4.shared.b16 {%0,%1,%2,%3}, [%4];"
                 : "=r"(r[0]), "=r"(r[1]), "=r"(r[2]), "=r"(r[3]) : "r"(addr));
}
__device__ __forceinline__ void mma16816(float* d, const uint32_t* a, const uint32_t* b) {
    asm volatile("mma.sync.aligned.m16n8k16.row.col.f32.bf16.bf16.f32 "
                 "{%0,%1,%2,%3}, {%4,%5,%6,%7}, {%8,%9}, {%0,%1,%2,%3};"
                 : "+f"(d[0]), "+f"(d[1]), "+f"(d[2]), "+f"(d[3])
                 : "r"(a[0]), "r"(a[1]), "r"(a[2]), "r"(a[3]), "r"(b[0]), "r"(b[1]));
}

__device__ __forceinline__ void load_edge(const void* ei, int e, int& s, int& d) {
    if (g_is64) {
        const long long* p = (const long long*)ei;
        s = (int)p[e]; d = (int)p[EE + e];
    } else {
        const int* p = (const int*)ei;
        s = p[e]; d = p[EE + e];
    }
}

// inclusive block scan over 256 threads
__device__ __forceinline__ int block_scan_incl(int v, int* ws) {
    int lane = threadIdx.x & 31, w = threadIdx.x >> 5;
    int x = v;
#pragma unroll
    for (int o = 1; o < 32; o <<= 1) {
        int u = __shfl_up_sync(0xffffffffu, x, o);
        if (lane >= o) x += u;
    }
    if (lane == 31) ws[w] = x;
    __syncthreads();
    if (w == 0) {
        int t = (lane < 8) ? ws[lane] : 0;
#pragma unroll
        for (int o = 1; o < 8; o <<= 1) {
            int u = __shfl_up_sync(0xffffffffu, t, o);
            if (lane >= o) t += u;
        }
        if (lane < 8) ws[lane] = t;
    }
    __syncthreads();
    if (w > 0) x += ws[w - 1];
    return x;
}

// Pull-mode aggregation: self + sum of neighbor rows (rows are pre-scaled).
__device__ __forceinline__ float4 agg_row(int n, int lane) {
    float4 a = *(const float4*)&g_hws[(size_t)n * DH + lane * 4];
    int e  = g_off[n];
    int e1 = g_off[n + 1];
    for (; e + 4 <= e1; e += 4) {
        int s0 = g_csr[e], s1 = g_csr[e + 1], s2 = g_csr[e + 2], s3 = g_csr[e + 3];
        float4 v0 = *(const float4*)&g_hws[(size_t)s0 * DH + lane * 4];
        float4 v1 = *(const float4*)&g_hws[(size_t)s1 * DH + lane * 4];
        float4 v2 = *(const float4*)&g_hws[(size_t)s2 * DH + lane * 4];
        float4 v3 = *(const float4*)&g_hws[(size_t)s3 * DH + lane * 4];
        a.x += (v0.x + v1.x) + (v2.x + v3.x);
        a.y += (v0.y + v1.y) + (v2.y + v3.y);
        a.z += (v0.z + v1.z) + (v2.z + v3.z);
        a.w += (v0.w + v1.w) + (v2.w + v3.w);
    }
    for (; e < e1; e++) {
        int s0 = g_csr[e];
        float4 v0 = *(const float4*)&g_hws[(size_t)s0 * DH + lane * 4];
        a.x += v0.x; a.y += v0.y; a.z += v0.z; a.w += v0.w;
    }
    return a;
}

// ---------------- weight prep + init -------------------------------------------
__global__ void k_prep(const float* __restrict__ W1, const float* __restrict__ rW,
                       const float* __restrict__ W2, const void* edges) {
    int i = blockIdx.x * blockDim.x + threadIdx.x;
    if (i < NN) g_cnt[i] = 0;
    if (i == 0) {
        const unsigned long long* p = (const unsigned long long*)edges;
        int is64 = 1;
        for (int j = 0; j < 8; j++) if (p[j] >= (unsigned long long)NN) is64 = 0;
        g_is64 = is64;
    }
    float val;
    unsigned short *ph, *pl;
    int idx;
    if (i < DH * DIN) {
        int n = i / DIN, k = i % DIN;
        val = W1[k * DH + n]; ph = g_b1hi; pl = g_b1lo; idx = i;
    } else if (i < 2 * DH * DIN) {
        int j = i - DH * DIN;
        int n = j / DIN, k = j % DIN;
        val = rW[k * DH + n]; ph = g_brhi; pl = g_brlo; idx = j;
    } else if (i < 2 * DH * DIN + DH * DH) {
        int j = i - 2 * DH * DIN;
        int n = j / DH, k = j % DH;
        val = W2[k * DH + n]; ph = g_w2hi; pl = g_w2lo; idx = j;
    } else return;
    __nv_bfloat16 h = __float2bfloat16(val);
    float r = val - __bfloat162float(h);
    __nv_bfloat16 l = __float2bfloat16(r);
    ph[idx] = __bfloat16_as_ushort(h);
    pl[idx] = __bfloat16_as_ushort(l);
}

__global__ void k_hist(const void* edges) {
    int e = blockIdx.x * blockDim.x + threadIdx.x;
    if (e >= EE) return;
    int s, d;
    load_edge(edges, e, s, d);
    atomicAdd(&g_cnt[d], 1);
}

// ---------------- parallel 3-phase scan ----------------------------------------
__global__ void k_scan1() {
    __shared__ int ws[8];
    int i = blockIdx.x * 256 + threadIdx.x;
    int c = (i < NN) ? g_cnt[i] : 0;
    if (i < NN) g_dinv[i] = rsqrtf((float)(c + 1));
    int lane = threadIdx.x & 31, w = threadIdx.x >> 5;
    int v = c;
#pragma unroll
    for (int o = 16; o; o >>= 1) v += __shfl_xor_sync(0xffffffffu, v, o);
    if (lane == 0) ws[w] = v;
    __syncthreads();
    if (w == 0) {
        int t = (lane < 8) ? ws[lane] : 0;
#pragma unroll
        for (int o = 4; o; o >>= 1) t += __shfl_xor_sync(0xffffffffu, t, o);
        if (lane == 0) g_bsum[blockIdx.x] = t;
    }
}

__global__ void k_scan2() {
    __shared__ int ws[8];
    int t = threadIdx.x;
    int v = (t < NB_SCAN) ? g_bsum[t] : 0;
    int incl = block_scan_incl(v, ws);
    g_bsum[t] = incl - v;   // exclusive prefix of block sums
}

__global__ void k_scan3() {
    __shared__ int ws[8];
    int i = blockIdx.x * 256 + threadIdx.x;
    int c = (i < NN) ? g_cnt[i] : 0;
    int incl = block_scan_incl(c, ws);
    int base = g_bsum[blockIdx.x];
    int excl = base + incl - c;
    if (i < NN) { g_off[i] = excl; g_cur[i] = excl; }
    if (i == NN - 1) g_off[NN] = base + incl;
}

__global__ void k_fill(const void* edges) {
    int e = blockIdx.x * blockDim.x + threadIdx.x;
    if (e >= EE) return;
    int s, d;
    load_edge(edges, e, s, d);
    int pos = atomicAdd(&g_cur[d], 1);
    g_csr[pos] = s;
}

// ---------------- tensor-core GEMM via mma.sync (bf16x3 split) -----------------
// which==0: A=x (kd=384). blockIdx.y: 0 -> W1, dinv-scale -> g_hws
//                                     1 -> rW, LayerNorm  -> g_res
// which==1: A=g_h1 (kd=128), single mode: W2, dinv-scale -> g_hws
#define SROW 80   // padded smem row stride in bytes (conflict-free for ldmatrix)

__global__ __launch_bounds__(256, 2) void k_gemm_mma(
    const float* __restrict__ Ain, int kd, int which,
    const float* __restrict__ lb, const float* __restrict__ lg, const float* __restrict__ lbe)
{
    __shared__ __align__(16) unsigned char sA_hi[128 * SROW];
    __shared__ __align__(16) unsigned char sA_lo[128 * SROW];
    __shared__ __align__(16) unsigned char sB_hi[128 * SROW];
    __shared__ __align__(16) unsigned char sB_lo[128 * SROW];
    __shared__ float s_lb[DH], s_lg[DH], s_lbe[DH];

    const int tid  = threadIdx.x;
    const int wid  = tid >> 5;
    const int lane = tid & 31;
    const int mode = blockIdx.y;
    const int row0 = blockIdx.x * 128;
    const float* A = which ? (const float*)g_h1 : Ain;
    const unsigned short* Bh;
    const unsigned short* Bl;
    if (which == 0) { Bh = mode ? g_brhi : g_b1hi; Bl = mode ? g_brlo : g_b1lo; }
    else            { Bh = g_w2hi; Bl = g_w2lo; }

    if (which == 0 && mode == 1 && tid < DH) {
        s_lb[tid] = lb[tid]; s_lg[tid] = lg[tid]; s_lbe[tid] = lbe[tid];
    }

    float acc[16][4];
#pragma unroll
    for (int i = 0; i < 16; i++)
#pragma unroll
        for (int j = 0; j < 4; j++) acc[i][j] = 0.f;

    const uint32_t bAhi = smem_u32(sA_hi) + (wid * 16 + (lane & 15)) * SROW + ((lane >> 4) & 1) * 16;
    const uint32_t bAlo = smem_u32(sA_lo) + (wid * 16 + (lane & 15)) * SROW + ((lane >> 4) & 1) * 16;
    const uint32_t nrow = (uint32_t)((lane & 7) | ((lane >> 4) << 3));
    const uint32_t bBhi = smem_u32(sB_hi) + nrow * SROW + ((lane >> 3) & 1) * 16;
    const uint32_t bBlo = smem_u32(sB_lo) + nrow * SROW + ((lane >> 3) & 1) * 16;
    const uint32_t stAhi = smem_u32(sA_hi), stAlo = smem_u32(sA_lo);
    const uint32_t stBhi = smem_u32(sB_hi), stBlo = smem_u32(sB_lo);

    const int T = kd >> 5;   // k-chunks of 32
    for (int t = 0; t < T; t++) {
        const int kt = t << 5;
        if (t) __syncthreads();
        // ---- A chunk: 128 rows x 32 fp32 -> hi/lo bf16 ----
#pragma unroll
        for (int u = 0; u < 4; u++) {
            int idx = u * 256 + tid;
            int r = idx >> 3, q = idx & 7;
            int gr = row0 + r;
            float4 v = make_float4(0.f, 0.f, 0.f, 0.f);
            if (gr < NN) v = *(const float4*)&A[(size_t)gr * kd + kt + q * 4];
            uint32_t h01, h23;
            asm("cvt.rn.bf16x2.f32 %0, %1, %2;" : "=r"(h01) : "f"(v.y), "f"(v.x));
            asm("cvt.rn.bf16x2.f32 %0, %1, %2;" : "=r"(h23) : "f"(v.w), "f"(v.z));
            float rx = v.x - __uint_as_float(h01 << 16);
            float ry = v.y - __uint_as_float(h01 & 0xffff0000u);
            float rz = v.z - __uint_as_float(h23 << 16);
            float rw = v.w - __uint_as_float(h23 & 0xffff0000u);
            uint32_t l01, l23;
            asm("cvt.rn.bf16x2.f32 %0, %1, %2;" : "=r"(l01) : "f"(ry), "f"(rx));
            asm("cvt.rn.bf16x2.f32 %0, %1, %2;" : "=r"(l23) : "f"(rw), "f"(rz));
            uint32_t off = (uint32_t)(r * SROW + q * 8);
            asm volatile("st.shared.v2.b32 [%0], {%1, %2};" :: "r"(stAhi + off), "r"(h01), "r"(h23) : "memory");
            asm volatile("st.shared.v2.b32 [%0], {%1, %2};" :: "r"(stAlo + off), "r"(l01), "r"(l23) : "memory");
        }
        // ---- B chunk: 128 n-rows x 32 k bf16 (hi & lo) ----
#pragma unroll
        for (int u = 0; u < 2; u++) {
            int idx = u * 256 + tid;
            int r = idx >> 2, q = idx & 3;
            uint4 vh = *(const uint4*)&Bh[(size_t)r * kd + kt + q * 8];
            uint4 vl = *(const uint4*)&Bl[(size_t)r * kd + kt + q * 8];
            uint32_t off = (uint32_t)(r * SROW + q * 16);
            asm volatile("st.shared.v4.b32 [%0], {%1, %2, %3, %4};"
                         :: "r"(stBhi + off), "r"(vh.x), "r"(vh.y), "r"(vh.z), "r"(vh.w) : "memory");
            asm volatile("st.shared.v4.b32 [%0], {%1, %2, %3, %4};"
                         :: "r"(stBlo + off), "r"(vl.x), "r"(vl.y), "r"(vl.z), "r"(vl.w) : "memory");
        }
        __syncthreads();
        // ---- compute ----
#pragma unroll
        for (int kb = 0; kb < 2; kb++) {
            uint32_t ah[4], al[4];
            ldm4(ah, bAhi + kb * 32);
            ldm4(al, bAlo + kb * 32);
#pragma unroll
            for (int nt = 0; nt < 8; nt++) {
                uint32_t bh[4], blr[4];
                ldm4(bh,  bBhi + nt * 16 * SROW + kb * 32);
                ldm4(blr, bBlo + nt * 16 * SROW + kb * 32);
                mma16816(acc[2 * nt],     ah, &bh[0]);
                mma16816(acc[2 * nt],     ah, &blr[0]);
                mma16816(acc[2 * nt],     al, &bh[0]);
                mma16816(acc[2 * nt + 1], ah, &bh[2]);
                mma16816(acc[2 * nt + 1], ah, &blr[2]);
                mma16816(acc[2 * nt + 1], al, &bh[2]);
            }
        }
    }

    // ---- epilogue ----
    const int r_in = lane >> 2;
    const int cq = (lane & 3) * 2;
    if (which == 1 || mode == 0) {
#pragma unroll
        for (int p = 0; p < 2; p++) {
            int row = row0 + wid * 16 + r_in + p * 8;
            if (row < NN) {
                float dv = g_dinv[row];
#pragma unroll
                for (int nt = 0; nt < 16; nt++) {
                    *(float2*)&g_hws[(size_t)row * DH + nt * 8 + cq] =
                        make_float2(acc[nt][2 * p] * dv, acc[nt][2 * p + 1] * dv);
                }
            }
        }
    } else {
#pragma unroll
        for (int p = 0; p < 2; p++) {
            float s = 0.f, q = 0.f;
#pragma unroll
            for (int nt = 0; nt < 16; nt++) {
                float v0 = acc[nt][2 * p]     + s_lb[nt * 8 + cq];
                float v1 = acc[nt][2 * p + 1] + s_lb[nt * 8 + cq + 1];
                s += v0 + v1; q += v0 * v0 + v1 * v1;
            }
            s += __shfl_xor_sync(0xffffffffu, s, 1);
            s += __shfl_xor_sync(0xffffffffu, s, 2);
            q += __shfl_xor_sync(0xffffffffu, q, 1);
            q += __shfl_xor_sync(0xffffffffu, q, 2);
            float m = s * (1.f / DH);
            float var = q * (1.f / DH) - m * m;
            float rstd = rsqrtf(var + 1e-5f);
            int row = row0 + wid * 16 + r_in + p * 8;
            if (row < NN) {
#pragma unroll
                for (int nt = 0; nt < 16; nt++) {
                    int c = nt * 8 + cq;
                    float v0 = acc[nt][2 * p]     + s_lb[c];
                    float v1 = acc[nt][2 * p + 1] + s_lb[c + 1];
                    *(float2*)&g_res[(size_t)row * DH + c] =
                        make_float2((v0 - m) * rstd * s_lg[c]     + s_lbe[c],
                                    (v1 - m) * rstd * s_lg[c + 1] + s_lbe[c + 1]);
                }
            }
        }
    }
}

// ---------------- agg1: h1 = elu(LN(agg*dinv + b1)) + res ----------------------
__global__ __launch_bounds__(256) void k_agg1(const float* __restrict__ b1,
                                              const float* __restrict__ g1,
                                              const float* __restrict__ be1) {
    int n = (blockIdx.x * blockDim.x + threadIdx.x) >> 5;
    if (n >= NN) return;
    int lane = threadIdx.x & 31;
    float4 a = agg_row(n, lane);
    float dv = g_dinv[n];
    float4 bb = *(const float4*)&b1[lane * 4];
    float v0 = fmaf(a.x, dv, bb.x), v1 = fmaf(a.y, dv, bb.y);
    float v2 = fmaf(a.z, dv, bb.z), v3 = fmaf(a.w, dv, bb.w);
    float s = v0 + v1 + v2 + v3;
    float q = v0 * v0 + v1 * v1 + v2 * v2 + v3 * v3;
#pragma unroll
    for (int o = 16; o; o >>= 1) {
        s += __shfl_xor_sync(0xffffffffu, s, o);
        q += __shfl_xor_sync(0xffffffffu, q, o);
    }
    float m = s * (1.f / DH);
    float var = q * (1.f / DH) - m * m;
    float rstd = rsqrtf(var + 1e-5f);
    float4 gg = *(const float4*)&g1[lane * 4];
    float4 be = *(const float4*)&be1[lane * 4];
    float y0 = elu1((v0 - m) * rstd * gg.x + be.x);
    float y1 = elu1((v1 - m) * rstd * gg.y + be.y);
    float y2 = elu1((v2 - m) * rstd * gg.z + be.z);
    float y3 = elu1((v3 - m) * rstd * gg.w + be.w);
    float4 r = *(const float4*)&g_res[(size_t)n * DH + lane * 4];
    *(float4*)&g_h1[(size_t)n * DH + lane * 4] =
        make_float4(y0 + r.x, y1 + r.y, y2 + r.z, y3 + r.w);
}

// ---------------- epilogue 2 (fused agg) + MLP head + softmax ------------------
#define EPI2_SMEM ((128 * 128 + 8 * 4 * 132) * 4)
__global__ __launch_bounds__(256, 2) void k_epi2(
    const float* __restrict__ b2, const float* __restrict__ g2, const float* __restrict__ be2,
    const float* __restrict__ mW1, const float* __restrict__ mb1,
    const float* __restrict__ mg_, const float* __restrict__ mbe_,
    const float* __restrict__ mW2, const float* __restrict__ mb2,
    float* __restrict__ out)
{
    extern __shared__ float sm[];
    float* W1s = sm;
    float* h2s = sm + 128 * 128;
    const int tid = threadIdx.x;
    for (int i = tid; i < 128 * 128 / 4; i += 256)
        ((float4*)W1s)[i] = ((const float4*)mW1)[i];
    __syncthreads();

    const int wid = tid >> 5, lane = tid & 31;
    float* myh2 = h2s + wid * (4 * 132);
    float4 b2v  = *(const float4*)&b2 [lane * 4];
    float4 g2v  = *(const float4*)&g2 [lane * 4];
    float4 be2v = *(const float4*)&be2[lane * 4];
    float4 mb1v = *(const float4*)&mb1[lane * 4];
    float4 mgv  = *(const float4*)&mg_[lane * 4];
    float4 mbev = *(const float4*)&mbe_[lane * 4];
    float mb2v[16];
#pragma unroll
    for (int c = 0; c < 16; c++) mb2v[c] = mb2[c];

    const int gw = blockIdx.x * 8 + wid;
    const int step = gridDim.x * 8 * 4;
    for (int nb = gw * 4; nb < NN; nb += step) {
#pragma unroll
        for (int s2 = 0; s2 < 4; s2++) {
            int n = nb + s2;
            float4 a = make_float4(0.f, 0.f, 0.f, 0.f), r = a;
            float dv = 0.f;
            if (n < NN) {
                dv = g_dinv[n];
                a = agg_row(n, lane);
                r = *(const float4*)&g_h1[(size_t)n * DH + lane * 4];
            }
            float v0 = fmaf(a.x, dv, b2v.x), v1 = fmaf(a.y, dv, b2v.y);
            float v2 = fmaf(a.z, dv, b2v.z), v3 = fmaf(a.w, dv, b2v.w);
            float s = v0 + v1 + v2 + v3;
            float q = v0 * v0 + v1 * v1 + v2 * v2 + v3 * v3;
#pragma unroll
            for (int o = 16; o; o >>= 1) {
                s += __shfl_xor_sync(0xffffffffu, s, o);
                q += __shfl_xor_sync(0xffffffffu, q, o);
            }
            float m = s * (1.f / DH);
            float var = q * (1.f / DH) - m * m;
            float rstd = rsqrtf(var + 1e-5f);
            float y0 = elu1((v0 - m) * rstd * g2v.x + be2v.x) + r.x;
            float y1 = elu1((v1 - m) * rstd * g2v.y + be2v.y) + r.y;
            float y2 = elu1((v2 - m) * rstd * g2v.z + be2v.z) + r.z;
            float y3 = elu1((v3 - m) * rstd * g2v.w + be2v.w) + r.w;
            *(float4*)&myh2[s2 * 132 + lane * 4] = make_float4(y0, y1, y2, y3);
        }
        __syncwarp();

        float4 zz[4];
#pragma unroll
        for (int s2 = 0; s2 < 4; s2++) zz[s2] = mb1v;
        for (int kk = 0; kk < 32; kk++) {
            float4 hq0 = *(const float4*)&myh2[0 * 132 + 4 * kk];
            float4 hq1 = *(const float4*)&myh2[1 * 132 + 4 * kk];
            float4 hq2 = *(const float4*)&myh2[2 * 132 + 4 * kk];
            float4 hq3 = *(const float4*)&myh2[3 * 132 + 4 * kk];
            float ha0[4] = {hq0.x, hq0.y, hq0.z, hq0.w};
            float ha1[4] = {hq1.x, hq1.y, hq1.z, hq1.w};
            float ha2[4] = {hq2.x, hq2.y, hq2.z, hq2.w};
            float ha3[4] = {hq3.x, hq3.y, hq3.z, hq3.w};
#pragma unroll
            for (int j = 0; j < 4; j++) {
                float4 w = *(const float4*)&W1s[(4 * kk + j) * 128 + lane * 4];
                zz[0].x = fmaf(ha0[j], w.x, zz[0].x); zz[0].y = fmaf(ha0[j], w.y, zz[0].y);
                zz[0].z = fmaf(ha0[j], w.z, zz[0].z); zz[0].w = fmaf(ha0[j], w.w, zz[0].w);
                zz[1].x = fmaf(ha1[j], w.x, zz[1].x); zz[1].y = fmaf(ha1[j], w.y, zz[1].y);
                zz[1].z = fmaf(ha1[j], w.z, zz[1].z); zz[1].w = fmaf(ha1[j], w.w, zz[1].w);
                zz[2].x = fmaf(ha2[j], w.x, zz[2].x); zz[2].y = fmaf(ha2[j], w.y, zz[2].y);
                zz[2].z = fmaf(ha2[j], w.z, zz[2].z); zz[2].w = fmaf(ha2[j], w.w, zz[2].w);
                zz[3].x = fmaf(ha3[j], w.x, zz[3].x); zz[3].y = fmaf(ha3[j], w.y, zz[3].y);
                zz[3].z = fmaf(ha3[j], w.z, zz[3].z); zz[3].w = fmaf(ha3[j], w.w, zz[3].w);
            }
        }
        __syncwarp();

#pragma unroll
        for (int s2 = 0; s2 < 4; s2++) {
            float4 z = zz[s2];
            float s = z.x + z.y + z.z + z.w;
            float q = z.x * z.x + z.y * z.y + z.z * z.z + z.w * z.w;
#pragma unroll
            for (int o = 16; o; o >>= 1) {
                s += __shfl_xor_sync(0xffffffffu, s, o);
                q += __shfl_xor_sync(0xffffffffu, q, o);
            }
            float m = s * (1.f / DH);
            float var = q * (1.f / DH) - m * m;
            float rstd = rsqrtf(var + 1e-5f);
            z.x = elu1((z.x - m) * rstd * mgv.x + mbev.x);
            z.y = elu1((z.y - m) * rstd * mgv.y + mbev.y);
            z.z = elu1((z.z - m) * rstd * mgv.z + mbev.z);
            z.w = elu1((z.w - m) * rstd * mgv.w + mbev.w);
            zz[s2] = z;
        }

#pragma unroll
        for (int s2 = 0; s2 < 4; s2++) {
            float Hp[16];
#pragma unroll
            for (int c = 0; c < 16; c++) Hp[c] = 0.f;
            float za[4] = {zz[s2].x, zz[s2].y, zz[s2].z, zz[s2].w};
#pragma unroll
            for (int j = 0; j < 4; j++) {
                int k = 4 * lane + j;
                const float4* wr = (const float4*)&mW2[k * 16];
                float4 w0 = wr[0], w1 = wr[1], w2 = wr[2], w3 = wr[3];
                float zv = za[j];
                Hp[0]  = fmaf(zv, w0.x, Hp[0]);  Hp[1]  = fmaf(zv, w0.y, Hp[1]);
                Hp[2]  = fmaf(zv, w0.z, Hp[2]);  Hp[3]  = fmaf(zv, w0.w, Hp[3]);
                Hp[4]  = fmaf(zv, w1.x, Hp[4]);  Hp[5]  = fmaf(zv, w1.y, Hp[5]);
                Hp[6]  = fmaf(zv, w1.z, Hp[6]);  Hp[7]  = fmaf(zv, w1.w, Hp[7]);
                Hp[8]  = fmaf(zv, w2.x, Hp[8]);  Hp[9]  = fmaf(zv, w2.y, Hp[9]);
                Hp[10] = fmaf(zv, w2.z, Hp[10]); Hp[11] = fmaf(zv, w2.w, Hp[11]);
                Hp[12] = fmaf(zv, w3.x, Hp[12]); Hp[13] = fmaf(zv, w3.y, Hp[13]);
                Hp[14] = fmaf(zv, w3.z, Hp[14]); Hp[15] = fmaf(zv, w3.w, Hp[15]);
            }
#pragma unroll
            for (int o = 16; o; o >>= 1)
#pragma unroll
                for (int c = 0; c < 16; c++)
                    Hp[c] += __shfl_xor_sync(0xffffffffu, Hp[c], o);
            int n = nb + s2;
            if (lane == 0 && n < NN) {
                float mx = -1e30f;
#pragma unroll
                for (int c = 0; c < 16; c++) { Hp[c] += mb2v[c]; mx = fmaxf(mx, Hp[c]); }
                float ss = 0.f;
#pragma unroll
                for (int c = 0; c < 16; c++) { Hp[c] = __expf(Hp[c] - mx); ss += Hp[c]; }
                float inv = 1.f / ss;
                *(float4*)&out[(size_t)n * 16 + 0]  = make_float4(Hp[0] * inv, Hp[1] * inv, Hp[2] * inv, Hp[3] * inv);
                *(float4*)&out[(size_t)n * 16 + 4]  = make_float4(Hp[4] * inv, Hp[5] * inv, Hp[6] * inv, Hp[7] * inv);
                *(float4*)&out[(size_t)n * 16 + 8]  = make_float4(Hp[8] * inv, Hp[9] * inv, Hp[10] * inv, Hp[11] * inv);
                *(float4*)&out[(size_t)n * 16 + 12] = make_float4(Hp[12] * inv, Hp[13] * inv, Hp[14] * inv, Hp[15] * inv);
            }
        }
    }
}

// ---------------- launcher -----------------------------------------------------
extern "C" void kernel_launch(void* const* d_in, const int* in_sizes, int n_in,
                              void* d_out, int out_size) {
    const float* x   = (const float*)d_in[0];
    const void*  ei  = d_in[1];
    const float* W1  = (const float*)d_in[2];
    const float* b1  = (const float*)d_in[3];
    const float* g1  = (const float*)d_in[4];
    const float* be1 = (const float*)d_in[5];
    const float* W2  = (const float*)d_in[6];
    const float* b2  = (const float*)d_in[7];
    const float* g2  = (const float*)d_in[8];
    const float* be2 = (const float*)d_in[9];
    const float* rW  = (const float*)d_in[10];
    const float* rb  = (const float*)d_in[11];
    const float* rg  = (const float*)d_in[12];
    const float* rbe = (const float*)d_in[13];
    const float* mW1 = (const float*)d_in[14];
    const float* mb1 = (const float*)d_in[15];
    const float* mg  = (const float*)d_in[16];
    const float* mbe = (const float*)d_in[17];
    const float* mW2 = (const float*)d_in[18];
    const float* mb2 = (const float*)d_in[19];
    float* out = (float*)d_out;

    cudaFuncSetAttribute(k_epi2, cudaFuncAttributeMaxDynamicSharedMemorySize, EPI2_SMEM);

    // 0: prep (weights + zero counts + dtype detect)
    k_prep<<<(2 * DH * DIN + DH * DH + 255) / 256, 256>>>(W1, rW, W2, ei);
    // 1: degree histogram
    k_hist<<<(EE + 255) / 256, 256>>>(ei);
    // 2-4: parallel scan (also writes g_dinv in scan1)
    k_scan1<<<NB_SCAN, 256>>>();
    k_scan2<<<1, 256>>>();
    k_scan3<<<NB_SCAN, 256>>>();

    const int nblk = (NN + 127) / 128;  // 391
    // 5: layer-1 GEMM (captured by ncu -s 5 -c 1)
    dim3 grid1(nblk, 2);
    k_gemm_mma<<<grid1, 256>>>(x, DIN, 0, rb, rg, rbe);
    // 6: CSR fill
    k_fill<<<(EE + 255) / 256, 256>>>(ei);
    // 7: layer-1 aggregation + epilogue
    k_agg1<<<(NN * 32 + 255) / 256, 256>>>(b1, g1, be1);
    // 8: layer-2 GEMM
    dim3 grid2(nblk, 1);
    k_gemm_mma<<<grid2, 256>>>(x, DH, 1, rb, rg, rbe);
    // 9: fused layer-2 aggregation + MLP head + softmax
    k_epi2<<<296, 256, EPI2_SMEM>>>(b2, g2, be2, mW1, mb1, mg, mbe, mW2, mb2, out);
}

// round 7
// speedup vs baseline: 2.1031x; 1.1070x over previous
#include <cuda_runtime.h>
#include <cuda_bf16.h>
#include <math.h>
#include <stdint.h>

#define NN 50000
#define EE 800000
#define DIN 384
#define DH 128
#define NB_SCAN 196   // ceil(50000/256)

// ---------------- scratch (device globals) ------------------------------------
__device__ int   g_is64;
__device__ int   g_cnt[NN];
__device__ int   g_bsum[256];
__device__ int   g_off[NN + 1];
__device__ int   g_cur[NN];
__device__ int   g_csr[EE];
__device__ float g_dinv[NN];
__device__ float g_hws[NN * DH];
__device__ float g_res[NN * DH];   // layer1: LN residual; later: h2
__device__ float g_h1 [NN * DH];
// split-precision transposed weights: [N=128, K] row-major
__device__ unsigned short g_b1hi[DH * DIN];  // W1^T
__device__ unsigned short g_b1lo[DH * DIN];
__device__ unsigned short g_brhi[DH * DIN];  // rW^T
__device__ unsigned short g_brlo[DH * DIN];
__device__ unsigned short g_w2hi[DH * DH];   // W2^T
__device__ unsigned short g_w2lo[DH * DH];
__device__ unsigned short g_m1hi[DH * DH];   // mW1^T
__device__ unsigned short g_m1lo[DH * DH];

// ---------------- helpers ------------------------------------------------------
__device__ __forceinline__ float elu1(float x) { return x > 0.f ? x : expm1f(x); }

__device__ __forceinline__ uint32_t smem_u32(const void* p) {
    uint32_t a;
    asm("{ .reg .u64 t; cvta.to.shared.u64 t, %1; cvt.u32.u64 %0, t; }" : "=r"(a) : "l"(p));
    return a;
}

__device__ __forceinline__ void ldm4(uint32_t* r, uint32_t addr) {
    asm volatile("ldmatrix.sync.aligned.m8n8.x4.shared.b16 {%0,%1,%2,%3}, [%4];"
                 : "=r"(r[0]), "=r"(r[1]), "=r"(r[2]), "=r"(r[3]) : "r"(addr));
}
__device__ __forceinline__ void mma16816(float* d, const uint32_t* a, const uint32_t* b) {
    asm volatile("mma.sync.aligned.m16n8k16.row.col.f32.bf16.bf16.f32 "
                 "{%0,%1,%2,%3}, {%4,%5,%6,%7}, {%8,%9}, {%0,%1,%2,%3};"
                 : "+f"(d[0]), "+f"(d[1]), "+f"(d[2]), "+f"(d[3])
                 : "r"(a[0]), "r"(a[1]), "r"(a[2]), "r"(a[3]), "r"(b[0]), "r"(b[1]));
}

__device__ __forceinline__ void load_edge(const void* ei, int e, int& s, int& d) {
    if (g_is64) {
        const long long* p = (const long long*)ei;
        s = (int)p[e]; d = (int)p[EE + e];
    } else {
        const int* p = (const int*)ei;
        s = p[e]; d = p[EE + e];
    }
}

// inclusive block scan over 256 threads
__device__ __forceinline__ int block_scan_incl(int v, int* ws) {
    int lane = threadIdx.x & 31, w = threadIdx.x >> 5;
    int x = v;
#pragma unroll
    for (int o = 1; o < 32; o <<= 1) {
        int u = __shfl_up_sync(0xffffffffu, x, o);
        if (lane >= o) x += u;
    }
    if (lane == 31) ws[w] = x;
    __syncthreads();
    if (w == 0) {
        int t = (lane < 8) ? ws[lane] : 0;
#pragma unroll
        for (int o = 1; o < 8; o <<= 1) {
            int u = __shfl_up_sync(0xffffffffu, t, o);
            if (lane >= o) t += u;
        }
        if (lane < 8) ws[lane] = t;
    }
    __syncthreads();
    if (w > 0) x += ws[w - 1];
    return x;
}

// Pull-mode aggregation: self + sum of neighbor rows (rows are pre-scaled).
__device__ __forceinline__ float4 agg_row(int n, int lane) {
    float4 a = *(const float4*)&g_hws[(size_t)n * DH + lane * 4];
    int e  = g_off[n];
    int e1 = g_off[n + 1];
    for (; e + 4 <= e1; e += 4) {
        int s0 = g_csr[e], s1 = g_csr[e + 1], s2 = g_csr[e + 2], s3 = g_csr[e + 3];
        float4 v0 = *(const float4*)&g_hws[(size_t)s0 * DH + lane * 4];
        float4 v1 = *(const float4*)&g_hws[(size_t)s1 * DH + lane * 4];
        float4 v2 = *(const float4*)&g_hws[(size_t)s2 * DH + lane * 4];
        float4 v3 = *(const float4*)&g_hws[(size_t)s3 * DH + lane * 4];
        a.x += (v0.x + v1.x) + (v2.x + v3.x);
        a.y += (v0.y + v1.y) + (v2.y + v3.y);
        a.z += (v0.z + v1.z) + (v2.z + v3.z);
        a.w += (v0.w + v1.w) + (v2.w + v3.w);
    }
    for (; e < e1; e++) {
        int s0 = g_csr[e];
        float4 v0 = *(const float4*)&g_hws[(size_t)s0 * DH + lane * 4];
        a.x += v0.x; a.y += v0.y; a.z += v0.z; a.w += v0.w;
    }
    return a;
}

// ---------------- weight prep + init -------------------------------------------
__global__ void k_prep(const float* __restrict__ W1, const float* __restrict__ rW,
                       const float* __restrict__ W2, const float* __restrict__ mW1,
                       const void* edges) {
    int i = blockIdx.x * blockDim.x + threadIdx.x;
    if (i < NN) g_cnt[i] = 0;
    if (i == 0) {
        const unsigned long long* p = (const unsigned long long*)edges;
        int is64 = 1;
        for (int j = 0; j < 8; j++) if (p[j] >= (unsigned long long)NN) is64 = 0;
        g_is64 = is64;
    }
    float val;
    unsigned short *ph, *pl;
    int idx;
    if (i < DH * DIN) {
        int n = i / DIN, k = i % DIN;
        val = W1[k * DH + n]; ph = g_b1hi; pl = g_b1lo; idx = i;
    } else if (i < 2 * DH * DIN) {
        int j = i - DH * DIN;
        int n = j / DIN, k = j % DIN;
        val = rW[k * DH + n]; ph = g_brhi; pl = g_brlo; idx = j;
    } else if (i < 2 * DH * DIN + DH * DH) {
        int j = i - 2 * DH * DIN;
        int n = j / DH, k = j % DH;
        val = W2[k * DH + n]; ph = g_w2hi; pl = g_w2lo; idx = j;
    } else if (i < 2 * DH * DIN + 2 * DH * DH) {
        int j = i - 2 * DH * DIN - DH * DH;
        int n = j / DH, k = j % DH;
        val = mW1[k * DH + n]; ph = g_m1hi; pl = g_m1lo; idx = j;
    } else return;
    __nv_bfloat16 h = __float2bfloat16(val);
    float r = val - __bfloat162float(h);
    __nv_bfloat16 l = __float2bfloat16(r);
    ph[idx] = __bfloat16_as_ushort(h);
    pl[idx] = __bfloat16_as_ushort(l);
}

__global__ void k_hist(const void* edges) {
    int e = blockIdx.x * blockDim.x + threadIdx.x;
    if (e >= EE) return;
    int s, d;
    load_edge(edges, e, s, d);
    atomicAdd(&g_cnt[d], 1);
}

// ---------------- parallel 3-phase scan ----------------------------------------
__global__ void k_scan1() {
    __shared__ int ws[8];
    int i = blockIdx.x * 256 + threadIdx.x;
    int c = (i < NN) ? g_cnt[i] : 0;
    if (i < NN) g_dinv[i] = rsqrtf((float)(c + 1));
    int lane = threadIdx.x & 31, w = threadIdx.x >> 5;
    int v = c;
#pragma unroll
    for (int o = 16; o; o >>= 1) v += __shfl_xor_sync(0xffffffffu, v, o);
    if (lane == 0) ws[w] = v;
    __syncthreads();
    if (w == 0) {
        int t = (lane < 8) ? ws[lane] : 0;
#pragma unroll
        for (int o = 4; o; o >>= 1) t += __shfl_xor_sync(0xffffffffu, t, o);
        if (lane == 0) g_bsum[blockIdx.x] = t;
    }
}

__global__ void k_scan2() {
    __shared__ int ws[8];
    int t = threadIdx.x;
    int v = (t < NB_SCAN) ? g_bsum[t] : 0;
    int incl = block_scan_incl(v, ws);
    g_bsum[t] = incl - v;
}

__global__ void k_scan3() {
    __shared__ int ws[8];
    int i = blockIdx.x * 256 + threadIdx.x;
    int c = (i < NN) ? g_cnt[i] : 0;
    int incl = block_scan_incl(c, ws);
    int base = g_bsum[blockIdx.x];
    int excl = base + incl - c;
    if (i < NN) { g_off[i] = excl; g_cur[i] = excl; }
    if (i == NN - 1) g_off[NN] = base + incl;
}

__global__ void k_fill(const void* edges) {
    int e = blockIdx.x * blockDim.x + threadIdx.x;
    if (e >= EE) return;
    int s, d;
    load_edge(edges, e, s, d);
    int pos = atomicAdd(&g_cur[d], 1);
    g_csr[pos] = s;
}

// ---------------- A-chunk conversion helper ------------------------------------
__device__ __forceinline__ void cvt_store_a(float4 v, uint32_t dst_hi, uint32_t dst_lo) {
    uint32_t h01, h23;
    asm("cvt.rn.bf16x2.f32 %0, %1, %2;" : "=r"(h01) : "f"(v.y), "f"(v.x));
    asm("cvt.rn.bf16x2.f32 %0, %1, %2;" : "=r"(h23) : "f"(v.w), "f"(v.z));
    float rx = v.x - __uint_as_float(h01 << 16);
    float ry = v.y - __uint_as_float(h01 & 0xffff0000u);
    float rz = v.z - __uint_as_float(h23 << 16);
    float rw = v.w - __uint_as_float(h23 & 0xffff0000u);
    uint32_t l01, l23;
    asm("cvt.rn.bf16x2.f32 %0, %1, %2;" : "=r"(l01) : "f"(ry), "f"(rx));
    asm("cvt.rn.bf16x2.f32 %0, %1, %2;" : "=r"(l23) : "f"(rw), "f"(rz));
    asm volatile("st.shared.v2.b32 [%0], {%1, %2};" :: "r"(dst_hi), "r"(h01), "r"(h23) : "memory");
    asm volatile("st.shared.v2.b32 [%0], {%1, %2};" :: "r"(dst_lo), "r"(l01), "r"(l23) : "memory");
}

// ---------------- tensor-core GEMM via mma.sync (bf16x3 split) -----------------
// which==0: A=x (kd=384). blockIdx.y: 0 -> W1, dinv-scale -> g_hws
//                                     1 -> rW, LayerNorm  -> g_res
// which==1: A=g_h1 (kd=128): W2, dinv-scale -> g_hws
#define SROW 80   // padded smem row stride in bytes (conflict-free for ldmatrix)

__global__ __launch_bounds__(256, 2) void k_gemm_mma(
    const float* __restrict__ Ain, int kd, int which,
    const float* __restrict__ lb, const float* __restrict__ lg, const float* __restrict__ lbe)
{
    __shared__ __align__(16) unsigned char sA_hi[128 * SROW];
    __shared__ __align__(16) unsigned char sA_lo[128 * SROW];
    __shared__ __align__(16) unsigned char sB_hi[128 * SROW];
    __shared__ __align__(16) unsigned char sB_lo[128 * SROW];
    __shared__ float s_lb[DH], s_lg[DH], s_lbe[DH];

    const int tid  = threadIdx.x;
    const int wid  = tid >> 5;
    const int lane = tid & 31;
    const int mode = blockIdx.y;
    const int row0 = blockIdx.x * 128;
    const float* A = which ? (const float*)g_h1 : Ain;
    const unsigned short* Bh;
    const unsigned short* Bl;
    if (which == 0) { Bh = mode ? g_brhi : g_b1hi; Bl = mode ? g_brlo : g_b1lo; }
    else            { Bh = g_w2hi; Bl = g_w2lo; }

    if (which == 0 && mode == 1 && tid < DH) {
        s_lb[tid] = lb[tid]; s_lg[tid] = lg[tid]; s_lbe[tid] = lbe[tid];
    }

    float acc[16][4];
#pragma unroll
    for (int i = 0; i < 16; i++)
#pragma unroll
        for (int j = 0; j < 4; j++) acc[i][j] = 0.f;

    const uint32_t bAhi = smem_u32(sA_hi) + (wid * 16 + (lane & 15)) * SROW + ((lane >> 4) & 1) * 16;
    const uint32_t bAlo = smem_u32(sA_lo) + (wid * 16 + (lane & 15)) * SROW + ((lane >> 4) & 1) * 16;
    const uint32_t nrow = (uint32_t)((lane & 7) | ((lane >> 4) << 3));
    const uint32_t bBhi = smem_u32(sB_hi) + nrow * SROW + ((lane >> 3) & 1) * 16;
    const uint32_t bBlo = smem_u32(sB_lo) + nrow * SROW + ((lane >> 3) & 1) * 16;
    const uint32_t stAhi = smem_u32(sA_hi), stAlo = smem_u32(sA_lo);
    const uint32_t stBhi = smem_u32(sB_hi), stBlo = smem_u32(sB_lo);

    // addressing for loads
    const int ar = tid >> 3, aq = tid & 7;        // + u*32 rows
    const int br = tid >> 2, bq = tid & 3;        // + u*64 rows
    const int agr = row0 + ar;

    float4 pa[4];
    uint4  pbh[2], pbl[2];
    const int T = kd >> 5;

    // prefetch chunk 0
#pragma unroll
    for (int u = 0; u < 4; u++) {
        int gr = agr + u * 32;
        pa[u] = (gr < NN) ? *(const float4*)&A[(size_t)gr * kd + aq * 4]
                          : make_float4(0.f, 0.f, 0.f, 0.f);
    }
#pragma unroll
    for (int u = 0; u < 2; u++) {
        int r = br + u * 64;
        pbh[u] = *(const uint4*)&Bh[(size_t)r * kd + bq * 8];
        pbl[u] = *(const uint4*)&Bl[(size_t)r * kd + bq * 8];
    }

    for (int t = 0; t < T; t++) {
        // ---- store prefetched chunk to smem ----
#pragma unroll
        for (int u = 0; u < 4; u++) {
            uint32_t off = (uint32_t)((ar + u * 32) * SROW + aq * 8);
            cvt_store_a(pa[u], stAhi + off, stAlo + off);
        }
#pragma unroll
        for (int u = 0; u < 2; u++) {
            uint32_t off = (uint32_t)((br + u * 64) * SROW + bq * 16);
            asm volatile("st.shared.v4.b32 [%0], {%1, %2, %3, %4};"
                         :: "r"(stBhi + off), "r"(pbh[u].x), "r"(pbh[u].y), "r"(pbh[u].z), "r"(pbh[u].w) : "memory");
            asm volatile("st.shared.v4.b32 [%0], {%1, %2, %3, %4};"
                         :: "r"(stBlo + off), "r"(pbl[u].x), "r"(pbl[u].y), "r"(pbl[u].z), "r"(pbl[u].w) : "memory");
        }
        __syncthreads();
        // ---- prefetch next chunk (LDGs overlap compute) ----
        if (t + 1 < T) {
            const int kt = (t + 1) << 5;
#pragma unroll
            for (int u = 0; u < 4; u++) {
                int gr = agr + u * 32;
                pa[u] = (gr < NN) ? *(const float4*)&A[(size_t)gr * kd + kt + aq * 4]
                                  : make_float4(0.f, 0.f, 0.f, 0.f);
            }
#pragma unroll
            for (int u = 0; u < 2; u++) {
                int r = br + u * 64;
                pbh[u] = *(const uint4*)&Bh[(size_t)r * kd + kt + bq * 8];
                pbl[u] = *(const uint4*)&Bl[(size_t)r * kd + kt + bq * 8];
            }
        }
        // ---- compute ----
#pragma unroll
        for (int kb = 0; kb < 2; kb++) {
            uint32_t ah[4], al[4];
            ldm4(ah, bAhi + kb * 32);
            ldm4(al, bAlo + kb * 32);
#pragma unroll
            for (int nt = 0; nt < 8; nt++) {
                uint32_t bh[4], blr[4];
                ldm4(bh,  bBhi + nt * 16 * SROW + kb * 32);
                ldm4(blr, bBlo + nt * 16 * SROW + kb * 32);
                mma16816(acc[2 * nt],     ah, &bh[0]);
                mma16816(acc[2 * nt],     ah, &blr[0]);
                mma16816(acc[2 * nt],     al, &bh[0]);
                mma16816(acc[2 * nt + 1], ah, &bh[2]);
                mma16816(acc[2 * nt + 1], ah, &blr[2]);
                mma16816(acc[2 * nt + 1], al, &bh[2]);
            }
        }
        __syncthreads();
    }

    // ---- epilogue ----
    const int r_in = lane >> 2;
    const int cq = (lane & 3) * 2;
    if (which == 1 || mode == 0) {
#pragma unroll
        for (int p = 0; p < 2; p++) {
            int row = row0 + wid * 16 + r_in + p * 8;
            if (row < NN) {
                float dv = g_dinv[row];
#pragma unroll
                for (int nt = 0; nt < 16; nt++) {
                    *(float2*)&g_hws[(size_t)row * DH + nt * 8 + cq] =
                        make_float2(acc[nt][2 * p] * dv, acc[nt][2 * p + 1] * dv);
                }
            }
        }
    } else {
#pragma unroll
        for (int p = 0; p < 2; p++) {
            float s = 0.f, q = 0.f;
#pragma unroll
            for (int nt = 0; nt < 16; nt++) {
                float v0 = acc[nt][2 * p]     + s_lb[nt * 8 + cq];
                float v1 = acc[nt][2 * p + 1] + s_lb[nt * 8 + cq + 1];
                s += v0 + v1; q += v0 * v0 + v1 * v1;
            }
            s += __shfl_xor_sync(0xffffffffu, s, 1);
            s += __shfl_xor_sync(0xffffffffu, s, 2);
            q += __shfl_xor_sync(0xffffffffu, q, 1);
            q += __shfl_xor_sync(0xffffffffu, q, 2);
            float m = s * (1.f / DH);
            float var = q * (1.f / DH) - m * m;
            float rstd = rsqrtf(var + 1e-5f);
            int row = row0 + wid * 16 + r_in + p * 8;
            if (row < NN) {
#pragma unroll
                for (int nt = 0; nt < 16; nt++) {
                    int c = nt * 8 + cq;
                    float v0 = acc[nt][2 * p]     + s_lb[c];
                    float v1 = acc[nt][2 * p + 1] + s_lb[c + 1];
                    *(float2*)&g_res[(size_t)row * DH + c] =
                        make_float2((v0 - m) * rstd * s_lg[c]     + s_lbe[c],
                                    (v1 - m) * rstd * s_lg[c + 1] + s_lbe[c + 1]);
                }
            }
        }
    }
}

// ---------------- agg kernels ---------------------------------------------------
// phase==0: h1 = elu(LN(agg*dinv + b)) + res          -> g_h1
// phase==1: h2 = elu(LN(agg*dinv + b)) + h1           -> g_res
__global__ __launch_bounds__(256) void k_agg(const float* __restrict__ b,
                                             const float* __restrict__ g,
                                             const float* __restrict__ be,
                                             int phase) {
    int n = (blockIdx.x * blockDim.x + threadIdx.x) >> 5;
    if (n >= NN) return;
    int lane = threadIdx.x & 31;
    float4 a = agg_row(n, lane);
    float dv = g_dinv[n];
    float4 bb = *(const float4*)&b[lane * 4];
    float v0 = fmaf(a.x, dv, bb.x), v1 = fmaf(a.y, dv, bb.y);
    float v2 = fmaf(a.z, dv, bb.z), v3 = fmaf(a.w, dv, bb.w);
    float s = v0 + v1 + v2 + v3;
    float q = v0 * v0 + v1 * v1 + v2 * v2 + v3 * v3;
#pragma unroll
    for (int o = 16; o; o >>= 1) {
        s += __shfl_xor_sync(0xffffffffu, s, o);
        q += __shfl_xor_sync(0xffffffffu, q, o);
    }
    float m = s * (1.f / DH);
    float var = q * (1.f / DH) - m * m;
    float rstd = rsqrtf(var + 1e-5f);
    float4 gg = *(const float4*)&g[lane * 4];
    float4 bev = *(const float4*)&be[lane * 4];
    float y0 = elu1((v0 - m) * rstd * gg.x + bev.x);
    float y1 = elu1((v1 - m) * rstd * gg.y + bev.y);
    float y2 = elu1((v2 - m) * rstd * gg.z + bev.z);
    float y3 = elu1((v3 - m) * rstd * gg.w + bev.w);
    const float* radd = phase ? &g_h1[(size_t)n * DH + lane * 4]
                              : &g_res[(size_t)n * DH + lane * 4];
    float4 r = *(const float4*)radd;
    float* outp = phase ? &g_res[(size_t)n * DH + lane * 4]
                        : &g_h1[(size_t)n * DH + lane * 4];
    *(float4*)outp = make_float4(y0 + r.x, y1 + r.y, y2 + r.z, y3 + r.w);
}

// ---------------- head: z = elu(LN(h2@mW1 + mb1)), H = z@mW2 + mb2, softmax ----
__global__ __launch_bounds__(256) void k_head(
    const float* __restrict__ mb1, const float* __restrict__ mg_,
    const float* __restrict__ mbe_, const float* __restrict__ mW2,
    const float* __restrict__ mb2, float* __restrict__ out)
{
    __shared__ __align__(16) unsigned char sA_hi[128 * SROW];
    __shared__ __align__(16) unsigned char sA_lo[128 * SROW];
    __shared__ __align__(16) unsigned char sB_hi[128 * SROW];
    __shared__ __align__(16) unsigned char sB_lo[128 * SROW];
    __shared__ float s_w2[128 * 17];
    __shared__ float s_lb[DH], s_lg[DH], s_lbe[DH], s_mb2[16];

    const int tid  = threadIdx.x;
    const int wid  = tid >> 5;
    const int lane = tid & 31;
    const int row0 = blockIdx.x * 128;
    const float* A = (const float*)g_res;   // h2
    const int kd = DH;

    for (int i = tid; i < 128 * 16; i += 256)
        s_w2[(i >> 4) * 17 + (i & 15)] = mW2[i];
    if (tid < DH) { s_lb[tid] = mb1[tid]; s_lg[tid] = mg_[tid]; s_lbe[tid] = mbe_[tid]; }
    if (tid < 16) s_mb2[tid] = mb2[tid];

    float acc[16][4];
#pragma unroll
    for (int i = 0; i < 16; i++)
#pragma unroll
        for (int j = 0; j < 4; j++) acc[i][j] = 0.f;

    const uint32_t bAhi = smem_u32(sA_hi) + (wid * 16 + (lane & 15)) * SROW + ((lane >> 4) & 1) * 16;
    const uint32_t bAlo = smem_u32(sA_lo) + (wid * 16 + (lane & 15)) * SROW + ((lane >> 4) & 1) * 16;
    const uint32_t nrow = (uint32_t)((lane & 7) | ((lane >> 4) << 3));
    const uint32_t bBhi = smem_u32(sB_hi) + nrow * SROW + ((lane >> 3) & 1) * 16;
    const uint32_t bBlo = smem_u32(sB_lo) + nrow * SROW + ((lane >> 3) & 1) * 16;
    const uint32_t stAhi = smem_u32(sA_hi), stAlo = smem_u32(sA_lo);
    const uint32_t stBhi = smem_u32(sB_hi), stBlo = smem_u32(sB_lo);

    const int ar = tid >> 3, aq = tid & 7;
    const int br = tid >> 2, bq = tid & 3;
    const int agr = row0 + ar;

    float4 pa[4];
    uint4  pbh[2], pbl[2];
    const int T = kd >> 5;   // 4

#pragma unroll
    for (int u = 0; u < 4; u++) {
        int gr = agr + u * 32;
        pa[u] = (gr < NN) ? *(const float4*)&A[(size_t)gr * kd + aq * 4]
                          : make_float4(0.f, 0.f, 0.f, 0.f);
    }
#pragma unroll
    for (int u = 0; u < 2; u++) {
        int r = br + u * 64;
        pbh[u] = *(const uint4*)&g_m1hi[(size_t)r * kd + bq * 8];
        pbl[u] = *(const uint4*)&g_m1lo[(size_t)r * kd + bq * 8];
    }

    for (int t = 0; t < T; t++) {
#pragma unroll
        for (int u = 0; u < 4; u++) {
            uint32_t off = (uint32_t)((ar + u * 32) * SROW + aq * 8);
            cvt_store_a(pa[u], stAhi + off, stAlo + off);
        }
#pragma unroll
        for (int u = 0; u < 2; u++) {
            uint32_t off = (uint32_t)((br + u * 64) * SROW + bq * 16);
            asm volatile("st.shared.v4.b32 [%0], {%1, %2, %3, %4};"
                         :: "r"(stBhi + off), "r"(pbh[u].x), "r"(pbh[u].y), "r"(pbh[u].z), "r"(pbh[u].w) : "memory");
            asm volatile("st.shared.v4.b32 [%0], {%1, %2, %3, %4};"
                         :: "r"(stBlo + off), "r"(pbl[u].x), "r"(pbl[u].y), "r"(pbl[u].z), "r"(pbl[u].w) : "memory");
        }
        __syncthreads();
        if (t + 1 < T) {
            const int kt = (t + 1) << 5;
#pragma unroll
            for (int u = 0; u < 4; u++) {
                int gr = agr + u * 32;
                pa[u] = (gr < NN) ? *(const float4*)&A[(size_t)gr * kd + kt + aq * 4]
                                  : make_float4(0.f, 0.f, 0.f, 0.f);
            }
#pragma unroll
            for (int u = 0; u < 2; u++) {
                int r = br + u * 64;
                pbh[u] = *(const uint4*)&g_m1hi[(size_t)r * kd + kt + bq * 8];
                pbl[u] = *(const uint4*)&g_m1lo[(size_t)r * kd + kt + bq * 8];
            }
        }
#pragma unroll
        for (int kb = 0; kb < 2; kb++) {
            uint32_t ah[4], al[4];
            ldm4(ah, bAhi + kb * 32);
            ldm4(al, bAlo + kb * 32);
#pragma unroll
            for (int nt = 0; nt < 8; nt++) {
                uint32_t bh[4], blr[4];
                ldm4(bh,  bBhi + nt * 16 * SROW + kb * 32);
                ldm4(blr, bBlo + nt * 16 * SROW + kb * 32);
                mma16816(acc[2 * nt],     ah, &bh[0]);
                mma16816(acc[2 * nt],     ah, &blr[0]);
                mma16816(acc[2 * nt],     al, &bh[0]);
                mma16816(acc[2 * nt + 1], ah, &bh[2]);
                mma16816(acc[2 * nt + 1], ah, &blr[2]);
                mma16816(acc[2 * nt + 1], al, &bh[2]);
            }
        }
        __syncthreads();
    }

    // ---- in-register epilogue: +mb1, LN, elu, z@mW2, softmax ----
    const int r_in = lane >> 2;
    const int cq = (lane & 3) * 2;
#pragma unroll
    for (int p = 0; p < 2; p++) {
        float z[32];
        float s = 0.f, q = 0.f;
#pragma unroll
        for (int nt = 0; nt < 16; nt++) {
            int c = nt * 8 + cq;
            float v0 = acc[nt][2 * p]     + s_lb[c];
            float v1 = acc[nt][2 * p + 1] + s_lb[c + 1];
            z[2 * nt] = v0; z[2 * nt + 1] = v1;
            s += v0 + v1; q += v0 * v0 + v1 * v1;
        }
        s += __shfl_xor_sync(0xffffffffu, s, 1);
        s += __shfl_xor_sync(0xffffffffu, s, 2);
        q += __shfl_xor_sync(0xffffffffu, q, 1);
        q += __shfl_xor_sync(0xffffffffu, q, 2);
        float m = s * (1.f / DH);
        float var = q * (1.f / DH) - m * m;
        float rstd = rsqrtf(var + 1e-5f);
#pragma unroll
        for (int nt = 0; nt < 16; nt++) {
            int c = nt * 8 + cq;
            z[2 * nt]     = elu1((z[2 * nt]     - m) * rstd * s_lg[c]     + s_lbe[c]);
            z[2 * nt + 1] = elu1((z[2 * nt + 1] - m) * rstd * s_lg[c + 1] + s_lbe[c + 1]);
        }
        float Hp[16];
#pragma unroll
        for (int c16 = 0; c16 < 16; c16++) Hp[c16] = 0.f;
#pragma unroll
        for (int nt = 0; nt < 16; nt++) {
            const float* w0 = &s_w2[(nt * 8 + cq) * 17];
            const float* w1 = &s_w2[(nt * 8 + cq + 1) * 17];
            float z0 = z[2 * nt], z1 = z[2 * nt + 1];
#pragma unroll
            for (int c16 = 0; c16 < 16; c16++)
                Hp[c16] = fmaf(z0, w0[c16], fmaf(z1, w1[c16], Hp[c16]));
        }
#pragma unroll
        for (int c16 = 0; c16 < 16; c16++) {
            Hp[c16] += __shfl_xor_sync(0xffffffffu, Hp[c16], 1);
            Hp[c16] += __shfl_xor_sync(0xffffffffu, Hp[c16], 2);
        }
        int row = row0 + wid * 16 + r_in + p * 8;
        if ((lane & 3) == 0 && row < NN) {
            float mx = -1e30f;
#pragma unroll
            for (int c16 = 0; c16 < 16; c16++) { Hp[c16] += s_mb2[c16]; mx = fmaxf(mx, Hp[c16]); }
            float ss = 0.f;
#pragma unroll
            for (int c16 = 0; c16 < 16; c16++) { Hp[c16] = __expf(Hp[c16] - mx); ss += Hp[c16]; }
            float inv = 1.f / ss;
            *(float4*)&out[(size_t)row * 16 + 0]  = make_float4(Hp[0] * inv, Hp[1] * inv, Hp[2] * inv, Hp[3] * inv);
            *(float4*)&out[(size_t)row * 16 + 4]  = make_float4(Hp[4] * inv, Hp[5] * inv, Hp[6] * inv, Hp[7] * inv);
            *(float4*)&out[(size_t)row * 16 + 8]  = make_float4(Hp[8] * inv, Hp[9] * inv, Hp[10] * inv, Hp[11] * inv);
            *(float4*)&out[(size_t)row * 16 + 12] = make_float4(Hp[12] * inv, Hp[13] * inv, Hp[14] * inv, Hp[15] * inv);
        }
    }
}

// ---------------- launcher -----------------------------------------------------
extern "C" void kernel_launch(void* const* d_in, const int* in_sizes, int n_in,
                              void* d_out, int out_size) {
    const float* x   = (const float*)d_in[0];
    const void*  ei  = d_in[1];
    const float* W1  = (const float*)d_in[2];
    const float* b1  = (const float*)d_in[3];
    const float* g1  = (const float*)d_in[4];
    const float* be1 = (const float*)d_in[5];
    const float* W2  = (const float*)d_in[6];
    const float* b2  = (const float*)d_in[7];
    const float* g2  = (const float*)d_in[8];
    const float* be2 = (const float*)d_in[9];
    const float* rW  = (const float*)d_in[10];
    const float* rb  = (const float*)d_in[11];
    const float* rg  = (const float*)d_in[12];
    const float* rbe = (const float*)d_in[13];
    const float* mW1 = (const float*)d_in[14];
    const float* mb1 = (const float*)d_in[15];
    const float* mg  = (const float*)d_in[16];
    const float* mbe = (const float*)d_in[17];
    const float* mW2 = (const float*)d_in[18];
    const float* mb2 = (const float*)d_in[19];
    float* out = (float*)d_out;

    // setup
    k_prep<<<(2 * DH * DIN + 2 * DH * DH + 255) / 256, 256>>>(W1, rW, W2, mW1, ei);
    k_hist<<<(EE + 255) / 256, 256>>>(ei);
    k_scan1<<<NB_SCAN, 256>>>();
    k_scan2<<<1, 256>>>();
    k_scan3<<<NB_SCAN, 256>>>();

    const int nblk = (NN + 127) / 128;  // 391
    // layer 1 GEMM (both weight matrices)
    dim3 grid1(nblk, 2);
    k_gemm_mma<<<grid1, 256>>>(x, DIN, 0, rb, rg, rbe);
    // CSR fill (overlaps gemm tail)
    k_fill<<<(EE + 255) / 256, 256>>>(ei);
    // layer-1 aggregation + epilogue -> g_h1
    k_agg<<<(NN * 32 + 255) / 256, 256>>>(b1, g1, be1, 0);
    // layer 2 GEMM
    dim3 grid2(nblk, 1);
    k_gemm_mma<<<grid2, 256>>>(x, DH, 1, rb, rg, rbe);
    // layer-2 aggregation + epilogue -> g_res (h2)
    k_agg<<<(NN * 32 + 255) / 256, 256>>>(b2, g2, be2, 1);
    // MLP head + softmax (tensor-core)
    k_head<<<nblk, 256>>>(mb1, mg, mbe, mW2, mb2, out);
}

// round 8
// speedup vs baseline: 2.1175x; 1.0069x over previous
#include <cuda_runtime.h>
#include <cuda_bf16.h>
#include <cuda_fp16.h>
#include <math.h>
#include <stdint.h>

#define NN 50000
#define EE 800000
#define DIN 384
#define DH 128
#define NB_SCAN 196   // ceil(50000/256)

// ---------------- scratch (device globals) ------------------------------------
__device__ int   g_is64;
__device__ int   g_cnt[NN];
__device__ int   g_bsum[256];
__device__ int   g_off[NN + 1];
__device__ int   g_csr[EE];
__device__ int   g_eidx[EE];
__device__ int   g_src32[EE];
__device__ int   g_dst32[EE];
__device__ float g_dinv[NN];
__device__ unsigned short g_hws[NN * DH];   // fp16 message rows (pre-scaled)
__device__ float g_res[NN * DH];            // layer1: LN residual; later: h2
__device__ float g_h1 [NN * DH];
// split-precision transposed weights: [N=128, K] row-major
__device__ unsigned short g_b1hi[DH * DIN];  // W1^T
__device__ unsigned short g_b1lo[DH * DIN];
__device__ unsigned short g_brhi[DH * DIN];  // rW^T
__device__ unsigned short g_brlo[DH * DIN];
__device__ unsigned short g_w2hi[DH * DH];   // W2^T
__device__ unsigned short g_w2lo[DH * DH];
__device__ unsigned short g_m1hi[DH * DH];   // mW1^T
__device__ unsigned short g_m1lo[DH * DH];

// ---------------- helpers ------------------------------------------------------
__device__ __forceinline__ float elu1(float x) { return x > 0.f ? x : expm1f(x); }

__device__ __forceinline__ uint32_t smem_u32(const void* p) {
    uint32_t a;
    asm("{ .reg .u64 t; cvta.to.shared.u64 t, %1; cvt.u32.u64 %0, t; }" : "=r"(a) : "l"(p));
    return a;
}

__device__ __forceinline__ void ldm4(uint32_t* r, uint32_t addr) {
    asm volatile("ldmatrix.sync.aligned.m8n8.x4.shared.b16 {%0,%1,%2,%3}, [%4];"
                 : "=r"(r[0]), "=r"(r[1]), "=r"(r[2]), "=r"(r[3]) : "r"(addr));
}
__device__ __forceinline__ void mma16816(float* d, const uint32_t* a, const uint32_t* b) {
    asm volatile("mma.sync.aligned.m16n8k16.row.col.f32.bf16.bf16.f32 "
                 "{%0,%1,%2,%3}, {%4,%5,%6,%7}, {%8,%9}, {%0,%1,%2,%3};"
                 : "+f"(d[0]), "+f"(d[1]), "+f"(d[2]), "+f"(d[3])
                 : "r"(a[0]), "r"(a[1]), "r"(a[2]), "r"(a[3]), "r"(b[0]), "r"(b[1]));
}

__device__ __forceinline__ void load_edge(const void* ei, int e, int& s, int& d) {
    if (g_is64) {
        const long long* p = (const long long*)ei;
        s = (int)p[e]; d = (int)p[EE + e];
    } else {
        const int* p = (const int*)ei;
        s = p[e]; d = p[EE + e];
    }
}

// inclusive block scan over 256 threads
__device__ __forceinline__ int block_scan_incl(int v, int* ws) {
    int lane = threadIdx.x & 31, w = threadIdx.x >> 5;
    int x = v;
#pragma unroll
    for (int o = 1; o < 32; o <<= 1) {
        int u = __shfl_up_sync(0xffffffffu, x, o);
        if (lane >= o) x += u;
    }
    if (lane == 31) ws[w] = x;
    __syncthreads();
    if (w == 0) {
        int t = (lane < 8) ? ws[lane] : 0;
#pragma unroll
        for (int o = 1; o < 8; o <<= 1) {
            int u = __shfl_up_sync(0xffffffffu, t, o);
            if (lane >= o) t += u;
        }
        if (lane < 8) ws[lane] = t;
    }
    __syncthreads();
    if (w > 0) x += ws[w - 1];
    return x;
}

// fp16 row gather: lane handles cols [lane*4, lane*4+4) = one uint2 (8 B)
__device__ __forceinline__ float4 h8_to_f4(uint2 u) {
    __half2 h0 = *(__half2*)&u.x;
    __half2 h1 = *(__half2*)&u.y;
    float2 f0 = __half22float2(h0);
    float2 f1 = __half22float2(h1);
    return make_float4(f0.x, f0.y, f1.x, f1.y);
}

// Pull-mode aggregation: self + sum of neighbor rows (rows pre-scaled, fp16).
__device__ __forceinline__ float4 agg_row(int n, int lane) {
    const uint2* hw = (const uint2*)g_hws;   // 32 uint2 per row
    float4 a = h8_to_f4(hw[(size_t)n * 32 + lane]);
    int e  = g_off[n];
    int e1 = g_off[n + 1];
    for (; e + 4 <= e1; e += 4) {
        int s0 = g_csr[e], s1 = g_csr[e + 1], s2 = g_csr[e + 2], s3 = g_csr[e + 3];
        float4 v0 = h8_to_f4(hw[(size_t)s0 * 32 + lane]);
        float4 v1 = h8_to_f4(hw[(size_t)s1 * 32 + lane]);
        float4 v2 = h8_to_f4(hw[(size_t)s2 * 32 + lane]);
        float4 v3 = h8_to_f4(hw[(size_t)s3 * 32 + lane]);
        a.x += (v0.x + v1.x) + (v2.x + v3.x);
        a.y += (v0.y + v1.y) + (v2.y + v3.y);
        a.z += (v0.z + v1.z) + (v2.z + v3.z);
        a.w += (v0.w + v1.w) + (v2.w + v3.w);
    }
    for (; e < e1; e++) {
        float4 v0 = h8_to_f4(hw[(size_t)g_csr[e] * 32 + lane]);
        a.x += v0.x; a.y += v0.y; a.z += v0.z; a.w += v0.w;
    }
    return a;
}

// ---------------- weight prep + init -------------------------------------------
__global__ void k_prep(const float* __restrict__ W1, const float* __restrict__ rW,
                       const float* __restrict__ W2, const float* __restrict__ mW1,
                       const void* edges) {
    int i = blockIdx.x * blockDim.x + threadIdx.x;
    if (i < NN) g_cnt[i] = 0;
    if (i == 0) {
        const unsigned long long* p = (const unsigned long long*)edges;
        int is64 = 1;
        for (int j = 0; j < 8; j++) if (p[j] >= (unsigned long long)NN) is64 = 0;
        g_is64 = is64;
    }
    float val;
    unsigned short *ph, *pl;
    int idx;
    if (i < DH * DIN) {
        int n = i / DIN, k = i % DIN;
        val = W1[k * DH + n]; ph = g_b1hi; pl = g_b1lo; idx = i;
    } else if (i < 2 * DH * DIN) {
        int j = i - DH * DIN;
        int n = j / DIN, k = j % DIN;
        val = rW[k * DH + n]; ph = g_brhi; pl = g_brlo; idx = j;
    } else if (i < 2 * DH * DIN + DH * DH) {
        int j = i - 2 * DH * DIN;
        int n = j / DH, k = j % DH;
        val = W2[k * DH + n]; ph = g_w2hi; pl = g_w2lo; idx = j;
    } else if (i < 2 * DH * DIN + 2 * DH * DH) {
        int j = i - 2 * DH * DIN - DH * DH;
        int n = j / DH, k = j % DH;
        val = mW1[k * DH + n]; ph = g_m1hi; pl = g_m1lo; idx = j;
    } else return;
    __nv_bfloat16 h = __float2bfloat16(val);
    float r = val - __bfloat162float(h);
    __nv_bfloat16 l = __float2bfloat16(r);
    ph[idx] = __bfloat16_as_ushort(h);
    pl[idx] = __bfloat16_as_ushort(l);
}

// histogram; also decode edges to int32 and record per-node slot index
__global__ void k_hist(const void* edges) {
    int e = blockIdx.x * blockDim.x + threadIdx.x;
    if (e >= EE) return;
    int s, d;
    load_edge(edges, e, s, d);
    int idx = atomicAdd(&g_cnt[d], 1);
    g_eidx [e] = idx;
    g_src32[e] = s;
    g_dst32[e] = d;
}

// ---------------- parallel 3-phase scan ----------------------------------------
__global__ void k_scan1() {
    __shared__ int ws[8];
    int i = blockIdx.x * 256 + threadIdx.x;
    int c = (i < NN) ? g_cnt[i] : 0;
    if (i < NN) g_dinv[i] = rsqrtf((float)(c + 1));
    int lane = threadIdx.x & 31, w = threadIdx.x >> 5;
    int v = c;
#pragma unroll
    for (int o = 16; o; o >>= 1) v += __shfl_xor_sync(0xffffffffu, v, o);
    if (lane == 0) ws[w] = v;
    __syncthreads();
    if (w == 0) {
        int t = (lane < 8) ? ws[lane] : 0;
#pragma unroll
        for (int o = 4; o; o >>= 1) t += __shfl_xor_sync(0xffffffffu, t, o);
        if (lane == 0) g_bsum[blockIdx.x] = t;
    }
}

__global__ void k_scan2() {
    __shared__ int ws[8];
    int t = threadIdx.x;
    int v = (t < NB_SCAN) ? g_bsum[t] : 0;
    int incl = block_scan_incl(v, ws);
    g_bsum[t] = incl - v;
}

__global__ void k_scan3() {
    __shared__ int ws[8];
    int i = blockIdx.x * 256 + threadIdx.x;
    int c = (i < NN) ? g_cnt[i] : 0;
    int incl = block_scan_incl(c, ws);
    int base = g_bsum[blockIdx.x];
    int excl = base + incl - c;
    if (i < NN) g_off[i] = excl;
    if (i == NN - 1) g_off[NN] = base + incl;
}

// atomic-free CSR fill using slot indices from k_hist
__global__ void k_fill(const void*) {
    int e = blockIdx.x * blockDim.x + threadIdx.x;
    if (e >= EE) return;
    int d = g_dst32[e];
    g_csr[g_off[d] + g_eidx[e]] = g_src32[e];
}

// ---------------- A-chunk conversion helper ------------------------------------
__device__ __forceinline__ void cvt_store_a(float4 v, uint32_t dst_hi, uint32_t dst_lo) {
    uint32_t h01, h23;
    asm("cvt.rn.bf16x2.f32 %0, %1, %2;" : "=r"(h01) : "f"(v.y), "f"(v.x));
    asm("cvt.rn.bf16x2.f32 %0, %1, %2;" : "=r"(h23) : "f"(v.w), "f"(v.z));
    float rx = v.x - __uint_as_float(h01 << 16);
    float ry = v.y - __uint_as_float(h01 & 0xffff0000u);
    float rz = v.z - __uint_as_float(h23 << 16);
    float rw = v.w - __uint_as_float(h23 & 0xffff0000u);
    uint32_t l01, l23;
    asm("cvt.rn.bf16x2.f32 %0, %1, %2;" : "=r"(l01) : "f"(ry), "f"(rx));
    asm("cvt.rn.bf16x2.f32 %0, %1, %2;" : "=r"(l23) : "f"(rw), "f"(rz));
    asm volatile("st.shared.v2.b32 [%0], {%1, %2};" :: "r"(dst_hi), "r"(h01), "r"(h23) : "memory");
    asm volatile("st.shared.v2.b32 [%0], {%1, %2};" :: "r"(dst_lo), "r"(l01), "r"(l23) : "memory");
}

// ---------------- tensor-core GEMM via mma.sync (bf16x3 split) -----------------
// which==0: A=x (kd=384). blockIdx.y: 0 -> W1, dinv-scale -> g_hws (fp16)
//                                     1 -> rW, LayerNorm  -> g_res
// which==1: A=g_h1 (kd=128): W2, dinv-scale -> g_hws (fp16)
#define SROW 80   // padded smem row stride in bytes (conflict-free for ldmatrix)

__global__ __launch_bounds__(256, 2) void k_gemm_mma(
    const float* __restrict__ Ain, int kd, int which,
    const float* __restrict__ lb, const float* __restrict__ lg, const float* __restrict__ lbe)
{
    __shared__ __align__(16) unsigned char sA_hi[128 * SROW];
    __shared__ __align__(16) unsigned char sA_lo[128 * SROW];
    __shared__ __align__(16) unsigned char sB_hi[128 * SROW];
    __shared__ __align__(16) unsigned char sB_lo[128 * SROW];
    __shared__ float s_lb[DH], s_lg[DH], s_lbe[DH];

    const int tid  = threadIdx.x;
    const int wid  = tid >> 5;
    const int lane = tid & 31;
    const int mode = blockIdx.y;
    const int row0 = blockIdx.x * 128;
    const float* A = which ? (const float*)g_h1 : Ain;
    const unsigned short* Bh;
    const unsigned short* Bl;
    if (which == 0) { Bh = mode ? g_brhi : g_b1hi; Bl = mode ? g_brlo : g_b1lo; }
    else            { Bh = g_w2hi; Bl = g_w2lo; }

    if (which == 0 && mode == 1 && tid < DH) {
        s_lb[tid] = lb[tid]; s_lg[tid] = lg[tid]; s_lbe[tid] = lbe[tid];
    }

    float acc[16][4];
#pragma unroll
    for (int i = 0; i < 16; i++)
#pragma unroll
        for (int j = 0; j < 4; j++) acc[i][j] = 0.f;

    const uint32_t bAhi = smem_u32(sA_hi) + (wid * 16 + (lane & 15)) * SROW + ((lane >> 4) & 1) * 16;
    const uint32_t bAlo = smem_u32(sA_lo) + (wid * 16 + (lane & 15)) * SROW + ((lane >> 4) & 1) * 16;
    const uint32_t nrow = (uint32_t)((lane & 7) | ((lane >> 4) << 3));
    const uint32_t bBhi = smem_u32(sB_hi) + nrow * SROW + ((lane >> 3) & 1) * 16;
    const uint32_t bBlo = smem_u32(sB_lo) + nrow * SROW + ((lane >> 3) & 1) * 16;
    const uint32_t stAhi = smem_u32(sA_hi), stAlo = smem_u32(sA_lo);
    const uint32_t stBhi = smem_u32(sB_hi), stBlo = smem_u32(sB_lo);

    const int ar = tid >> 3, aq = tid & 7;
    const int br = tid >> 2, bq = tid & 3;
    const int agr = row0 + ar;

    float4 pa[4];
    uint4  pbh[2], pbl[2];
    const int T = kd >> 5;

#pragma unroll
    for (int u = 0; u < 4; u++) {
        int gr = agr + u * 32;
        pa[u] = (gr < NN) ? *(const float4*)&A[(size_t)gr * kd + aq * 4]
                          : make_float4(0.f, 0.f, 0.f, 0.f);
    }
#pragma unroll
    for (int u = 0; u < 2; u++) {
        int r = br + u * 64;
        pbh[u] = *(const uint4*)&Bh[(size_t)r * kd + bq * 8];
        pbl[u] = *(const uint4*)&Bl[(size_t)r * kd + bq * 8];
    }

    for (int t = 0; t < T; t++) {
#pragma unroll
        for (int u = 0; u < 4; u++) {
            uint32_t off = (uint32_t)((ar + u * 32) * SROW + aq * 8);
            cvt_store_a(pa[u], stAhi + off, stAlo + off);
        }
#pragma unroll
        for (int u = 0; u < 2; u++) {
            uint32_t off = (uint32_t)((br + u * 64) * SROW + bq * 16);
            asm volatile("st.shared.v4.b32 [%0], {%1, %2, %3, %4};"
                         :: "r"(stBhi + off), "r"(pbh[u].x), "r"(pbh[u].y), "r"(pbh[u].z), "r"(pbh[u].w) : "memory");
            asm volatile("st.shared.v4.b32 [%0], {%1, %2, %3, %4};"
                         :: "r"(stBlo + off), "r"(pbl[u].x), "r"(pbl[u].y), "r"(pbl[u].z), "r"(pbl[u].w) : "memory");
        }
        __syncthreads();
        if (t + 1 < T) {
            const int kt = (t + 1) << 5;
#pragma unroll
            for (int u = 0; u < 4; u++) {
                int gr = agr + u * 32;
                pa[u] = (gr < NN) ? *(const float4*)&A[(size_t)gr * kd + kt + aq * 4]
                                  : make_float4(0.f, 0.f, 0.f, 0.f);
            }
#pragma unroll
            for (int u = 0; u < 2; u++) {
                int r = br + u * 64;
                pbh[u] = *(const uint4*)&Bh[(size_t)r * kd + kt + bq * 8];
                pbl[u] = *(const uint4*)&Bl[(size_t)r * kd + kt + bq * 8];
            }
        }
#pragma unroll
        for (int kb = 0; kb < 2; kb++) {
            uint32_t ah[4], al[4];
            ldm4(ah, bAhi + kb * 32);
            ldm4(al, bAlo + kb * 32);
#pragma unroll
            for (int nt = 0; nt < 8; nt++) {
                uint32_t bh[4], blr[4];
                ldm4(bh,  bBhi + nt * 16 * SROW + kb * 32);
                ldm4(blr, bBlo + nt * 16 * SROW + kb * 32);
                mma16816(acc[2 * nt],     ah, &bh[0]);
                mma16816(acc[2 * nt],     ah, &blr[0]);
                mma16816(acc[2 * nt],     al, &bh[0]);
                mma16816(acc[2 * nt + 1], ah, &bh[2]);
                mma16816(acc[2 * nt + 1], ah, &blr[2]);
                mma16816(acc[2 * nt + 1], al, &bh[2]);
            }
        }
        __syncthreads();
    }

    // ---- epilogue ----
    const int r_in = lane >> 2;
    const int cq = (lane & 3) * 2;
    if (which == 1 || mode == 0) {
#pragma unroll
        for (int p = 0; p < 2; p++) {
            int row = row0 + wid * 16 + r_in + p * 8;
            if (row < NN) {
                float dv = g_dinv[row];
#pragma unroll
                for (int nt = 0; nt < 16; nt++) {
                    __half2 hh = __floats2half2_rn(acc[nt][2 * p] * dv, acc[nt][2 * p + 1] * dv);
                    *(__half2*)&g_hws[(size_t)row * DH + nt * 8 + cq] = hh;
                }
            }
        }
    } else {
#pragma unroll
        for (int p = 0; p < 2; p++) {
            float s = 0.f, q = 0.f;
#pragma unroll
            for (int nt = 0; nt < 16; nt++) {
                float v0 = acc[nt][2 * p]     + s_lb[nt * 8 + cq];
                float v1 = acc[nt][2 * p + 1] + s_lb[nt * 8 + cq + 1];
                s += v0 + v1; q += v0 * v0 + v1 * v1;
            }
            s += __shfl_xor_sync(0xffffffffu, s, 1);
            s += __shfl_xor_sync(0xffffffffu, s, 2);
            q += __shfl_xor_sync(0xffffffffu, q, 1);
            q += __shfl_xor_sync(0xffffffffu, q, 2);
            float m = s * (1.f / DH);
            float var = q * (1.f / DH) - m * m;
            float rstd = rsqrtf(var + 1e-5f);
            int row = row0 + wid * 16 + r_in + p * 8;
            if (row < NN) {
#pragma unroll
                for (int nt = 0; nt < 16; nt++) {
                    int c = nt * 8 + cq;
                    float v0 = acc[nt][2 * p]     + s_lb[c];
                    float v1 = acc[nt][2 * p + 1] + s_lb[c + 1];
                    *(float2*)&g_res[(size_t)row * DH + c] =
                        make_float2((v0 - m) * rstd * s_lg[c]     + s_lbe[c],
                                    (v1 - m) * rstd * s_lg[c + 1] + s_lbe[c + 1]);
                }
            }
        }
    }
}

// ---------------- agg kernels ---------------------------------------------------
// phase==0: h1 = elu(LN(agg*dinv + b)) + res          -> g_h1
// phase==1: h2 = elu(LN(agg*dinv + b)) + h1           -> g_res
__global__ __launch_bounds__(256) void k_agg(const float* __restrict__ b,
                                             const float* __restrict__ g,
                                             const float* __restrict__ be,
                                             int phase) {
    int n = (blockIdx.x * blockDim.x + threadIdx.x) >> 5;
    if (n >= NN) return;
    int lane = threadIdx.x & 31;
    float4 a = agg_row(n, lane);
    float dv = g_dinv[n];
    float4 bb = *(const float4*)&b[lane * 4];
    float v0 = fmaf(a.x, dv, bb.x), v1 = fmaf(a.y, dv, bb.y);
    float v2 = fmaf(a.z, dv, bb.z), v3 = fmaf(a.w, dv, bb.w);
    float s = v0 + v1 + v2 + v3;
    float q = v0 * v0 + v1 * v1 + v2 * v2 + v3 * v3;
#pragma unroll
    for (int o = 16; o; o >>= 1) {
        s += __shfl_xor_sync(0xffffffffu, s, o);
        q += __shfl_xor_sync(0xffffffffu, q, o);
    }
    float m = s * (1.f / DH);
    float var = q * (1.f / DH) - m * m;
    float rstd = rsqrtf(var + 1e-5f);
    float4 gg = *(const float4*)&g[lane * 4];
    float4 bev = *(const float4*)&be[lane * 4];
    float y0 = elu1((v0 - m) * rstd * gg.x + bev.x);
    float y1 = elu1((v1 - m) * rstd * gg.y + bev.y);
    float y2 = elu1((v2 - m) * rstd * gg.z + bev.z);
    float y3 = elu1((v3 - m) * rstd * gg.w + bev.w);
    const float* radd = phase ? &g_h1[(size_t)n * DH + lane * 4]
                              : &g_res[(size_t)n * DH + lane * 4];
    float4 r = *(const float4*)radd;
    float* outp = phase ? &g_res[(size_t)n * DH + lane * 4]
                        : &g_h1[(size_t)n * DH + lane * 4];
    *(float4*)outp = make_float4(y0 + r.x, y1 + r.y, y2 + r.z, y3 + r.w);
}

// ---------------- head: z = elu(LN(h2@mW1 + mb1)), H = z@mW2 + mb2, softmax ----
__global__ __launch_bounds__(256) void k_head(
    const float* __restrict__ mb1, const float* __restrict__ mg_,
    const float* __restrict__ mbe_, const float* __restrict__ mW2,
    const float* __restrict__ mb2, float* __restrict__ out)
{
    __shared__ __align__(16) unsigned char sA_hi[128 * SROW];
    __shared__ __align__(16) unsigned char sA_lo[128 * SROW];
    __shared__ __align__(16) unsigned char sB_hi[128 * SROW];
    __shared__ __align__(16) unsigned char sB_lo[128 * SROW];
    __shared__ float s_w2[128 * 17];
    __shared__ float s_lb[DH], s_lg[DH], s_lbe[DH], s_mb2[16];

    const int tid  = threadIdx.x;
    const int wid  = tid >> 5;
    const int lane = tid & 31;
    const int row0 = blockIdx.x * 128;
    const float* A = (const float*)g_res;   // h2
    const int kd = DH;

    for (int i = tid; i < 128 * 16; i += 256)
        s_w2[(i >> 4) * 17 + (i & 15)] = mW2[i];
    if (tid < DH) { s_lb[tid] = mb1[tid]; s_lg[tid] = mg_[tid]; s_lbe[tid] = mbe_[tid]; }
    if (tid < 16) s_mb2[tid] = mb2[tid];

    float acc[16][4];
#pragma unroll
    for (int i = 0; i < 16; i++)
#pragma unroll
        for (int j = 0; j < 4; j++) acc[i][j] = 0.f;

    const uint32_t bAhi = smem_u32(sA_hi) + (wid * 16 + (lane & 15)) * SROW + ((lane >> 4) & 1) * 16;
    const uint32_t bAlo = smem_u32(sA_lo) + (wid * 16 + (lane & 15)) * SROW + ((lane >> 4) & 1) * 16;
    const uint32_t nrow = (uint32_t)((lane & 7) | ((lane >> 4) << 3));
    const uint32_t bBhi = smem_u32(sB_hi) + nrow * SROW + ((lane >> 3) & 1) * 16;
    const uint32_t bBlo = smem_u32(sB_lo) + nrow * SROW + ((lane >> 3) & 1) * 16;
    const uint32_t stAhi = smem_u32(sA_hi), stAlo = smem_u32(sA_lo);
    const uint32_t stBhi = smem_u32(sB_hi), stBlo = smem_u32(sB_lo);

    const int ar = tid >> 3, aq = tid & 7;
    const int br = tid >> 2, bq = tid & 3;
    const int agr = row0 + ar;

    float4 pa[4];
    uint4  pbh[2], pbl[2];
    const int T = kd >> 5;   // 4

#pragma unroll
    for (int u = 0; u < 4; u++) {
        int gr = agr + u * 32;
        pa[u] = (gr < NN) ? *(const float4*)&A[(size_t)gr * kd + aq * 4]
                          : make_float4(0.f, 0.f, 0.f, 0.f);
    }
#pragma unroll
    for (int u = 0; u < 2; u++) {
        int r = br + u * 64;
        pbh[u] = *(const uint4*)&g_m1hi[(size_t)r * kd + bq * 8];
        pbl[u] = *(const uint4*)&g_m1lo[(size_t)r * kd + bq * 8];
    }

    for (int t = 0; t < T; t++) {
#pragma unroll
        for (int u = 0; u < 4; u++) {
            uint32_t off = (uint32_t)((ar + u * 32) * SROW + aq * 8);
            cvt_store_a(pa[u], stAhi + off, stAlo + off);
        }
#pragma unroll
        for (int u = 0; u < 2; u++) {
            uint32_t off = (uint32_t)((br + u * 64) * SROW + bq * 16);
            asm volatile("st.shared.v4.b32 [%0], {%1, %2, %3, %4};"
                         :: "r"(stBhi + off), "r"(pbh[u].x), "r"(pbh[u].y), "r"(pbh[u].z), "r"(pbh[u].w) : "memory");
            asm volatile("st.shared.v4.b32 [%0], {%1, %2, %3, %4};"
                         :: "r"(stBlo + off), "r"(pbl[u].x), "r"(pbl[u].y), "r"(pbl[u].z), "r"(pbl[u].w) : "memory");
        }
        __syncthreads();
        if (t + 1 < T) {
            const int kt = (t + 1) << 5;
#pragma unroll
            for (int u = 0; u < 4; u++) {
                int gr = agr + u * 32;
                pa[u] = (gr < NN) ? *(const float4*)&A[(size_t)gr * kd + kt + aq * 4]
                                  : make_float4(0.f, 0.f, 0.f, 0.f);
            }
#pragma unroll
            for (int u = 0; u < 2; u++) {
                int r = br + u * 64;
                pbh[u] = *(const uint4*)&g_m1hi[(size_t)r * kd + kt + bq * 8];
                pbl[u] = *(const uint4*)&g_m1lo[(size_t)r * kd + kt + bq * 8];
            }
        }
#pragma unroll
        for (int kb = 0; kb < 2; kb++) {
            uint32_t ah[4], al[4];
            ldm4(ah, bAhi + kb * 32);
            ldm4(al, bAlo + kb * 32);
#pragma unroll
            for (int nt = 0; nt < 8; nt++) {
                uint32_t bh[4], blr[4];
                ldm4(bh,  bBhi + nt * 16 * SROW + kb * 32);
                ldm4(blr, bBlo + nt * 16 * SROW + kb * 32);
                mma16816(acc[2 * nt],     ah, &bh[0]);
                mma16816(acc[2 * nt],     ah, &blr[0]);
                mma16816(acc[2 * nt],     al, &bh[0]);
                mma16816(acc[2 * nt + 1], ah, &bh[2]);
                mma16816(acc[2 * nt + 1], ah, &blr[2]);
                mma16816(acc[2 * nt + 1], al, &bh[2]);
            }
        }
        __syncthreads();
    }

    // ---- in-register epilogue: +mb1, LN, elu, z@mW2, softmax ----
    const int r_in = lane >> 2;
    const int cq = (lane & 3) * 2;
#pragma unroll
    for (int p = 0; p < 2; p++) {
        float z[32];
        float s = 0.f, q = 0.f;
#pragma unroll
        for (int nt = 0; nt < 16; nt++) {
            int c = nt * 8 + cq;
            float v0 = acc[nt][2 * p]     + s_lb[c];
            float v1 = acc[nt][2 * p + 1] + s_lb[c + 1];
            z[2 * nt] = v0; z[2 * nt + 1] = v1;
            s += v0 + v1; q += v0 * v0 + v1 * v1;
        }
        s += __shfl_xor_sync(0xffffffffu, s, 1);
        s += __shfl_xor_sync(0xffffffffu, s, 2);
        q += __shfl_xor_sync(0xffffffffu, q, 1);
        q += __shfl_xor_sync(0xffffffffu, q, 2);
        float m = s * (1.f / DH);
        float var = q * (1.f / DH) - m * m;
        float rstd = rsqrtf(var + 1e-5f);
#pragma unroll
        for (int nt = 0; nt < 16; nt++) {
            int c = nt * 8 + cq;
            z[2 * nt]     = elu1((z[2 * nt]     - m) * rstd * s_lg[c]     + s_lbe[c]);
            z[2 * nt + 1] = elu1((z[2 * nt + 1] - m) * rstd * s_lg[c + 1] + s_lbe[c + 1]);
        }
        float Hp[16];
#pragma unroll
        for (int c16 = 0; c16 < 16; c16++) Hp[c16] = 0.f;
#pragma unroll
        for (int nt = 0; nt < 16; nt++) {
            const float* w0 = &s_w2[(nt * 8 + cq) * 17];
            const float* w1 = &s_w2[(nt * 8 + cq + 1) * 17];
            float z0 = z[2 * nt], z1 = z[2 * nt + 1];
#pragma unroll
            for (int c16 = 0; c16 < 16; c16++)
                Hp[c16] = fmaf(z0, w0[c16], fmaf(z1, w1[c16], Hp[c16]));
        }
#pragma unroll
        for (int c16 = 0; c16 < 16; c16++) {
            Hp[c16] += __shfl_xor_sync(0xffffffffu, Hp[c16], 1);
            Hp[c16] += __shfl_xor_sync(0xffffffffu, Hp[c16], 2);
        }
        int row = row0 + wid * 16 + r_in + p * 8;
        if ((lane & 3) == 0 && row < NN) {
            float mx = -1e30f;
#pragma unroll
            for (int c16 = 0; c16 < 16; c16++) { Hp[c16] += s_mb2[c16]; mx = fmaxf(mx, Hp[c16]); }
            float ss = 0.f;
#pragma unroll
            for (int c16 = 0; c16 < 16; c16++) { Hp[c16] = __expf(Hp[c16] - mx); ss += Hp[c16]; }
            float inv = 1.f / ss;
            *(float4*)&out[(size_t)row * 16 + 0]  = make_float4(Hp[0] * inv, Hp[1] * inv, Hp[2] * inv, Hp[3] * inv);
            *(float4*)&out[(size_t)row * 16 + 4]  = make_float4(Hp[4] * inv, Hp[5] * inv, Hp[6] * inv, Hp[7] * inv);
            *(float4*)&out[(size_t)row * 16 + 8]  = make_float4(Hp[8] * inv, Hp[9] * inv, Hp[10] * inv, Hp[11] * inv);
            *(float4*)&out[(size_t)row * 16 + 12] = make_float4(Hp[12] * inv, Hp[13] * inv, Hp[14] * inv, Hp[15] * inv);
        }
    }
}

// ---------------- launcher -----------------------------------------------------
extern "C" void kernel_launch(void* const* d_in, const int* in_sizes, int n_in,
                              void* d_out, int out_size) {
    const float* x   = (const float*)d_in[0];
    const void*  ei  = d_in[1];
    const float* W1  = (const float*)d_in[2];
    const float* b1  = (const float*)d_in[3];
    const float* g1  = (const float*)d_in[4];
    const float* be1 = (const float*)d_in[5];
    const float* W2  = (const float*)d_in[6];
    const float* b2  = (const float*)d_in[7];
    const float* g2  = (const float*)d_in[8];
    const float* be2 = (const float*)d_in[9];
    const float* rW  = (const float*)d_in[10];
    const float* rb  = (const float*)d_in[11];
    const float* rg  = (const float*)d_in[12];
    const float* rbe = (const float*)d_in[13];
    const float* mW1 = (const float*)d_in[14];
    const float* mb1 = (const float*)d_in[15];
    const float* mg  = (const float*)d_in[16];
    const float* mbe = (const float*)d_in[17];
    const float* mW2 = (const float*)d_in[18];
    const float* mb2 = (const float*)d_in[19];
    float* out = (float*)d_out;

    // setup
    k_prep<<<(2 * DH * DIN + 2 * DH * DH + 255) / 256, 256>>>(W1, rW, W2, mW1, ei);
    k_hist<<<(EE + 255) / 256, 256>>>(ei);
    k_scan1<<<NB_SCAN, 256>>>();
    k_scan2<<<1, 256>>>();
    k_scan3<<<NB_SCAN, 256>>>();

    const int nblk = (NN + 127) / 128;  // 391
    // layer 1 GEMM (both weight matrices)
    dim3 grid1(nblk, 2);
    k_gemm_mma<<<grid1, 256>>>(x, DIN, 0, rb, rg, rbe);
    // atomic-free CSR fill
    k_fill<<<(EE + 255) / 256, 256>>>(ei);
    // layer-1 aggregation + epilogue -> g_h1
    k_agg<<<(NN * 32 + 255) / 256, 256>>>(b1, g1, be1, 0);
    // layer 2 GEMM
    dim3 grid2(nblk, 1);
    k_gemm_mma<<<grid2, 256>>>(x, DH, 1, rb, rg, rbe);
    // layer-2 aggregation + epilogue -> g_res (h2)
    k_agg<<<(NN * 32 + 255) / 256, 256>>>(b2, g2, be2, 1);
    // MLP head + softmax (tensor-core)
    k_head<<<nblk, 256>>>(mb1, mg, mbe, mW2, mb2, out);
}

// round 9
// speedup vs baseline: 2.1266x; 1.0043x over previous
#include <cuda_runtime.h>
#include <cuda_bf16.h>
#include <cuda_fp16.h>
#include <math.h>
#include <stdint.h>

#define NN 50000
#define EE 800000
#define DIN 384
#define DH 128
#define NB_SCAN 196   // ceil(50000/256)

// ---------------- scratch (device globals) ------------------------------------
__device__ int   g_is64;
__device__ int   g_cnt[NN];
__device__ int   g_bsum[256];
__device__ int   g_off[NN + 1];
__device__ int   g_csr[EE];
__device__ int   g_eidx[EE];
__device__ int   g_src32[EE];
__device__ int   g_dst32[EE];
__device__ float g_dinv[NN];
__device__ unsigned short g_hws[NN * DH];   // fp16 message rows (pre-scaled)
__device__ float g_res[NN * DH];            // layer1: LN residual; later: h2
__device__ float g_h1 [NN * DH];
// split-precision transposed weights: [N=128, K] row-major
__device__ unsigned short g_b1hi[DH * DIN];  // W1^T
__device__ unsigned short g_b1lo[DH * DIN];
__device__ unsigned short g_brhi[DH * DIN];  // rW^T
__device__ unsigned short g_brlo[DH * DIN];
__device__ unsigned short g_w2hi[DH * DH];   // W2^T
__device__ unsigned short g_w2lo[DH * DH];
__device__ unsigned short g_m1hi[DH * DH];   // mW1^T
__device__ unsigned short g_m1lo[DH * DH];

// ---------------- helpers ------------------------------------------------------
__device__ __forceinline__ float elu1(float x) { return x > 0.f ? x : expm1f(x); }

__device__ __forceinline__ uint32_t smem_u32(const void* p) {
    uint32_t a;
    asm("{ .reg .u64 t; cvta.to.shared.u64 t, %1; cvt.u32.u64 %0, t; }" : "=r"(a) : "l"(p));
    return a;
}

__device__ __forceinline__ void ldm4(uint32_t* r, uint32_t addr) {
    asm volatile("ldmatrix.sync.aligned.m8n8.x4.shared.b16 {%0,%1,%2,%3}, [%4];"
                 : "=r"(r[0]), "=r"(r[1]), "=r"(r[2]), "=r"(r[3]) : "r"(addr));
}
__device__ __forceinline__ void mma16816(float* d, const uint32_t* a, const uint32_t* b) {
    asm volatile("mma.sync.aligned.m16n8k16.row.col.f32.bf16.bf16.f32 "
                 "{%0,%1,%2,%3}, {%4,%5,%6,%7}, {%8,%9}, {%0,%1,%2,%3};"
                 : "+f"(d[0]), "+f"(d[1]), "+f"(d[2]), "+f"(d[3])
                 : "r"(a[0]), "r"(a[1]), "r"(a[2]), "r"(a[3]), "r"(b[0]), "r"(b[1]));
}

__device__ __forceinline__ void load_edge(const void* ei, int e, int& s, int& d) {
    if (g_is64) {
        const long long* p = (const long long*)ei;
        s = (int)p[e]; d = (int)p[EE + e];
    } else {
        const int* p = (const int*)ei;
        s = p[e]; d = p[EE + e];
    }
}

// inclusive block scan over 256 threads
__device__ __forceinline__ int block_scan_incl(int v, int* ws) {
    int lane = threadIdx.x & 31, w = threadIdx.x >> 5;
    int x = v;
#pragma unroll
    for (int o = 1; o < 32; o <<= 1) {
        int u = __shfl_up_sync(0xffffffffu, x, o);
        if (lane >= o) x += u;
    }
    if (lane == 31) ws[w] = x;
    __syncthreads();
    if (w == 0) {
        int t = (lane < 8) ? ws[lane] : 0;
#pragma unroll
        for (int o = 1; o < 8; o <<= 1) {
            int u = __shfl_up_sync(0xffffffffu, t, o);
            if (lane >= o) t += u;
        }
        if (lane < 8) ws[lane] = t;
    }
    __syncthreads();
    if (w > 0) x += ws[w - 1];
    return x;
}

// fp16 row gather: lane handles cols [lane*4, lane*4+4) = one uint2 (8 B)
__device__ __forceinline__ float4 h8_to_f4(uint2 u) {
    __half2 h0 = *(__half2*)&u.x;
    __half2 h1 = *(__half2*)&u.y;
    float2 f0 = __half22float2(h0);
    float2 f1 = __half22float2(h1);
    return make_float4(f0.x, f0.y, f1.x, f1.y);
}

// Pull-mode aggregation: self + sum of neighbor rows (rows pre-scaled, fp16).
__device__ __forceinline__ float4 agg_row(int n, int lane) {
    const uint2* hw = (const uint2*)g_hws;   // 32 uint2 per row
    float4 a = h8_to_f4(hw[(size_t)n * 32 + lane]);
    int e  = g_off[n];
    int e1 = g_off[n + 1];
    for (; e + 4 <= e1; e += 4) {
        int s0 = g_csr[e], s1 = g_csr[e + 1], s2 = g_csr[e + 2], s3 = g_csr[e + 3];
        float4 v0 = h8_to_f4(hw[(size_t)s0 * 32 + lane]);
        float4 v1 = h8_to_f4(hw[(size_t)s1 * 32 + lane]);
        float4 v2 = h8_to_f4(hw[(size_t)s2 * 32 + lane]);
        float4 v3 = h8_to_f4(hw[(size_t)s3 * 32 + lane]);
        a.x += (v0.x + v1.x) + (v2.x + v3.x);
        a.y += (v0.y + v1.y) + (v2.y + v3.y);
        a.z += (v0.z + v1.z) + (v2.z + v3.z);
        a.w += (v0.w + v1.w) + (v2.w + v3.w);
    }
    for (; e < e1; e++) {
        float4 v0 = h8_to_f4(hw[(size_t)g_csr[e] * 32 + lane]);
        a.x += v0.x; a.y += v0.y; a.z += v0.z; a.w += v0.w;
    }
    return a;
}

// ---------------- weight prep + init -------------------------------------------
__global__ void k_prep(const float* __restrict__ W1, const float* __restrict__ rW,
                       const float* __restrict__ W2, const float* __restrict__ mW1,
                       const void* edges) {
    int i = blockIdx.x * blockDim.x + threadIdx.x;
    if (i < NN) g_cnt[i] = 0;
    if (i == 0) {
        const unsigned long long* p = (const unsigned long long*)edges;
        int is64 = 1;
        for (int j = 0; j < 8; j++) if (p[j] >= (unsigned long long)NN) is64 = 0;
        g_is64 = is64;
    }
    float val;
    unsigned short *ph, *pl;
    int idx;
    if (i < DH * DIN) {
        int n = i / DIN, k = i % DIN;
        val = W1[k * DH + n]; ph = g_b1hi; pl = g_b1lo; idx = i;
    } else if (i < 2 * DH * DIN) {
        int j = i - DH * DIN;
        int n = j / DIN, k = j % DIN;
        val = rW[k * DH + n]; ph = g_brhi; pl = g_brlo; idx = j;
    } else if (i < 2 * DH * DIN + DH * DH) {
        int j = i - 2 * DH * DIN;
        int n = j / DH, k = j % DH;
        val = W2[k * DH + n]; ph = g_w2hi; pl = g_w2lo; idx = j;
    } else if (i < 2 * DH * DIN + 2 * DH * DH) {
        int j = i - 2 * DH * DIN - DH * DH;
        int n = j / DH, k = j % DH;
        val = mW1[k * DH + n]; ph = g_m1hi; pl = g_m1lo; idx = j;
    } else return;
    __nv_bfloat16 h = __float2bfloat16(val);
    float r = val - __bfloat162float(h);
    __nv_bfloat16 l = __float2bfloat16(r);
    ph[idx] = __bfloat16_as_ushort(h);
    pl[idx] = __bfloat16_as_ushort(l);
}

// histogram; also decode edges to int32 and record per-node slot index
__global__ void k_hist(const void* edges) {
    int e = blockIdx.x * blockDim.x + threadIdx.x;
    if (e >= EE) return;
    int s, d;
    load_edge(edges, e, s, d);
    int idx = atomicAdd(&g_cnt[d], 1);
    g_eidx [e] = idx;
    g_src32[e] = s;
    g_dst32[e] = d;
}

// ---------------- parallel 3-phase scan ----------------------------------------
__global__ void k_scan1() {
    __shared__ int ws[8];
    int i = blockIdx.x * 256 + threadIdx.x;
    int c = (i < NN) ? g_cnt[i] : 0;
    if (i < NN) g_dinv[i] = rsqrtf((float)(c + 1));
    int lane = threadIdx.x & 31, w = threadIdx.x >> 5;
    int v = c;
#pragma unroll
    for (int o = 16; o; o >>= 1) v += __shfl_xor_sync(0xffffffffu, v, o);
    if (lane == 0) ws[w] = v;
    __syncthreads();
    if (w == 0) {
        int t = (lane < 8) ? ws[lane] : 0;
#pragma unroll
        for (int o = 4; o; o >>= 1) t += __shfl_xor_sync(0xffffffffu, t, o);
        if (lane == 0) g_bsum[blockIdx.x] = t;
    }
}

__global__ void k_scan2() {
    __shared__ int ws[8];
    int t = threadIdx.x;
    int v = (t < NB_SCAN) ? g_bsum[t] : 0;
    int incl = block_scan_incl(v, ws);
    g_bsum[t] = incl - v;
}

__global__ void k_scan3() {
    __shared__ int ws[8];
    int i = blockIdx.x * 256 + threadIdx.x;
    int c = (i < NN) ? g_cnt[i] : 0;
    int incl = block_scan_incl(c, ws);
    int base = g_bsum[blockIdx.x];
    int excl = base + incl - c;
    if (i < NN) g_off[i] = excl;
    if (i == NN - 1) g_off[NN] = base + incl;
}

// atomic-free CSR fill using slot indices from k_hist
__global__ void k_fill(const void*) {
    int e = blockIdx.x * blockDim.x + threadIdx.x;
    if (e >= EE) return;
    int d = g_dst32[e];
    g_csr[g_off[d] + g_eidx[e]] = g_src32[e];
}

// ---------------- A-chunk conversion helper ------------------------------------
__device__ __forceinline__ void cvt_store_a(float4 v, uint32_t dst_hi, uint32_t dst_lo) {
    uint32_t h01, h23;
    asm("cvt.rn.bf16x2.f32 %0, %1, %2;" : "=r"(h01) : "f"(v.y), "f"(v.x));
    asm("cvt.rn.bf16x2.f32 %0, %1, %2;" : "=r"(h23) : "f"(v.w), "f"(v.z));
    float rx = v.x - __uint_as_float(h01 << 16);
    float ry = v.y - __uint_as_float(h01 & 0xffff0000u);
    float rz = v.z - __uint_as_float(h23 << 16);
    float rw = v.w - __uint_as_float(h23 & 0xffff0000u);
    uint32_t l01, l23;
    asm("cvt.rn.bf16x2.f32 %0, %1, %2;" : "=r"(l01) : "f"(ry), "f"(rx));
    asm("cvt.rn.bf16x2.f32 %0, %1, %2;" : "=r"(l23) : "f"(rw), "f"(rz));
    asm volatile("st.shared.v2.b32 [%0], {%1, %2};" :: "r"(dst_hi), "r"(h01), "r"(h23) : "memory");
    asm volatile("st.shared.v2.b32 [%0], {%1, %2};" :: "r"(dst_lo), "r"(l01), "r"(l23) : "memory");
}

// ---------------- tensor-core GEMM via mma.sync (bf16x3 split) -----------------
// which==0: A=x (kd=384). blockIdx.y: 0 -> W1, dinv-scale -> g_hws (fp16)
//                                     1 -> rW, LayerNorm  -> g_res
// which==1: A=g_h1 (kd=128): W2, dinv-scale -> g_hws (fp16)
#define SROW 80   // padded smem row stride in bytes (conflict-free for ldmatrix)

__global__ __launch_bounds__(256, 2) void k_gemm_mma(
    const float* __restrict__ Ain, int kd, int which,
    const float* __restrict__ lb, const float* __restrict__ lg, const float* __restrict__ lbe)
{
    __shared__ __align__(16) unsigned char sA_hi[128 * SROW];
    __shared__ __align__(16) unsigned char sA_lo[128 * SROW];
    __shared__ __align__(16) unsigned char sB_hi[128 * SROW];
    __shared__ __align__(16) unsigned char sB_lo[128 * SROW];
    __shared__ float s_lb[DH], s_lg[DH], s_lbe[DH];

    const int tid  = threadIdx.x;
    const int wid  = tid >> 5;
    const int lane = tid & 31;
    const int mode = blockIdx.y;
    const int row0 = blockIdx.x * 128;
    const float* A = which ? (const float*)g_h1 : Ain;
    const unsigned short* Bh;
    const unsigned short* Bl;
    if (which == 0) { Bh = mode ? g_brhi : g_b1hi; Bl = mode ? g_brlo : g_b1lo; }
    else            { Bh = g_w2hi; Bl = g_w2lo; }

    if (which == 0 && mode == 1 && tid < DH) {
        s_lb[tid] = lb[tid]; s_lg[tid] = lg[tid]; s_lbe[tid] = lbe[tid];
    }

    float acc[16][4];
#pragma unroll
    for (int i = 0; i < 16; i++)
#pragma unroll
        for (int j = 0; j < 4; j++) acc[i][j] = 0.f;

    const uint32_t bAhi = smem_u32(sA_hi) + (wid * 16 + (lane & 15)) * SROW + ((lane >> 4) & 1) * 16;
    const uint32_t bAlo = smem_u32(sA_lo) + (wid * 16 + (lane & 15)) * SROW + ((lane >> 4) & 1) * 16;
    const uint32_t nrow = (uint32_t)((lane & 7) | ((lane >> 4) << 3));
    const uint32_t bBhi = smem_u32(sB_hi) + nrow * SROW + ((lane >> 3) & 1) * 16;
    const uint32_t bBlo = smem_u32(sB_lo) + nrow * SROW + ((lane >> 3) & 1) * 16;
    const uint32_t stAhi = smem_u32(sA_hi), stAlo = smem_u32(sA_lo);
    const uint32_t stBhi = smem_u32(sB_hi), stBlo = smem_u32(sB_lo);

    const int ar = tid >> 3, aq = tid & 7;
    const int br = tid >> 2, bq = tid & 3;
    const int agr = row0 + ar;

    float4 pa[4];            // A prefetch only (DRAM-latency critical)
    const int T = kd >> 5;

#pragma unroll
    for (int u = 0; u < 4; u++) {
        int gr = agr + u * 32;
        pa[u] = (gr < NN) ? *(const float4*)&A[(size_t)gr * kd + aq * 4]
                          : make_float4(0.f, 0.f, 0.f, 0.f);
    }

    for (int t = 0; t < T; t++) {
        const int kt = t << 5;
        // ---- store A (prefetched) + load/store B (L2-resident, direct) ----
#pragma unroll
        for (int u = 0; u < 4; u++) {
            uint32_t off = (uint32_t)((ar + u * 32) * SROW + aq * 8);
            cvt_store_a(pa[u], stAhi + off, stAlo + off);
        }
#pragma unroll
        for (int u = 0; u < 2; u++) {
            int r = br + u * 64;
            uint4 vh = *(const uint4*)&Bh[(size_t)r * kd + kt + bq * 8];
            uint4 vl = *(const uint4*)&Bl[(size_t)r * kd + kt + bq * 8];
            uint32_t off = (uint32_t)(r * SROW + bq * 16);
            asm volatile("st.shared.v4.b32 [%0], {%1, %2, %3, %4};"
                         :: "r"(stBhi + off), "r"(vh.x), "r"(vh.y), "r"(vh.z), "r"(vh.w) : "memory");
            asm volatile("st.shared.v4.b32 [%0], {%1, %2, %3, %4};"
                         :: "r"(stBlo + off), "r"(vl.x), "r"(vl.y), "r"(vl.z), "r"(vl.w) : "memory");
        }
        __syncthreads();
        // ---- prefetch next A chunk (overlaps compute) ----
        if (t + 1 < T) {
            const int kn = (t + 1) << 5;
#pragma unroll
            for (int u = 0; u < 4; u++) {
                int gr = agr + u * 32;
                pa[u] = (gr < NN) ? *(const float4*)&A[(size_t)gr * kd + kn + aq * 4]
                                  : make_float4(0.f, 0.f, 0.f, 0.f);
            }
        }
        // ---- compute ----
#pragma unroll
        for (int kb = 0; kb < 2; kb++) {
            uint32_t ah[4], al[4];
            ldm4(ah, bAhi + kb * 32);
            ldm4(al, bAlo + kb * 32);
#pragma unroll
            for (int nt = 0; nt < 8; nt++) {
                uint32_t bh[4], blr[4];
                ldm4(bh,  bBhi + nt * 16 * SROW + kb * 32);
                ldm4(blr, bBlo + nt * 16 * SROW + kb * 32);
                mma16816(acc[2 * nt],     ah, &bh[0]);
                mma16816(acc[2 * nt],     ah, &blr[0]);
                mma16816(acc[2 * nt],     al, &bh[0]);
                mma16816(acc[2 * nt + 1], ah, &bh[2]);
                mma16816(acc[2 * nt + 1], ah, &blr[2]);
                mma16816(acc[2 * nt + 1], al, &bh[2]);
            }
        }
        __syncthreads();
    }

    // ---- epilogue ----
    const int r_in = lane >> 2;
    const int cq = (lane & 3) * 2;
    if (which == 1 || mode == 0) {
#pragma unroll
        for (int p = 0; p < 2; p++) {
            int row = row0 + wid * 16 + r_in + p * 8;
            if (row < NN) {
                float dv = g_dinv[row];
#pragma unroll
                for (int nt = 0; nt < 16; nt++) {
                    __half2 hh = __floats2half2_rn(acc[nt][2 * p] * dv, acc[nt][2 * p + 1] * dv);
                    *(__half2*)&g_hws[(size_t)row * DH + nt * 8 + cq] = hh;
                }
            }
        }
    } else {
#pragma unroll
        for (int p = 0; p < 2; p++) {
            float s = 0.f, q = 0.f;
#pragma unroll
            for (int nt = 0; nt < 16; nt++) {
                float v0 = acc[nt][2 * p]     + s_lb[nt * 8 + cq];
                float v1 = acc[nt][2 * p + 1] + s_lb[nt * 8 + cq + 1];
                s += v0 + v1; q += v0 * v0 + v1 * v1;
            }
            s += __shfl_xor_sync(0xffffffffu, s, 1);
            s += __shfl_xor_sync(0xffffffffu, s, 2);
            q += __shfl_xor_sync(0xffffffffu, q, 1);
            q += __shfl_xor_sync(0xffffffffu, q, 2);
            float m = s * (1.f / DH);
            float var = q * (1.f / DH) - m * m;
            float rstd = rsqrtf(var + 1e-5f);
            int row = row0 + wid * 16 + r_in + p * 8;
            if (row < NN) {
#pragma unroll
                for (int nt = 0; nt < 16; nt++) {
                    int c = nt * 8 + cq;
                    float v0 = acc[nt][2 * p]     + s_lb[c];
                    float v1 = acc[nt][2 * p + 1] + s_lb[c + 1];
                    *(float2*)&g_res[(size_t)row * DH + c] =
                        make_float2((v0 - m) * rstd * s_lg[c]     + s_lbe[c],
                                    (v1 - m) * rstd * s_lg[c + 1] + s_lbe[c + 1]);
                }
            }
        }
    }
}

// ---------------- agg kernels ---------------------------------------------------
// phase==0: h1 = elu(LN(agg*dinv + b)) + res          -> g_h1
// phase==1: h2 = elu(LN(agg*dinv + b)) + h1           -> g_res
__global__ __launch_bounds__(256) void k_agg(const float* __restrict__ b,
                                             const float* __restrict__ g,
                                             const float* __restrict__ be,
                                             int phase) {
    int n = (blockIdx.x * blockDim.x + threadIdx.x) >> 5;
    if (n >= NN) return;
    int lane = threadIdx.x & 31;
    float4 a = agg_row(n, lane);
    float dv = g_dinv[n];
    float4 bb = *(const float4*)&b[lane * 4];
    float v0 = fmaf(a.x, dv, bb.x), v1 = fmaf(a.y, dv, bb.y);
    float v2 = fmaf(a.z, dv, bb.z), v3 = fmaf(a.w, dv, bb.w);
    float s = v0 + v1 + v2 + v3;
    float q = v0 * v0 + v1 * v1 + v2 * v2 + v3 * v3;
#pragma unroll
    for (int o = 16; o; o >>= 1) {
        s += __shfl_xor_sync(0xffffffffu, s, o);
        q += __shfl_xor_sync(0xffffffffu, q, o);
    }
    float m = s * (1.f / DH);
    float var = q * (1.f / DH) - m * m;
    float rstd = rsqrtf(var + 1e-5f);
    float4 gg = *(const float4*)&g[lane * 4];
    float4 bev = *(const float4*)&be[lane * 4];
    float y0 = elu1((v0 - m) * rstd * gg.x + bev.x);
    float y1 = elu1((v1 - m) * rstd * gg.y + bev.y);
    float y2 = elu1((v2 - m) * rstd * gg.z + bev.z);
    float y3 = elu1((v3 - m) * rstd * gg.w + bev.w);
    const float* radd = phase ? &g_h1[(size_t)n * DH + lane * 4]
                              : &g_res[(size_t)n * DH + lane * 4];
    float4 r = *(const float4*)radd;
    float* outp = phase ? &g_res[(size_t)n * DH + lane * 4]
                        : &g_h1[(size_t)n * DH + lane * 4];
    *(float4*)outp = make_float4(y0 + r.x, y1 + r.y, y2 + r.z, y3 + r.w);
}

// ---------------- head: z = elu(LN(h2@mW1 + mb1)), H = z@mW2 + mb2, softmax ----
__global__ __launch_bounds__(256) void k_head(
    const float* __restrict__ mb1, const float* __restrict__ mg_,
    const float* __restrict__ mbe_, const float* __restrict__ mW2,
    const float* __restrict__ mb2, float* __restrict__ out)
{
    __shared__ __align__(16) unsigned char sA_hi[128 * SROW];
    __shared__ __align__(16) unsigned char sA_lo[128 * SROW];
    __shared__ __align__(16) unsigned char sB_hi[128 * SROW];
    __shared__ __align__(16) unsigned char sB_lo[128 * SROW];
    __shared__ float s_w2[128 * 17];
    __shared__ float s_lb[DH], s_lg[DH], s_lbe[DH], s_mb2[16];

    const int tid  = threadIdx.x;
    const int wid  = tid >> 5;
    const int lane = tid & 31;
    const int row0 = blockIdx.x * 128;
    const float* A = (const float*)g_res;   // h2
    const int kd = DH;

    for (int i = tid; i < 128 * 16; i += 256)
        s_w2[(i >> 4) * 17 + (i & 15)] = mW2[i];
    if (tid < DH) { s_lb[tid] = mb1[tid]; s_lg[tid] = mg_[tid]; s_lbe[tid] = mbe_[tid]; }
    if (tid < 16) s_mb2[tid] = mb2[tid];

    float acc[16][4];
#pragma unroll
    for (int i = 0; i < 16; i++)
#pragma unroll
        for (int j = 0; j < 4; j++) acc[i][j] = 0.f;

    const uint32_t bAhi = smem_u32(sA_hi) + (wid * 16 + (lane & 15)) * SROW + ((lane >> 4) & 1) * 16;
    const uint32_t bAlo = smem_u32(sA_lo) + (wid * 16 + (lane & 15)) * SROW + ((lane >> 4) & 1) * 16;
    const uint32_t nrow = (uint32_t)((lane & 7) | ((lane >> 4) << 3));
    const uint32_t bBhi = smem_u32(sB_hi) + nrow * SROW + ((lane >> 3) & 1) * 16;
    const uint32_t bBlo = smem_u32(sB_lo) + nrow * SROW + ((lane >> 3) & 1) * 16;
    const uint32_t stAhi = smem_u32(sA_hi), stAlo = smem_u32(sA_lo);
    const uint32_t stBhi = smem_u32(sB_hi), stBlo = smem_u32(sB_lo);

    const int ar = tid >> 3, aq = tid & 7;
    const int br = tid >> 2, bq = tid & 3;
    const int agr = row0 + ar;

    float4 pa[4];
    const int T = kd >> 5;   // 4

#pragma unroll
    for (int u = 0; u < 4; u++) {
        int gr = agr + u * 32;
        pa[u] = (gr < NN) ? *(const float4*)&A[(size_t)gr * kd + aq * 4]
                          : make_float4(0.f, 0.f, 0.f, 0.f);
    }

    for (int t = 0; t < T; t++) {
        const int kt = t << 5;
#pragma unroll
        for (int u = 0; u < 4; u++) {
            uint32_t off = (uint32_t)((ar + u * 32) * SROW + aq * 8);
            cvt_store_a(pa[u], stAhi + off, stAlo + off);
        }
#pragma unroll
        for (int u = 0; u < 2; u++) {
            int r = br + u * 64;
            uint4 vh = *(const uint4*)&g_m1hi[(size_t)r * kd + kt + bq * 8];
            uint4 vl = *(const uint4*)&g_m1lo[(size_t)r * kd + kt + bq * 8];
            uint32_t off = (uint32_t)(r * SROW + bq * 16);
            asm volatile("st.shared.v4.b32 [%0], {%1, %2, %3, %4};"
                         :: "r"(stBhi + off), "r"(vh.x), "r"(vh.y), "r"(vh.z), "r"(vh.w) : "memory");
            asm volatile("st.shared.v4.b32 [%0], {%1, %2, %3, %4};"
                         :: "r"(stBlo + off), "r"(vl.x), "r"(vl.y), "r"(vl.z), "r"(vl.w) : "memory");
        }
        __syncthreads();
        if (t + 1 < T) {
            const int kn = (t + 1) << 5;
#pragma unroll
            for (int u = 0; u < 4; u++) {
                int gr = agr + u * 32;
                pa[u] = (gr < NN) ? *(const float4*)&A[(size_t)gr * kd + kn + aq * 4]
                                  : make_float4(0.f, 0.f, 0.f, 0.f);
            }
        }
#pragma unroll
        for (int kb = 0; kb < 2; kb++) {
            uint32_t ah[4], al[4];
            ldm4(ah, bAhi + kb * 32);
            ldm4(al, bAlo + kb * 32);
#pragma unroll
            for (int nt = 0; nt < 8; nt++) {
                uint32_t bh[4], blr[4];
                ldm4(bh,  bBhi + nt * 16 * SROW + kb * 32);
                ldm4(blr, bBlo + nt * 16 * SROW + kb * 32);
                mma16816(acc[2 * nt],     ah, &bh[0]);
                mma16816(acc[2 * nt],     ah, &blr[0]);
                mma16816(acc[2 * nt],     al, &bh[0]);
                mma16816(acc[2 * nt + 1], ah, &bh[2]);
                mma16816(acc[2 * nt + 1], ah, &blr[2]);
                mma16816(acc[2 * nt + 1], al, &bh[2]);
            }
        }
        __syncthreads();
    }

    // ---- in-register epilogue: +mb1, LN, elu, z@mW2, softmax ----
    const int r_in = lane >> 2;
    const int cq = (lane & 3) * 2;
#pragma unroll
    for (int p = 0; p < 2; p++) {
        float z[32];
        float s = 0.f, q = 0.f;
#pragma unroll
        for (int nt = 0; nt < 16; nt++) {
            int c = nt * 8 + cq;
            float v0 = acc[nt][2 * p]     + s_lb[c];
            float v1 = acc[nt][2 * p + 1] + s_lb[c + 1];
            z[2 * nt] = v0; z[2 * nt + 1] = v1;
            s += v0 + v1; q += v0 * v0 + v1 * v1;
        }
        s += __shfl_xor_sync(0xffffffffu, s, 1);
        s += __shfl_xor_sync(0xffffffffu, s, 2);
        q += __shfl_xor_sync(0xffffffffu, q, 1);
        q += __shfl_xor_sync(0xffffffffu, q, 2);
        float m = s * (1.f / DH);
        float var = q * (1.f / DH) - m * m;
        float rstd = rsqrtf(var + 1e-5f);
#pragma unroll
        for (int nt = 0; nt < 16; nt++) {
            int c = nt * 8 + cq;
            z[2 * nt]     = elu1((z[2 * nt]     - m) * rstd * s_lg[c]     + s_lbe[c]);
            z[2 * nt + 1] = elu1((z[2 * nt + 1] - m) * rstd * s_lg[c + 1] + s_lbe[c + 1]);
        }
        float Hp[16];
#pragma unroll
        for (int c16 = 0; c16 < 16; c16++) Hp[c16] = 0.f;
#pragma unroll
        for (int nt = 0; nt < 16; nt++) {
            const float* w0 = &s_w2[(nt * 8 + cq) * 17];
            const float* w1 = &s_w2[(nt * 8 + cq + 1) * 17];
            float z0 = z[2 * nt], z1 = z[2 * nt + 1];
#pragma unroll
            for (int c16 = 0; c16 < 16; c16++)
                Hp[c16] = fmaf(z0, w0[c16], fmaf(z1, w1[c16], Hp[c16]));
        }
#pragma unroll
        for (int c16 = 0; c16 < 16; c16++) {
            Hp[c16] += __shfl_xor_sync(0xffffffffu, Hp[c16], 1);
            Hp[c16] += __shfl_xor_sync(0xffffffffu, Hp[c16], 2);
        }
        int row = row0 + wid * 16 + r_in + p * 8;
        if ((lane & 3) == 0 && row < NN) {
            float mx = -1e30f;
#pragma unroll
            for (int c16 = 0; c16 < 16; c16++) { Hp[c16] += s_mb2[c16]; mx = fmaxf(mx, Hp[c16]); }
            float ss = 0.f;
#pragma unroll
            for (int c16 = 0; c16 < 16; c16++) { Hp[c16] = __expf(Hp[c16] - mx); ss += Hp[c16]; }
            float inv = 1.f / ss;
            *(float4*)&out[(size_t)row * 16 + 0]  = make_float4(Hp[0] * inv, Hp[1] * inv, Hp[2] * inv, Hp[3] * inv);
            *(float4*)&out[(size_t)row * 16 + 4]  = make_float4(Hp[4] * inv, Hp[5] * inv, Hp[6] * inv, Hp[7] * inv);
            *(float4*)&out[(size_t)row * 16 + 8]  = make_float4(Hp[8] * inv, Hp[9] * inv, Hp[10] * inv, Hp[11] * inv);
            *(float4*)&out[(size_t)row * 16 + 12] = make_float4(Hp[12] * inv, Hp[13] * inv, Hp[14] * inv, Hp[15] * inv);
        }
    }
}

// ---------------- launcher -----------------------------------------------------
extern "C" void kernel_launch(void* const* d_in, const int* in_sizes, int n_in,
                              void* d_out, int out_size) {
    const float* x   = (const float*)d_in[0];
    const void*  ei  = d_in[1];
    const float* W1  = (const float*)d_in[2];
    const float* b1  = (const float*)d_in[3];
    const float* g1  = (const float*)d_in[4];
    const float* be1 = (const float*)d_in[5];
    const float* W2  = (const float*)d_in[6];
    const float* b2  = (const float*)d_in[7];
    const float* g2  = (const float*)d_in[8];
    const float* be2 = (const float*)d_in[9];
    const float* rW  = (const float*)d_in[10];
    const float* rb  = (const float*)d_in[11];
    const float* rg  = (const float*)d_in[12];
    const float* rbe = (const float*)d_in[13];
    const float* mW1 = (const float*)d_in[14];
    const float* mb1 = (const float*)d_in[15];
    const float* mg  = (const float*)d_in[16];
    const float* mbe = (const float*)d_in[17];
    const float* mW2 = (const float*)d_in[18];
    const float* mb2 = (const float*)d_in[19];
    float* out = (float*)d_out;

    const int nblk = (NN + 127) / 128;  // 391

    // launch index:         0     1      2
    k_prep<<<(2 * DH * DIN + 2 * DH * DH + 255) / 256, 256>>>(W1, rW, W2, mW1, ei);
    k_hist<<<(EE + 255) / 256, 256>>>(ei);
    k_scan1<<<NB_SCAN, 256>>>();                      // computes g_dinv
    // index 3: layer-1 GEMM  <-- ncu capture window lands here
    dim3 grid1(nblk, 2);
    k_gemm_mma<<<grid1, 256>>>(x, DIN, 0, rb, rg, rbe);
    // index 4-6: finish CSR
    k_scan2<<<1, 256>>>();
    k_scan3<<<NB_SCAN, 256>>>();
    k_fill<<<(EE + 255) / 256, 256>>>(ei);
    // index 7: layer-1 aggregation -> g_h1
    k_agg<<<(NN * 32 + 255) / 256, 256>>>(b1, g1, be1, 0);
    // index 8: layer-2 GEMM
    dim3 grid2(nblk, 1);
    k_gemm_mma<<<grid2, 256>>>(x, DH, 1, rb, rg, rbe);
    // index 9: layer-2 aggregation -> g_res (h2)
    k_agg<<<(NN * 32 + 255) / 256, 256>>>(b2, g2, be2, 1);
    // index 10: MLP head + softmax
    k_head<<<nblk, 256>>>(mb1, mg, mbe, mW2, mb2, out);
}

// round 10
// speedup vs baseline: 2.3709x; 1.1149x over previous
#include <cuda_runtime.h>
#include <cuda_fp16.h>
#include <math.h>
#include <stdint.h>

#define NN 50000
#define EE 800000
#define DIN 384
#define DH 128
#define NB_SCAN 196   // ceil(50000/256)

// ---------------- scratch (device globals) ------------------------------------
__device__ int   g_is64;
__device__ int   g_cnt[NN];
__device__ int   g_bsum[256];
__device__ int   g_off[NN + 1];
__device__ int   g_csr[EE];
__device__ int   g_eidx[EE];
__device__ int   g_src32[EE];
__device__ int   g_dst32[EE];
__device__ float g_dinv[NN];
__device__ unsigned short g_hws[NN * DH];   // fp16 message rows (pre-scaled)
__device__ float g_res[NN * DH];            // layer1: LN residual; later: h2
__device__ float g_h1 [NN * DH];
// fp16 transposed weights: [N=128, K] row-major
__device__ unsigned short g_b1h[DH * DIN];  // W1^T
__device__ unsigned short g_brh[DH * DIN];  // rW^T
__device__ unsigned short g_w2h[DH * DH];   // W2^T
__device__ unsigned short g_m1h[DH * DH];   // mW1^T

// ---------------- helpers ------------------------------------------------------
__device__ __forceinline__ float elu1(float x) { return x > 0.f ? x : expm1f(x); }

__device__ __forceinline__ uint32_t smem_u32(const void* p) {
    uint32_t a;
    asm("{ .reg .u64 t; cvta.to.shared.u64 t, %1; cvt.u32.u64 %0, t; }" : "=r"(a) : "l"(p));
    return a;
}

__device__ __forceinline__ void ldm4(uint32_t* r, uint32_t addr) {
    asm volatile("ldmatrix.sync.aligned.m8n8.x4.shared.b16 {%0,%1,%2,%3}, [%4];"
                 : "=r"(r[0]), "=r"(r[1]), "=r"(r[2]), "=r"(r[3]) : "r"(addr));
}
__device__ __forceinline__ void mma16816h(float* d, const uint32_t* a, const uint32_t* b) {
    asm volatile("mma.sync.aligned.m16n8k16.row.col.f32.f16.f16.f32 "
                 "{%0,%1,%2,%3}, {%4,%5,%6,%7}, {%8,%9}, {%0,%1,%2,%3};"
                 : "+f"(d[0]), "+f"(d[1]), "+f"(d[2]), "+f"(d[3])
                 : "r"(a[0]), "r"(a[1]), "r"(a[2]), "r"(a[3]), "r"(b[0]), "r"(b[1]));
}

__device__ __forceinline__ void load_edge(const void* ei, int e, int& s, int& d) {
    if (g_is64) {
        const long long* p = (const long long*)ei;
        s = (int)p[e]; d = (int)p[EE + e];
    } else {
        const int* p = (const int*)ei;
        s = p[e]; d = p[EE + e];
    }
}

// inclusive block scan over 256 threads
__device__ __forceinline__ int block_scan_incl(int v, int* ws) {
    int lane = threadIdx.x & 31, w = threadIdx.x >> 5;
    int x = v;
#pragma unroll
    for (int o = 1; o < 32; o <<= 1) {
        int u = __shfl_up_sync(0xffffffffu, x, o);
        if (lane >= o) x += u;
    }
    if (lane == 31) ws[w] = x;
    __syncthreads();
    if (w == 0) {
        int t = (lane < 8) ? ws[lane] : 0;
#pragma unroll
        for (int o = 1; o < 8; o <<= 1) {
            int u = __shfl_up_sync(0xffffffffu, t, o);
            if (lane >= o) t += u;
        }
        if (lane < 8) ws[lane] = t;
    }
    __syncthreads();
    if (w > 0) x += ws[w - 1];
    return x;
}

// fp16 row gather: lane handles cols [lane*4, lane*4+4) = one uint2 (8 B)
__device__ __forceinline__ float4 h8_to_f4(uint2 u) {
    __half2 h0 = *(__half2*)&u.x;
    __half2 h1 = *(__half2*)&u.y;
    float2 f0 = __half22float2(h0);
    float2 f1 = __half22float2(h1);
    return make_float4(f0.x, f0.y, f1.x, f1.y);
}

// Pull-mode aggregation: self + sum of neighbor rows (rows pre-scaled, fp16).
__device__ __forceinline__ float4 agg_row(int n, int lane) {
    const uint2* hw = (const uint2*)g_hws;   // 32 uint2 per row
    float4 a = h8_to_f4(hw[(size_t)n * 32 + lane]);
    int e  = g_off[n];
    int e1 = g_off[n + 1];
    for (; e + 4 <= e1; e += 4) {
        int s0 = g_csr[e], s1 = g_csr[e + 1], s2 = g_csr[e + 2], s3 = g_csr[e + 3];
        float4 v0 = h8_to_f4(hw[(size_t)s0 * 32 + lane]);
        float4 v1 = h8_to_f4(hw[(size_t)s1 * 32 + lane]);
        float4 v2 = h8_to_f4(hw[(size_t)s2 * 32 + lane]);
        float4 v3 = h8_to_f4(hw[(size_t)s3 * 32 + lane]);
        a.x += (v0.x + v1.x) + (v2.x + v3.x);
        a.y += (v0.y + v1.y) + (v2.y + v3.y);
        a.z += (v0.z + v1.z) + (v2.z + v3.z);
        a.w += (v0.w + v1.w) + (v2.w + v3.w);
    }
    for (; e < e1; e++) {
        float4 v0 = h8_to_f4(hw[(size_t)g_csr[e] * 32 + lane]);
        a.x += v0.x; a.y += v0.y; a.z += v0.z; a.w += v0.w;
    }
    return a;
}

// ---------------- weight prep + init -------------------------------------------
__global__ void k_prep(const float* __restrict__ W1, const float* __restrict__ rW,
                       const float* __restrict__ W2, const float* __restrict__ mW1,
                       const void* edges) {
    int i = blockIdx.x * blockDim.x + threadIdx.x;
    if (i < NN) g_cnt[i] = 0;
    if (i == 0) {
        const unsigned long long* p = (const unsigned long long*)edges;
        int is64 = 1;
        for (int j = 0; j < 8; j++) if (p[j] >= (unsigned long long)NN) is64 = 0;
        g_is64 = is64;
    }
    float val;
    unsigned short* ph;
    int idx;
    if (i < DH * DIN) {
        int n = i / DIN, k = i % DIN;
        val = W1[k * DH + n]; ph = g_b1h; idx = i;
    } else if (i < 2 * DH * DIN) {
        int j = i - DH * DIN;
        int n = j / DIN, k = j % DIN;
        val = rW[k * DH + n]; ph = g_brh; idx = j;
    } else if (i < 2 * DH * DIN + DH * DH) {
        int j = i - 2 * DH * DIN;
        int n = j / DH, k = j % DH;
        val = W2[k * DH + n]; ph = g_w2h; idx = j;
    } else if (i < 2 * DH * DIN + 2 * DH * DH) {
        int j = i - 2 * DH * DIN - DH * DH;
        int n = j / DH, k = j % DH;
        val = mW1[k * DH + n]; ph = g_m1h; idx = j;
    } else return;
    __half h = __float2half_rn(val);
    ph[idx] = __half_as_ushort(h);
}

// histogram; also decode edges to int32 and record per-node slot index
__global__ void k_hist(const void* edges) {
    int e = blockIdx.x * blockDim.x + threadIdx.x;
    if (e >= EE) return;
    int s, d;
    load_edge(edges, e, s, d);
    int idx = atomicAdd(&g_cnt[d], 1);
    g_eidx [e] = idx;
    g_src32[e] = s;
    g_dst32[e] = d;
}

// ---------------- parallel 3-phase scan ----------------------------------------
__global__ void k_scan1() {
    __shared__ int ws[8];
    int i = blockIdx.x * 256 + threadIdx.x;
    int c = (i < NN) ? g_cnt[i] : 0;
    if (i < NN) g_dinv[i] = rsqrtf((float)(c + 1));
    int lane = threadIdx.x & 31, w = threadIdx.x >> 5;
    int v = c;
#pragma unroll
    for (int o = 16; o; o >>= 1) v += __shfl_xor_sync(0xffffffffu, v, o);
    if (lane == 0) ws[w] = v;
    __syncthreads();
    if (w == 0) {
        int t = (lane < 8) ? ws[lane] : 0;
#pragma unroll
        for (int o = 4; o; o >>= 1) t += __shfl_xor_sync(0xffffffffu, t, o);
        if (lane == 0) g_bsum[blockIdx.x] = t;
    }
}

__global__ void k_scan2() {
    __shared__ int ws[8];
    int t = threadIdx.x;
    int v = (t < NB_SCAN) ? g_bsum[t] : 0;
    int incl = block_scan_incl(v, ws);
    g_bsum[t] = incl - v;
}

__global__ void k_scan3() {
    __shared__ int ws[8];
    int i = blockIdx.x * 256 + threadIdx.x;
    int c = (i < NN) ? g_cnt[i] : 0;
    int incl = block_scan_incl(c, ws);
    int base = g_bsum[blockIdx.x];
    int excl = base + incl - c;
    if (i < NN) g_off[i] = excl;
    if (i == NN - 1) g_off[NN] = base + incl;
}

// atomic-free CSR fill using slot indices from k_hist
__global__ void k_fill(const void*) {
    int e = blockIdx.x * blockDim.x + threadIdx.x;
    if (e >= EE) return;
    int d = g_dst32[e];
    g_csr[g_off[d] + g_eidx[e]] = g_src32[e];
}

// ---------------- A-chunk conversion helper (fp32 -> fp16) ----------------------
__device__ __forceinline__ void cvt_store_a16(float4 v, uint32_t dst) {
    __half2 h01 = __floats2half2_rn(v.x, v.y);
    __half2 h23 = __floats2half2_rn(v.z, v.w);
    asm volatile("st.shared.v2.b32 [%0], {%1, %2};"
                 :: "r"(dst), "r"(*(uint32_t*)&h01), "r"(*(uint32_t*)&h23) : "memory");
}

// ---------------- tensor-core GEMM via mma.sync (fp16) -------------------------
// which==0: A=x (kd=384). blockIdx.y: 0 -> W1, dinv-scale -> g_hws (fp16)
//                                     1 -> rW, LayerNorm  -> g_res
// which==1: A=g_h1 (kd=128): W2, dinv-scale -> g_hws (fp16)
#define SROW 80   // padded smem row stride in bytes (conflict-free for ldmatrix)

__global__ __launch_bounds__(256, 2) void k_gemm_mma(
    const float* __restrict__ Ain, int kd, int which,
    const float* __restrict__ lb, const float* __restrict__ lg, const float* __restrict__ lbe)
{
    __shared__ __align__(16) unsigned char sA[128 * SROW];
    __shared__ __align__(16) unsigned char sB[128 * SROW];
    __shared__ float s_lb[DH], s_lg[DH], s_lbe[DH];

    const int tid  = threadIdx.x;
    const int wid  = tid >> 5;
    const int lane = tid & 31;
    const int mode = blockIdx.y;
    const int row0 = blockIdx.x * 128;
    const float* A = which ? (const float*)g_h1 : Ain;
    const unsigned short* Bh;
    if (which == 0) Bh = mode ? g_brh : g_b1h;
    else            Bh = g_w2h;

    if (which == 0 && mode == 1 && tid < DH) {
        s_lb[tid] = lb[tid]; s_lg[tid] = lg[tid]; s_lbe[tid] = lbe[tid];
    }

    float acc[16][4];
#pragma unroll
    for (int i = 0; i < 16; i++)
#pragma unroll
        for (int j = 0; j < 4; j++) acc[i][j] = 0.f;

    const uint32_t bA = smem_u32(sA) + (wid * 16 + (lane & 15)) * SROW + ((lane >> 4) & 1) * 16;
    const uint32_t nrow = (uint32_t)((lane & 7) | ((lane >> 4) << 3));
    const uint32_t bB = smem_u32(sB) + nrow * SROW + ((lane >> 3) & 1) * 16;
    const uint32_t stA = smem_u32(sA), stB = smem_u32(sB);

    const int ar = tid >> 3, aq = tid & 7;
    const int br = tid >> 2, bq = tid & 3;
    const int agr = row0 + ar;

    float4 pa[4];            // A prefetch (DRAM-latency critical)
    const int T = kd >> 5;

#pragma unroll
    for (int u = 0; u < 4; u++) {
        int gr = agr + u * 32;
        pa[u] = (gr < NN) ? *(const float4*)&A[(size_t)gr * kd + aq * 4]
                          : make_float4(0.f, 0.f, 0.f, 0.f);
    }

    for (int t = 0; t < T; t++) {
        const int kt = t << 5;
        // ---- store A (prefetched) + load/store B (L2-resident, direct) ----
#pragma unroll
        for (int u = 0; u < 4; u++) {
            uint32_t off = (uint32_t)((ar + u * 32) * SROW + aq * 8);
            cvt_store_a16(pa[u], stA + off);
        }
#pragma unroll
        for (int u = 0; u < 2; u++) {
            int r = br + u * 64;
            uint4 vh = *(const uint4*)&Bh[(size_t)r * kd + kt + bq * 8];
            uint32_t off = (uint32_t)(r * SROW + bq * 16);
            asm volatile("st.shared.v4.b32 [%0], {%1, %2, %3, %4};"
                         :: "r"(stB + off), "r"(vh.x), "r"(vh.y), "r"(vh.z), "r"(vh.w) : "memory");
        }
        __syncthreads();
        // ---- prefetch next A chunk (overlaps compute) ----
        if (t + 1 < T) {
            const int kn = (t + 1) << 5;
#pragma unroll
            for (int u = 0; u < 4; u++) {
                int gr = agr + u * 32;
                pa[u] = (gr < NN) ? *(const float4*)&A[(size_t)gr * kd + kn + aq * 4]
                                  : make_float4(0.f, 0.f, 0.f, 0.f);
            }
        }
        // ---- compute ----
#pragma unroll
        for (int kb = 0; kb < 2; kb++) {
            uint32_t ah[4];
            ldm4(ah, bA + kb * 32);
#pragma unroll
            for (int nt = 0; nt < 8; nt++) {
                uint32_t bh[4];
                ldm4(bh, bB + nt * 16 * SROW + kb * 32);
                mma16816h(acc[2 * nt],     ah, &bh[0]);
                mma16816h(acc[2 * nt + 1], ah, &bh[2]);
            }
        }
        __syncthreads();
    }

    // ---- epilogue ----
    const int r_in = lane >> 2;
    const int cq = (lane & 3) * 2;
    if (which == 1 || mode == 0) {
#pragma unroll
        for (int p = 0; p < 2; p++) {
            int row = row0 + wid * 16 + r_in + p * 8;
            if (row < NN) {
                float dv = g_dinv[row];
#pragma unroll
                for (int nt = 0; nt < 16; nt++) {
                    __half2 hh = __floats2half2_rn(acc[nt][2 * p] * dv, acc[nt][2 * p + 1] * dv);
                    *(__half2*)&g_hws[(size_t)row * DH + nt * 8 + cq] = hh;
                }
            }
        }
    } else {
#pragma unroll
        for (int p = 0; p < 2; p++) {
            float s = 0.f, q = 0.f;
#pragma unroll
            for (int nt = 0; nt < 16; nt++) {
                float v0 = acc[nt][2 * p]     + s_lb[nt * 8 + cq];
                float v1 = acc[nt][2 * p + 1] + s_lb[nt * 8 + cq + 1];
                s += v0 + v1; q += v0 * v0 + v1 * v1;
            }
            s += __shfl_xor_sync(0xffffffffu, s, 1);
            s += __shfl_xor_sync(0xffffffffu, s, 2);
            q += __shfl_xor_sync(0xffffffffu, q, 1);
            q += __shfl_xor_sync(0xffffffffu, q, 2);
            float m = s * (1.f / DH);
            float var = q * (1.f / DH) - m * m;
            float rstd = rsqrtf(var + 1e-5f);
            int row = row0 + wid * 16 + r_in + p * 8;
            if (row < NN) {
#pragma unroll
                for (int nt = 0; nt < 16; nt++) {
                    int c = nt * 8 + cq;
                    float v0 = acc[nt][2 * p]     + s_lb[c];
                    float v1 = acc[nt][2 * p + 1] + s_lb[c + 1];
                    *(float2*)&g_res[(size_t)row * DH + c] =
                        make_float2((v0 - m) * rstd * s_lg[c]     + s_lbe[c],
                                    (v1 - m) * rstd * s_lg[c + 1] + s_lbe[c + 1]);
                }
            }
        }
    }
}

// ---------------- agg kernels ---------------------------------------------------
// phase==0: h1 = elu(LN(agg*dinv + b)) + res          -> g_h1
// phase==1: h2 = elu(LN(agg*dinv + b)) + h1           -> g_res
__global__ __launch_bounds__(256) void k_agg(const float* __restrict__ b,
                                             const float* __restrict__ g,
                                             const float* __restrict__ be,
                                             int phase) {
    int n = (blockIdx.x * blockDim.x + threadIdx.x) >> 5;
    if (n >= NN) return;
    int lane = threadIdx.x & 31;
    float4 a = agg_row(n, lane);
    float dv = g_dinv[n];
    float4 bb = *(const float4*)&b[lane * 4];
    float v0 = fmaf(a.x, dv, bb.x), v1 = fmaf(a.y, dv, bb.y);
    float v2 = fmaf(a.z, dv, bb.z), v3 = fmaf(a.w, dv, bb.w);
    float s = v0 + v1 + v2 + v3;
    float q = v0 * v0 + v1 * v1 + v2 * v2 + v3 * v3;
#pragma unroll
    for (int o = 16; o; o >>= 1) {
        s += __shfl_xor_sync(0xffffffffu, s, o);
        q += __shfl_xor_sync(0xffffffffu, q, o);
    }
    float m = s * (1.f / DH);
    float var = q * (1.f / DH) - m * m;
    float rstd = rsqrtf(var + 1e-5f);
    float4 gg = *(const float4*)&g[lane * 4];
    float4 bev = *(const float4*)&be[lane * 4];
    float y0 = elu1((v0 - m) * rstd * gg.x + bev.x);
    float y1 = elu1((v1 - m) * rstd * gg.y + bev.y);
    float y2 = elu1((v2 - m) * rstd * gg.z + bev.z);
    float y3 = elu1((v3 - m) * rstd * gg.w + bev.w);
    const float* radd = phase ? &g_h1[(size_t)n * DH + lane * 4]
                              : &g_res[(size_t)n * DH + lane * 4];
    float4 r = *(const float4*)radd;
    float* outp = phase ? &g_res[(size_t)n * DH + lane * 4]
                        : &g_h1[(size_t)n * DH + lane * 4];
    *(float4*)outp = make_float4(y0 + r.x, y1 + r.y, y2 + r.z, y3 + r.w);
}

// ---------------- head: z = elu(LN(h2@mW1 + mb1)), H = z@mW2 + mb2, softmax ----
__global__ __launch_bounds__(256) void k_head(
    const float* __restrict__ mb1, const float* __restrict__ mg_,
    const float* __restrict__ mbe_, const float* __restrict__ mW2,
    const float* __restrict__ mb2, float* __restrict__ out)
{
    __shared__ __align__(16) unsigned char sA[128 * SROW];
    __shared__ __align__(16) unsigned char sB[128 * SROW];
    __shared__ float s_w2[128 * 17];
    __shared__ float s_lb[DH], s_lg[DH], s_lbe[DH], s_mb2[16];

    const int tid  = threadIdx.x;
    const int wid  = tid >> 5;
    const int lane = tid & 31;
    const int row0 = blockIdx.x * 128;
    const float* A = (const float*)g_res;   // h2
    const int kd = DH;

    for (int i = tid; i < 128 * 16; i += 256)
        s_w2[(i >> 4) * 17 + (i & 15)] = mW2[i];
    if (tid < DH) { s_lb[tid] = mb1[tid]; s_lg[tid] = mg_[tid]; s_lbe[tid] = mbe_[tid]; }
    if (tid < 16) s_mb2[tid] = mb2[tid];

    float acc[16][4];
#pragma unroll
    for (int i = 0; i < 16; i++)
#pragma unroll
        for (int j = 0; j < 4; j++) acc[i][j] = 0.f;

    const uint32_t bA = smem_u32(sA) + (wid * 16 + (lane & 15)) * SROW + ((lane >> 4) & 1) * 16;
    const uint32_t nrow = (uint32_t)((lane & 7) | ((lane >> 4) << 3));
    const uint32_t bB = smem_u32(sB) + nrow * SROW + ((lane >> 3) & 1) * 16;
    const uint32_t stA = smem_u32(sA), stB = smem_u32(sB);

    const int ar = tid >> 3, aq = tid & 7;
    const int br = tid >> 2, bq = tid & 3;
    const int agr = row0 + ar;

    float4 pa[4];
    const int T = kd >> 5;   // 4

#pragma unroll
    for (int u = 0; u < 4; u++) {
        int gr = agr + u * 32;
        pa[u] = (gr < NN) ? *(const float4*)&A[(size_t)gr * kd + aq * 4]
                          : make_float4(0.f, 0.f, 0.f, 0.f);
    }

    for (int t = 0; t < T; t++) {
        const int kt = t << 5;
#pragma unroll
        for (int u = 0; u < 4; u++) {
            uint32_t off = (uint32_t)((ar + u * 32) * SROW + aq * 8);
            cvt_store_a16(pa[u], stA + off);
        }
#pragma unroll
        for (int u = 0; u < 2; u++) {
            int r = br + u * 64;
            uint4 vh = *(const uint4*)&g_m1h[(size_t)r * kd + kt + bq * 8];
            uint32_t off = (uint32_t)(r * SROW + bq * 16);
            asm volatile("st.shared.v4.b32 [%0], {%1, %2, %3, %4};"
                         :: "r"(stB + off), "r"(vh.x), "r"(vh.y), "r"(vh.z), "r"(vh.w) : "memory");
        }
        __syncthreads();
        if (t + 1 < T) {
            const int kn = (t + 1) << 5;
#pragma unroll
            for (int u = 0; u < 4; u++) {
                int gr = agr + u * 32;
                pa[u] = (gr < NN) ? *(const float4*)&A[(size_t)gr * kd + kn + aq * 4]
                                  : make_float4(0.f, 0.f, 0.f, 0.f);
            }
        }
#pragma unroll
        for (int kb = 0; kb < 2; kb++) {
            uint32_t ah[4];
            ldm4(ah, bA + kb * 32);
#pragma unroll
            for (int nt = 0; nt < 8; nt++) {
                uint32_t bh[4];
                ldm4(bh, bB + nt * 16 * SROW + kb * 32);
                mma16816h(acc[2 * nt],     ah, &bh[0]);
                mma16816h(acc[2 * nt + 1], ah, &bh[2]);
            }
        }
        __syncthreads();
    }

    // ---- in-register epilogue: +mb1, LN, elu, z@mW2, softmax ----
    const int r_in = lane >> 2;
    const int cq = (lane & 3) * 2;
#pragma unroll
    for (int p = 0; p < 2; p++) {
        float z[32];
        float s = 0.f, q = 0.f;
#pragma unroll
        for (int nt = 0; nt < 16; nt++) {
            int c = nt * 8 + cq;
            float v0 = acc[nt][2 * p]     + s_lb[c];
            float v1 = acc[nt][2 * p + 1] + s_lb[c + 1];
            z[2 * nt] = v0; z[2 * nt + 1] = v1;
            s += v0 + v1; q += v0 * v0 + v1 * v1;
        }
        s += __shfl_xor_sync(0xffffffffu, s, 1);
        s += __shfl_xor_sync(0xffffffffu, s, 2);
        q += __shfl_xor_sync(0xffffffffu, q, 1);
        q += __shfl_xor_sync(0xffffffffu, q, 2);
        float m = s * (1.f / DH);
        float var = q * (1.f / DH) - m * m;
        float rstd = rsqrtf(var + 1e-5f);
#pragma unroll
        for (int nt = 0; nt < 16; nt++) {
            int c = nt * 8 + cq;
            z[2 * nt]     = elu1((z[2 * nt]     - m) * rstd * s_lg[c]     + s_lbe[c]);
            z[2 * nt + 1] = elu1((z[2 * nt + 1] - m) * rstd * s_lg[c + 1] + s_lbe[c + 1]);
        }
        float Hp[16];
#pragma unroll
        for (int c16 = 0; c16 < 16; c16++) Hp[c16] = 0.f;
#pragma unroll
        for (int nt = 0; nt < 16; nt++) {
            const float* w0 = &s_w2[(nt * 8 + cq) * 17];
            const float* w1 = &s_w2[(nt * 8 + cq + 1) * 17];
            float z0 = z[2 * nt], z1 = z[2 * nt + 1];
#pragma unroll
            for (int c16 = 0; c16 < 16; c16++)
                Hp[c16] = fmaf(z0, w0[c16], fmaf(z1, w1[c16], Hp[c16]));
        }
#pragma unroll
        for (int c16 = 0; c16 < 16; c16++) {
            Hp[c16] += __shfl_xor_sync(0xffffffffu, Hp[c16], 1);
            Hp[c16] += __shfl_xor_sync(0xffffffffu, Hp[c16], 2);
        }
        int row = row0 + wid * 16 + r_in + p * 8;
        if ((lane & 3) == 0 && row < NN) {
            float mx = -1e30f;
#pragma unroll
            for (int c16 = 0; c16 < 16; c16++) { Hp[c16] += s_mb2[c16]; mx = fmaxf(mx, Hp[c16]); }
            float ss = 0.f;
#pragma unroll
            for (int c16 = 0; c16 < 16; c16++) { Hp[c16] = __expf(Hp[c16] - mx); ss += Hp[c16]; }
            float inv = 1.f / ss;
            *(float4*)&out[(size_t)row * 16 + 0]  = make_float4(Hp[0] * inv, Hp[1] * inv, Hp[2] * inv, Hp[3] * inv);
            *(float4*)&out[(size_t)row * 16 + 4]  = make_float4(Hp[4] * inv, Hp[5] * inv, Hp[6] * inv, Hp[7] * inv);
            *(float4*)&out[(size_t)row * 16 + 8]  = make_float4(Hp[8] * inv, Hp[9] * inv, Hp[10] * inv, Hp[11] * inv);
            *(float4*)&out[(size_t)row * 16 + 12] = make_float4(Hp[12] * inv, Hp[13] * inv, Hp[14] * inv, Hp[15] * inv);
        }
    }
}

// ---------------- launcher -----------------------------------------------------
extern "C" void kernel_launch(void* const* d_in, const int* in_sizes, int n_in,
                              void* d_out, int out_size) {
    const float* x   = (const float*)d_in[0];
    const void*  ei  = d_in[1];
    const float* W1  = (const float*)d_in[2];
    const float* b1  = (const float*)d_in[3];
    const float* g1  = (const float*)d_in[4];
    const float* be1 = (const float*)d_in[5];
    const float* W2  = (const float*)d_in[6];
    const float* b2  = (const float*)d_in[7];
    const float* g2  = (const float*)d_in[8];
    const float* be2 = (const float*)d_in[9];
    const float* rW  = (const float*)d_in[10];
    const float* rb  = (const float*)d_in[11];
    const float* rg  = (const float*)d_in[12];
    const float* rbe = (const float*)d_in[13];
    const float* mW1 = (const float*)d_in[14];
    const float* mb1 = (const float*)d_in[15];
    const float* mg  = (const float*)d_in[16];
    const float* mbe = (const float*)d_in[17];
    const float* mW2 = (const float*)d_in[18];
    const float* mb2 = (const float*)d_in[19];
    float* out = (float*)d_out;

    const int nblk = (NN + 127) / 128;  // 391

    // launch index:         0     1      2
    k_prep<<<(2 * DH * DIN + 2 * DH * DH + 255) / 256, 256>>>(W1, rW, W2, mW1, ei);
    k_hist<<<(EE + 255) / 256, 256>>>(ei);
    k_scan1<<<NB_SCAN, 256>>>();                      // computes g_dinv
    // index 3: layer-1 GEMM  <-- ncu capture window lands here
    dim3 grid1(nblk, 2);
    k_gemm_mma<<<grid1, 256>>>(x, DIN, 0, rb, rg, rbe);
    // index 4-6: finish CSR
    k_scan2<<<1, 256>>>();
    k_scan3<<<NB_SCAN, 256>>>();
    k_fill<<<(EE + 255) / 256, 256>>>(ei);
    // index 7: layer-1 aggregation -> g_h1
    k_agg<<<(NN * 32 + 255) / 256, 256>>>(b1, g1, be1, 0);
    // index 8: layer-2 GEMM
    dim3 grid2(nblk, 1);
    k_gemm_mma<<<grid2, 256>>>(x, DH, 1, rb, rg, rbe);
    // index 9: layer-2 aggregation -> g_res (h2)
    k_agg<<<(NN * 32 + 255) / 256, 256>>>(b2, g2, be2, 1);
    // index 10: MLP head + softmax
    k_head<<<nblk, 256>>>(mb1, mg, mbe, mW2, mb2, out);
}

// round 11
// speedup vs baseline: 2.4266x; 1.0235x over previous
#include <cuda_runtime.h>
#include <cuda_fp16.h>
#include <math.h>
#include <stdint.h>

#define NN 50000
#define EE 800000
#define DIN 384
#define DH 128
#define NB_SCAN 196   // ceil(50000/256)

// ---------------- scratch (device globals) ------------------------------------
__device__ int   g_is64;
__device__ int   g_cnt[NN];
__device__ int   g_bsum[256];
__device__ int   g_off[NN + 1];
__device__ int   g_csr[EE];
__device__ int   g_eidx[EE];
__device__ int   g_src32[EE];
__device__ int   g_dst32[EE];
__device__ float g_dinv[NN];
__device__ unsigned short g_hws[NN * DH];   // fp16 message rows (pre-scaled)
__device__ float g_res[NN * DH];            // layer-1 LN residual (fp32)
__device__ unsigned short g_h1[NN * DH];    // h1 (fp16)
__device__ unsigned short g_h2[NN * DH];    // h2 (fp16)
// fp16 transposed weights: [N=128, K] row-major
__device__ unsigned short g_b1h[DH * DIN];  // W1^T
__device__ unsigned short g_brh[DH * DIN];  // rW^T
__device__ unsigned short g_w2h[DH * DH];   // W2^T
__device__ unsigned short g_m1h[DH * DH];   // mW1^T

// ---------------- helpers ------------------------------------------------------
__device__ __forceinline__ float elu1(float x) { return x > 0.f ? x : expm1f(x); }

__device__ __forceinline__ uint32_t smem_u32(const void* p) {
    uint32_t a;
    asm("{ .reg .u64 t; cvta.to.shared.u64 t, %1; cvt.u32.u64 %0, t; }" : "=r"(a) : "l"(p));
    return a;
}

__device__ __forceinline__ void ldm4(uint32_t* r, uint32_t addr) {
    asm volatile("ldmatrix.sync.aligned.m8n8.x4.shared.b16 {%0,%1,%2,%3}, [%4];"
                 : "=r"(r[0]), "=r"(r[1]), "=r"(r[2]), "=r"(r[3]) : "r"(addr));
}
__device__ __forceinline__ void mma16816h(float* d, const uint32_t* a, const uint32_t* b) {
    asm volatile("mma.sync.aligned.m16n8k16.row.col.f32.f16.f16.f32 "
                 "{%0,%1,%2,%3}, {%4,%5,%6,%7}, {%8,%9}, {%0,%1,%2,%3};"
                 : "+f"(d[0]), "+f"(d[1]), "+f"(d[2]), "+f"(d[3])
                 : "r"(a[0]), "r"(a[1]), "r"(a[2]), "r"(a[3]), "r"(b[0]), "r"(b[1]));
}

__device__ __forceinline__ void load_edge(const void* ei, int e, int& s, int& d) {
    if (g_is64) {
        const long long* p = (const long long*)ei;
        s = (int)p[e]; d = (int)p[EE + e];
    } else {
        const int* p = (const int*)ei;
        s = p[e]; d = p[EE + e];
    }
}

// inclusive block scan over 256 threads
__device__ __forceinline__ int block_scan_incl(int v, int* ws) {
    int lane = threadIdx.x & 31, w = threadIdx.x >> 5;
    int x = v;
#pragma unroll
    for (int o = 1; o < 32; o <<= 1) {
        int u = __shfl_up_sync(0xffffffffu, x, o);
        if (lane >= o) x += u;
    }
    if (lane == 31) ws[w] = x;
    __syncthreads();
    if (w == 0) {
        int t = (lane < 8) ? ws[lane] : 0;
#pragma unroll
        for (int o = 1; o < 8; o <<= 1) {
            int u = __shfl_up_sync(0xffffffffu, t, o);
            if (lane >= o) t += u;
        }
        if (lane < 8) ws[lane] = t;
    }
    __syncthreads();
    if (w > 0) x += ws[w - 1];
    return x;
}

__device__ __forceinline__ float4 h8_to_f4(uint2 u) {
    __half2 h0 = *(__half2*)&u.x;
    __half2 h1 = *(__half2*)&u.y;
    float2 f0 = __half22float2(h0);
    float2 f1 = __half22float2(h1);
    return make_float4(f0.x, f0.y, f1.x, f1.y);
}

// Pull-mode aggregation: self + sum of neighbor rows (rows pre-scaled, fp16).
__device__ __forceinline__ float4 agg_row(int n, int lane) {
    const uint2* hw = (const uint2*)g_hws;
    float4 a = h8_to_f4(hw[(size_t)n * 32 + lane]);
    int e  = g_off[n];
    int e1 = g_off[n + 1];
    for (; e + 4 <= e1; e += 4) {
        int s0 = g_csr[e], s1 = g_csr[e + 1], s2 = g_csr[e + 2], s3 = g_csr[e + 3];
        float4 v0 = h8_to_f4(hw[(size_t)s0 * 32 + lane]);
        float4 v1 = h8_to_f4(hw[(size_t)s1 * 32 + lane]);
        float4 v2 = h8_to_f4(hw[(size_t)s2 * 32 + lane]);
        float4 v3 = h8_to_f4(hw[(size_t)s3 * 32 + lane]);
        a.x += (v0.x + v1.x) + (v2.x + v3.x);
        a.y += (v0.y + v1.y) + (v2.y + v3.y);
        a.z += (v0.z + v1.z) + (v2.z + v3.z);
        a.w += (v0.w + v1.w) + (v2.w + v3.w);
    }
    for (; e < e1; e++) {
        float4 v0 = h8_to_f4(hw[(size_t)g_csr[e] * 32 + lane]);
        a.x += v0.x; a.y += v0.y; a.z += v0.z; a.w += v0.w;
    }
    return a;
}

// ---------------- weight prep + init -------------------------------------------
__global__ void k_prep(const float* __restrict__ W1, const float* __restrict__ rW,
                       const float* __restrict__ W2, const float* __restrict__ mW1,
                       const void* edges) {
    int i = blockIdx.x * blockDim.x + threadIdx.x;
    if (i < NN) g_cnt[i] = 0;
    if (i == 0) {
        const unsigned long long* p = (const unsigned long long*)edges;
        int is64 = 1;
        for (int j = 0; j < 8; j++) if (p[j] >= (unsigned long long)NN) is64 = 0;
        g_is64 = is64;
    }
    float val;
    unsigned short* ph;
    int idx;
    if (i < DH * DIN) {
        int n = i / DIN, k = i % DIN;
        val = W1[k * DH + n]; ph = g_b1h; idx = i;
    } else if (i < 2 * DH * DIN) {
        int j = i - DH * DIN;
        int n = j / DIN, k = j % DIN;
        val = rW[k * DH + n]; ph = g_brh; idx = j;
    } else if (i < 2 * DH * DIN + DH * DH) {
        int j = i - 2 * DH * DIN;
        int n = j / DH, k = j % DH;
        val = W2[k * DH + n]; ph = g_w2h; idx = j;
    } else if (i < 2 * DH * DIN + 2 * DH * DH) {
        int j = i - 2 * DH * DIN - DH * DH;
        int n = j / DH, k = j % DH;
        val = mW1[k * DH + n]; ph = g_m1h; idx = j;
    } else return;
    ph[idx] = __half_as_ushort(__float2half_rn(val));
}

__global__ void k_hist(const void* edges) {
    int e = blockIdx.x * blockDim.x + threadIdx.x;
    if (e >= EE) return;
    int s, d;
    load_edge(edges, e, s, d);
    int idx = atomicAdd(&g_cnt[d], 1);
    g_eidx [e] = idx;
    g_src32[e] = s;
    g_dst32[e] = d;
}

// ---------------- scans ---------------------------------------------------------
__global__ void k_scan1() {
    __shared__ int ws[8];
    int i = blockIdx.x * 256 + threadIdx.x;
    int c = (i < NN) ? g_cnt[i] : 0;
    if (i < NN) g_dinv[i] = rsqrtf((float)(c + 1));
    int lane = threadIdx.x & 31, w = threadIdx.x >> 5;
    int v = c;
#pragma unroll
    for (int o = 16; o; o >>= 1) v += __shfl_xor_sync(0xffffffffu, v, o);
    if (lane == 0) ws[w] = v;
    __syncthreads();
    if (w == 0) {
        int t = (lane < 8) ? ws[lane] : 0;
#pragma unroll
        for (int o = 4; o; o >>= 1) t += __shfl_xor_sync(0xffffffffu, t, o);
        if (lane == 0) g_bsum[blockIdx.x] = t;
    }
}

// merged scan2+scan3: each block derives its base by reducing bsum[0..bid)
__global__ void k_scan3() {
    __shared__ int ws[8];
    __shared__ int ws2[8];
    __shared__ int s_base;
    int t = threadIdx.x;
    int lane = t & 31, w = t >> 5;
    // base = sum of bsum[j], j < blockIdx.x
    int part = (t < blockIdx.x) ? g_bsum[t] : 0;
#pragma unroll
    for (int o = 16; o; o >>= 1) part += __shfl_xor_sync(0xffffffffu, part, o);
    if (lane == 0) ws2[w] = part;
    __syncthreads();
    if (w == 0) {
        int x = (lane < 8) ? ws2[lane] : 0;
#pragma unroll
        for (int o = 4; o; o >>= 1) x += __shfl_xor_sync(0xffffffffu, x, o);
        if (lane == 0) s_base = x;
    }
    __syncthreads();
    int base = s_base;
    int i = blockIdx.x * 256 + t;
    int c = (i < NN) ? g_cnt[i] : 0;
    int incl = block_scan_incl(c, ws);
    int excl = base + incl - c;
    if (i < NN) g_off[i] = excl;
    if (i == NN - 1) g_off[NN] = base + incl;
}

__global__ void k_fill(const void*) {
    int e = blockIdx.x * blockDim.x + threadIdx.x;
    if (e >= EE) return;
    int d = g_dst32[e];
    g_csr[g_off[d] + g_eidx[e]] = g_src32[e];
}

// ---------------- A-chunk conversion helper (fp32 -> fp16) ----------------------
__device__ __forceinline__ void cvt_store_a16(float4 v, uint32_t dst) {
    __half2 h01 = __floats2half2_rn(v.x, v.y);
    __half2 h23 = __floats2half2_rn(v.z, v.w);
    asm volatile("st.shared.v2.b32 [%0], {%1, %2};"
                 :: "r"(dst), "r"(*(uint32_t*)&h01), "r"(*(uint32_t*)&h23) : "memory");
}

// ---------------- tensor-core GEMM, 4x2 warp tiling -----------------------------
// WHICH==0: A=x fp32 (kd=384). blockIdx.y: 0 -> W1, dinv-scale -> g_hws (fp16)
//                                          1 -> rW, LayerNorm  -> g_res (fp32)
// WHICH==1: A=g_h1 fp16 (kd=128): W2, dinv-scale -> g_hws (fp16)
#define SROW 80

template<int WHICH>
__global__ __launch_bounds__(256, 2) void k_gemm_mma(
    const float* __restrict__ Ain, int kd,
    const float* __restrict__ lb, const float* __restrict__ lg, const float* __restrict__ lbe)
{
    __shared__ __align__(16) unsigned char sA[128 * SROW];
    __shared__ __align__(16) unsigned char sB[128 * SROW];
    __shared__ float s_lb[DH], s_lg[DH], s_lbe[DH];
    __shared__ float sS[2][128], sQ[2][128];

    const int tid  = threadIdx.x;
    const int wid  = tid >> 5;
    const int lane = tid & 31;
    const int wm   = wid >> 1;    // M stripe (0..3) of 32 rows
    const int wn   = wid & 1;     // N half (0..1) of 64 cols
    const int mode = blockIdx.y;
    const int row0 = blockIdx.x * 128;
    const unsigned short* Bh;
    if (WHICH == 0) Bh = mode ? g_brh : g_b1h;
    else            Bh = g_w2h;

    if (WHICH == 0 && mode == 1 && tid < DH) {
        s_lb[tid] = lb[tid]; s_lg[tid] = lg[tid]; s_lbe[tid] = lbe[tid];
    }

    float acc[2][8][4];
#pragma unroll
    for (int i = 0; i < 2; i++)
#pragma unroll
        for (int j = 0; j < 8; j++)
#pragma unroll
            for (int k = 0; k < 4; k++) acc[i][j][k] = 0.f;

    const uint32_t stA = smem_u32(sA), stB = smem_u32(sB);
    const uint32_t bA = stA + (wm * 32 + (lane & 15)) * SROW + ((lane >> 4) & 1) * 16;
    const uint32_t nrow = (uint32_t)((lane & 7) | ((lane >> 4) << 3));
    const uint32_t bB = stB + (wn * 64 + nrow) * SROW + ((lane >> 3) & 1) * 16;

    const int ar = tid >> 3, aq = tid & 7;
    const int br = tid >> 2, bq = tid & 3;
    const int agr = row0 + ar;
    const int T = kd >> 5;

    float4 pa[4];
    uint2  pa16[4];
    if (WHICH == 0) {
#pragma unroll
        for (int u = 0; u < 4; u++) {
            int gr = agr + u * 32;
            pa[u] = (gr < NN) ? *(const float4*)&Ain[(size_t)gr * kd + aq * 4]
                              : make_float4(0.f, 0.f, 0.f, 0.f);
        }
    } else {
#pragma unroll
        for (int u = 0; u < 4; u++) {
            int gr = agr + u * 32;
            pa16[u] = (gr < NN) ? *(const uint2*)&g_h1[(size_t)gr * kd + aq * 4]
                                : make_uint2(0u, 0u);
        }
    }

    for (int t = 0; t < T; t++) {
        const int kt = t << 5;
#pragma unroll
        for (int u = 0; u < 4; u++) {
            uint32_t off = (uint32_t)((ar + u * 32) * SROW + aq * 8);
            if (WHICH == 0) cvt_store_a16(pa[u], stA + off);
            else
                asm volatile("st.shared.v2.b32 [%0], {%1, %2};"
                             :: "r"(stA + off), "r"(pa16[u].x), "r"(pa16[u].y) : "memory");
        }
#pragma unroll
        for (int u = 0; u < 2; u++) {
            int r = br + u * 64;
            uint4 vh = *(const uint4*)&Bh[(size_t)r * kd + kt + bq * 8];
            uint32_t off = (uint32_t)(r * SROW + bq * 16);
            asm volatile("st.shared.v4.b32 [%0], {%1, %2, %3, %4};"
                         :: "r"(stB + off), "r"(vh.x), "r"(vh.y), "r"(vh.z), "r"(vh.w) : "memory");
        }
        __syncthreads();
        if (t + 1 < T) {
            const int kn = (t + 1) << 5;
            if (WHICH == 0) {
#pragma unroll
                for (int u = 0; u < 4; u++) {
                    int gr = agr + u * 32;
                    pa[u] = (gr < NN) ? *(const float4*)&Ain[(size_t)gr * kd + kn + aq * 4]
                                      : make_float4(0.f, 0.f, 0.f, 0.f);
                }
            } else {
#pragma unroll
                for (int u = 0; u < 4; u++) {
                    int gr = agr + u * 32;
                    pa16[u] = (gr < NN) ? *(const uint2*)&g_h1[(size_t)gr * kd + kn + aq * 4]
                                        : make_uint2(0u, 0u);
                }
            }
        }
#pragma unroll
        for (int kb = 0; kb < 2; kb++) {
            uint32_t a0[4], a1[4];
            ldm4(a0, bA + kb * 32);
            ldm4(a1, bA + 16 * SROW + kb * 32);
#pragma unroll
            for (int nt = 0; nt < 4; nt++) {
                uint32_t bh[4];
                ldm4(bh, bB + nt * 16 * SROW + kb * 32);
                mma16816h(acc[0][2 * nt],     a0, &bh[0]);
                mma16816h(acc[0][2 * nt + 1], a0, &bh[2]);
                mma16816h(acc[1][2 * nt],     a1, &bh[0]);
                mma16816h(acc[1][2 * nt + 1], a1, &bh[2]);
            }
        }
        __syncthreads();
    }

    // ---- epilogue ----
    const int r_in = lane >> 2;
    const int cq = (lane & 3) * 2;
    if (WHICH == 1 || mode == 0) {
#pragma unroll
        for (int mt = 0; mt < 2; mt++)
#pragma unroll
            for (int p = 0; p < 2; p++) {
                int row = row0 + wm * 32 + mt * 16 + r_in + p * 8;
                if (row < NN) {
                    float dv = g_dinv[row];
#pragma unroll
                    for (int j = 0; j < 8; j++) {
                        int col = wn * 64 + j * 8 + cq;
                        __half2 hh = __floats2half2_rn(acc[mt][j][2 * p] * dv,
                                                       acc[mt][j][2 * p + 1] * dv);
                        *(__half2*)&g_hws[(size_t)row * DH + col] = hh;
                    }
                }
            }
    } else {
        // LN across full row: cross-warp (wn pair) partial exchange
        float sv[2][2], qv[2][2];
#pragma unroll
        for (int mt = 0; mt < 2; mt++)
#pragma unroll
            for (int p = 0; p < 2; p++) {
                float s = 0.f, q = 0.f;
#pragma unroll
                for (int j = 0; j < 8; j++) {
                    int col = wn * 64 + j * 8 + cq;
                    float v0 = acc[mt][j][2 * p]     + s_lb[col];
                    float v1 = acc[mt][j][2 * p + 1] + s_lb[col + 1];
                    s += v0 + v1; q += v0 * v0 + v1 * v1;
                }
                s += __shfl_xor_sync(0xffffffffu, s, 1);
                s += __shfl_xor_sync(0xffffffffu, s, 2);
                q += __shfl_xor_sync(0xffffffffu, q, 1);
                q += __shfl_xor_sync(0xffffffffu, q, 2);
                sv[mt][p] = s; qv[mt][p] = q;
            }
        if ((lane & 3) == 0) {
#pragma unroll
            for (int mt = 0; mt < 2; mt++)
#pragma unroll
                for (int p = 0; p < 2; p++) {
                    int rc = wm * 32 + mt * 16 + r_in + p * 8;
                    sS[wn][rc] = sv[mt][p];
                    sQ[wn][rc] = qv[mt][p];
                }
        }
        __syncthreads();
#pragma unroll
        for (int mt = 0; mt < 2; mt++)
#pragma unroll
            for (int p = 0; p < 2; p++) {
                int rc = wm * 32 + mt * 16 + r_in + p * 8;
                float s = sS[0][rc] + sS[1][rc];
                float q = sQ[0][rc] + sQ[1][rc];
                float m = s * (1.f / DH);
                float var = q * (1.f / DH) - m * m;
                float rstd = rsqrtf(var + 1e-5f);
                int row = row0 + rc;
                if (row < NN) {
#pragma unroll
                    for (int j = 0; j < 8; j++) {
                        int col = wn * 64 + j * 8 + cq;
                        float v0 = acc[mt][j][2 * p]     + s_lb[col];
                        float v1 = acc[mt][j][2 * p + 1] + s_lb[col + 1];
                        *(float2*)&g_res[(size_t)row * DH + col] =
                            make_float2((v0 - m) * rstd * s_lg[col]     + s_lbe[col],
                                        (v1 - m) * rstd * s_lg[col + 1] + s_lbe[col + 1]);
                    }
                }
            }
    }
}

// ---------------- agg kernels ---------------------------------------------------
// phase==0: h1 = elu(LN(agg*dinv + b)) + res(g_res fp32)  -> g_h1 (fp16)
// phase==1: h2 = elu(LN(agg*dinv + b)) + h1(g_h1 fp16)    -> g_h2 (fp16)
__global__ __launch_bounds__(256) void k_agg(const float* __restrict__ b,
                                             const float* __restrict__ g,
                                             const float* __restrict__ be,
                                             int phase) {
    int n = (blockIdx.x * blockDim.x + threadIdx.x) >> 5;
    if (n >= NN) return;
    int lane = threadIdx.x & 31;
    float4 a = agg_row(n, lane);
    float dv = g_dinv[n];
    float4 bb = *(const float4*)&b[lane * 4];
    float v0 = fmaf(a.x, dv, bb.x), v1 = fmaf(a.y, dv, bb.y);
    float v2 = fmaf(a.z, dv, bb.z), v3 = fmaf(a.w, dv, bb.w);
    float s = v0 + v1 + v2 + v3;
    float q = v0 * v0 + v1 * v1 + v2 * v2 + v3 * v3;
#pragma unroll
    for (int o = 16; o; o >>= 1) {
        s += __shfl_xor_sync(0xffffffffu, s, o);
        q += __shfl_xor_sync(0xffffffffu, q, o);
    }
    float m = s * (1.f / DH);
    float var = q * (1.f / DH) - m * m;
    float rstd = rsqrtf(var + 1e-5f);
    float4 gg = *(const float4*)&g[lane * 4];
    float4 bev = *(const float4*)&be[lane * 4];
    float y0 = elu1((v0 - m) * rstd * gg.x + bev.x);
    float y1 = elu1((v1 - m) * rstd * gg.y + bev.y);
    float y2 = elu1((v2 - m) * rstd * gg.z + bev.z);
    float y3 = elu1((v3 - m) * rstd * gg.w + bev.w);
    float4 r;
    if (phase) r = h8_to_f4(*(const uint2*)&g_h1[(size_t)n * DH + lane * 4]);
    else       r = *(const float4*)&g_res[(size_t)n * DH + lane * 4];
    __half2 o01 = __floats2half2_rn(y0 + r.x, y1 + r.y);
    __half2 o23 = __floats2half2_rn(y2 + r.z, y3 + r.w);
    uint2 o = make_uint2(*(uint32_t*)&o01, *(uint32_t*)&o23);
    if (phase) *(uint2*)&g_h2[(size_t)n * DH + lane * 4] = o;
    else       *(uint2*)&g_h1[(size_t)n * DH + lane * 4] = o;
}

// ---------------- head: z = elu(LN(h2@mW1 + mb1)), H = z@mW2 + mb2, softmax ----
__global__ __launch_bounds__(256) void k_head(
    const float* __restrict__ mb1, const float* __restrict__ mg_,
    const float* __restrict__ mbe_, const float* __restrict__ mW2,
    const float* __restrict__ mb2, float* __restrict__ out)
{
    __shared__ __align__(16) unsigned char sA[128 * SROW];
    __shared__ __align__(16) unsigned char sB[128 * SROW];
    __shared__ float s_w2[128 * 17];
    __shared__ float s_lb[DH], s_lg[DH], s_lbe[DH], s_mb2[16];

    const int tid  = threadIdx.x;
    const int wid  = tid >> 5;
    const int lane = tid & 31;
    const int row0 = blockIdx.x * 128;
    const int kd = DH;

    for (int i = tid; i < 128 * 16; i += 256)
        s_w2[(i >> 4) * 17 + (i & 15)] = mW2[i];
    if (tid < DH) { s_lb[tid] = mb1[tid]; s_lg[tid] = mg_[tid]; s_lbe[tid] = mbe_[tid]; }
    if (tid < 16) s_mb2[tid] = mb2[tid];

    float acc[16][4];
#pragma unroll
    for (int i = 0; i < 16; i++)
#pragma unroll
        for (int j = 0; j < 4; j++) acc[i][j] = 0.f;

    const uint32_t stA = smem_u32(sA), stB = smem_u32(sB);
    const uint32_t bA = stA + (wid * 16 + (lane & 15)) * SROW + ((lane >> 4) & 1) * 16;
    const uint32_t nrow = (uint32_t)((lane & 7) | ((lane >> 4) << 3));
    const uint32_t bB = stB + nrow * SROW + ((lane >> 3) & 1) * 16;

    const int ar = tid >> 3, aq = tid & 7;
    const int br = tid >> 2, bq = tid & 3;
    const int agr = row0 + ar;
    const int T = kd >> 5;   // 4

    uint2 pa16[4];
#pragma unroll
    for (int u = 0; u < 4; u++) {
        int gr = agr + u * 32;
        pa16[u] = (gr < NN) ? *(const uint2*)&g_h2[(size_t)gr * kd + aq * 4]
                            : make_uint2(0u, 0u);
    }

    for (int t = 0; t < T; t++) {
        const int kt = t << 5;
#pragma unroll
        for (int u = 0; u < 4; u++) {
            uint32_t off = (uint32_t)((ar + u * 32) * SROW + aq * 8);
            asm volatile("st.shared.v2.b32 [%0], {%1, %2};"
                         :: "r"(stA + off), "r"(pa16[u].x), "r"(pa16[u].y) : "memory");
        }
#pragma unroll
        for (int u = 0; u < 2; u++) {
            int r = br + u * 64;
            uint4 vh = *(const uint4*)&g_m1h[(size_t)r * kd + kt + bq * 8];
            uint32_t off = (uint32_t)(r * SROW + bq * 16);
            asm volatile("st.shared.v4.b32 [%0], {%1, %2, %3, %4};"
                         :: "r"(stB + off), "r"(vh.x), "r"(vh.y), "r"(vh.z), "r"(vh.w) : "memory");
        }
        __syncthreads();
        if (t + 1 < T) {
            const int kn = (t + 1) << 5;
#pragma unroll
            for (int u = 0; u < 4; u++) {
                int gr = agr + u * 32;
                pa16[u] = (gr < NN) ? *(const uint2*)&g_h2[(size_t)gr * kd + kn + aq * 4]
                                    : make_uint2(0u, 0u);
            }
        }
#pragma unroll
        for (int kb = 0; kb < 2; kb++) {
            uint32_t ah[4];
            ldm4(ah, bA + kb * 32);
#pragma unroll
            for (int nt = 0; nt < 8; nt++) {
                uint32_t bh[4];
                ldm4(bh, bB + nt * 16 * SROW + kb * 32);
                mma16816h(acc[2 * nt],     ah, &bh[0]);
                mma16816h(acc[2 * nt + 1], ah, &bh[2]);
            }
        }
        __syncthreads();
    }

    // ---- in-register epilogue: +mb1, LN, elu, z@mW2, softmax ----
    const int r_in = lane >> 2;
    const int cq = (lane & 3) * 2;
#pragma unroll
    for (int p = 0; p < 2; p++) {
        float z[32];
        float s = 0.f, q = 0.f;
#pragma unroll
        for (int nt = 0; nt < 16; nt++) {
            int c = nt * 8 + cq;
            float v0 = acc[nt][2 * p]     + s_lb[c];
            float v1 = acc[nt][2 * p + 1] + s_lb[c + 1];
            z[2 * nt] = v0; z[2 * nt + 1] = v1;
            s += v0 + v1; q += v0 * v0 + v1 * v1;
        }
        s += __shfl_xor_sync(0xffffffffu, s, 1);
        s += __shfl_xor_sync(0xffffffffu, s, 2);
        q += __shfl_xor_sync(0xffffffffu, q, 1);
        q += __shfl_xor_sync(0xffffffffu, q, 2);
        float m = s * (1.f / DH);
        float var = q * (1.f / DH) - m * m;
        float rstd = rsqrtf(var + 1e-5f);
#pragma unroll
        for (int nt = 0; nt < 16; nt++) {
            int c = nt * 8 + cq;
            z[2 * nt]     = elu1((z[2 * nt]     - m) * rstd * s_lg[c]     + s_lbe[c]);
            z[2 * nt + 1] = elu1((z[2 * nt + 1] - m) * rstd * s_lg[c + 1] + s_lbe[c + 1]);
        }
        float Hp[16];
#pragma unroll
        for (int c16 = 0; c16 < 16; c16++) Hp[c16] = 0.f;
#pragma unroll
        for (int nt = 0; nt < 16; nt++) {
            const float* w0 = &s_w2[(nt * 8 + cq) * 17];
            const float* w1 = &s_w2[(nt * 8 + cq + 1) * 17];
            float z0 = z[2 * nt], z1 = z[2 * nt + 1];
#pragma unroll
            for (int c16 = 0; c16 < 16; c16++)
                Hp[c16] = fmaf(z0, w0[c16], fmaf(z1, w1[c16], Hp[c16]));
        }
#pragma unroll
        for (int c16 = 0; c16 < 16; c16++) {
            Hp[c16] += __shfl_xor_sync(0xffffffffu, Hp[c16], 1);
            Hp[c16] += __shfl_xor_sync(0xffffffffu, Hp[c16], 2);
        }
        int row = row0 + wid * 16 + r_in + p * 8;
        if ((lane & 3) == 0 && row < NN) {
            float mx = -1e30f;
#pragma unroll
            for (int c16 = 0; c16 < 16; c16++) { Hp[c16] += s_mb2[c16]; mx = fmaxf(mx, Hp[c16]); }
            float ss = 0.f;
#pragma unroll
            for (int c16 = 0; c16 < 16; c16++) { Hp[c16] = __expf(Hp[c16] - mx); ss += Hp[c16]; }
            float inv = 1.f / ss;
            *(float4*)&out[(size_t)row * 16 + 0]  = make_float4(Hp[0] * inv, Hp[1] * inv, Hp[2] * inv, Hp[3] * inv);
            *(float4*)&out[(size_t)row * 16 + 4]  = make_float4(Hp[4] * inv, Hp[5] * inv, Hp[6] * inv, Hp[7] * inv);
            *(float4*)&out[(size_t)row * 16 + 8]  = make_float4(Hp[8] * inv, Hp[9] * inv, Hp[10] * inv, Hp[11] * inv);
            *(float4*)&out[(size_t)row * 16 + 12] = make_float4(Hp[12] * inv, Hp[13] * inv, Hp[14] * inv, Hp[15] * inv);
        }
    }
}

// ---------------- launcher -----------------------------------------------------
extern "C" void kernel_launch(void* const* d_in, const int* in_sizes, int n_in,
                              void* d_out, int out_size) {
    const float* x   = (const float*)d_in[0];
    const void*  ei  = d_in[1];
    const float* W1  = (const float*)d_in[2];
    const float* b1  = (const float*)d_in[3];
    const float* g1  = (const float*)d_in[4];
    const float* be1 = (const float*)d_in[5];
    const float* W2  = (const float*)d_in[6];
    const float* b2  = (const float*)d_in[7];
    const float* g2  = (const float*)d_in[8];
    const float* be2 = (const float*)d_in[9];
    const float* rW  = (const float*)d_in[10];
    const float* rb  = (const float*)d_in[11];
    const float* rg  = (const float*)d_in[12];
    const float* rbe = (const float*)d_in[13];
    const float* mW1 = (const float*)d_in[14];
    const float* mb1 = (const float*)d_in[15];
    const float* mg  = (const float*)d_in[16];
    const float* mbe = (const float*)d_in[17];
    const float* mW2 = (const float*)d_in[18];
    const float* mb2 = (const float*)d_in[19];
    float* out = (float*)d_out;

    const int nblk = (NN + 127) / 128;  // 391

    // launch index:         0     1      2
    k_prep<<<(2 * DH * DIN + 2 * DH * DH + 255) / 256, 256>>>(W1, rW, W2, mW1, ei);
    k_hist<<<(EE + 255) / 256, 256>>>(ei);
    k_scan1<<<NB_SCAN, 256>>>();                      // computes g_dinv + bsum
    // index 3: layer-1 GEMM  <-- ncu capture window
    dim3 grid1(nblk, 2);
    k_gemm_mma<0><<<grid1, 256>>>(x, DIN, rb, rg, rbe);
    // index 4-5: finish CSR
    k_scan3<<<NB_SCAN, 256>>>();
    k_fill<<<(EE + 255) / 256, 256>>>(ei);
    // index 6: layer-1 aggregation -> g_h1 (fp16)
    k_agg<<<(NN * 32 + 255) / 256, 256>>>(b1, g1, be1, 0);
    // index 7: layer-2 GEMM (A = g_h1 fp16)
    dim3 grid2(nblk, 1);
    k_gemm_mma<1><<<grid2, 256>>>(x, DH, rb, rg, rbe);
    // index 8: layer-2 aggregation -> g_h2 (fp16)
    k_agg<<<(NN * 32 + 255) / 256, 256>>>(b2, g2, be2, 1);
    // index 9: MLP head + softmax (A = g_h2 fp16)
    k_head<<<nblk, 256>>>(mb1, mg, mbe, mW2, mb2, out);
}